// round 2
// baseline (speedup 1.0000x reference)
#include <cuda_runtime.h>
#include <math.h>

// Problem constants
#define BB 2
#define TT 2048
#define CC 1024
#define HH 16
#define DHD 64
#define MT (BB * TT)          // 4096 rows

// ---------------------------------------------------------------------------
// Scratch (device globals: allocation-free per harness rules)
// ---------------------------------------------------------------------------
__device__ float g_q[MT * 2 * CC];     // [4096, 2048]
__device__ float g_k[MT * 2 * CC];     // [4096, 2048]
__device__ float g_v[MT * CC];         // [4096, 1024]
__device__ float g_y[MT * CC];         // attention output [4096, 1024]
__device__ float g_y2[MT * CC];        // after wo
__device__ float g_h[MT * (CC / 2)];   // after wc [4096, 512]
__device__ float g_lambda;

// ---------------------------------------------------------------------------
// Generic TN SGEMM: C[M,N] = A[M,K] @ B[N,K]^T (+ bias[N])
// 128x128 block, BK=16, 256 threads, 8x8 microtile, float4 smem reads.
// Requires M%128==0, N%128==0, K%16==0 (true for all shapes here).
// ---------------------------------------------------------------------------
__global__ __launch_bounds__(256) void sgemm_tn(
    const float* __restrict__ A, const float* __restrict__ B,
    const float* __restrict__ bias, float* __restrict__ C,
    int M, int N, int K)
{
    __shared__ float As[16][128];
    __shared__ float Bs[16][128];

    const int tid = threadIdx.x;
    const int m0 = blockIdx.y * 128;
    const int n0 = blockIdx.x * 128;
    const int ty = tid >> 4;       // 0..15
    const int tx = tid & 15;       // 0..15
    const int lr = tid >> 1;       // 0..127
    const int lk = (tid & 1) << 3; // 0 or 8

    float acc[8][8];
#pragma unroll
    for (int r = 0; r < 8; r++)
#pragma unroll
        for (int c = 0; c < 8; c++) acc[r][c] = 0.f;

    const float* Ag = A + (size_t)(m0 + lr) * K + lk;
    const float* Bg = B + (size_t)(n0 + lr) * K + lk;

    for (int k0 = 0; k0 < K; k0 += 16) {
        float4 a0 = *(const float4*)(Ag + k0);
        float4 a1 = *(const float4*)(Ag + k0 + 4);
        float4 b0 = *(const float4*)(Bg + k0);
        float4 b1 = *(const float4*)(Bg + k0 + 4);
        __syncthreads();
        As[lk + 0][lr] = a0.x; As[lk + 1][lr] = a0.y;
        As[lk + 2][lr] = a0.z; As[lk + 3][lr] = a0.w;
        As[lk + 4][lr] = a1.x; As[lk + 5][lr] = a1.y;
        As[lk + 6][lr] = a1.z; As[lk + 7][lr] = a1.w;
        Bs[lk + 0][lr] = b0.x; Bs[lk + 1][lr] = b0.y;
        Bs[lk + 2][lr] = b0.z; Bs[lk + 3][lr] = b0.w;
        Bs[lk + 4][lr] = b1.x; Bs[lk + 5][lr] = b1.y;
        Bs[lk + 6][lr] = b1.z; Bs[lk + 7][lr] = b1.w;
        __syncthreads();
#pragma unroll
        for (int kk = 0; kk < 16; kk++) {
            float4 av0 = *(const float4*)&As[kk][ty * 8];
            float4 av1 = *(const float4*)&As[kk][ty * 8 + 4];
            float4 bv0 = *(const float4*)&Bs[kk][tx * 8];
            float4 bv1 = *(const float4*)&Bs[kk][tx * 8 + 4];
            float a[8] = {av0.x, av0.y, av0.z, av0.w, av1.x, av1.y, av1.z, av1.w};
            float b[8] = {bv0.x, bv0.y, bv0.z, bv0.w, bv1.x, bv1.y, bv1.z, bv1.w};
#pragma unroll
            for (int r = 0; r < 8; r++)
#pragma unroll
                for (int c = 0; c < 8; c++) acc[r][c] = fmaf(a[r], b[c], acc[r][c]);
        }
    }

    float bv[8];
#pragma unroll
    for (int c = 0; c < 8; c++) bv[c] = bias ? bias[n0 + tx * 8 + c] : 0.f;

#pragma unroll
    for (int r = 0; r < 8; r++) {
        float* Crow = C + (size_t)(m0 + ty * 8 + r) * N + n0 + tx * 8;
        float4 o0 = make_float4(acc[r][0] + bv[0], acc[r][1] + bv[1],
                                acc[r][2] + bv[2], acc[r][3] + bv[3]);
        float4 o1 = make_float4(acc[r][4] + bv[4], acc[r][5] + bv[5],
                                acc[r][6] + bv[6], acc[r][7] + bv[7]);
        *(float4*)(Crow)     = o0;
        *(float4*)(Crow + 4) = o1;
    }
}

// ---------------------------------------------------------------------------
// Lambda scalar
// ---------------------------------------------------------------------------
__global__ void lambda_kernel(const float* __restrict__ lq1, const float* __restrict__ lk1,
                              const float* __restrict__ lq2, const float* __restrict__ lk2)
{
    if (threadIdx.x == 0) {
        float s1 = 0.f, s2 = 0.f;
        for (int i = 0; i < HH; i++) {
            s1 = fmaf(lq1[i], lk1[i], s1);
            s2 = fmaf(lq2[i], lk2[i], s2);
        }
        double li = 0.8 - 0.6 * exp(-0.3 * 11.0);  // N_LAYER=12
        g_lambda = (float)(exp((double)s1) - exp((double)s2) + li);
    }
}

// ---------------------------------------------------------------------------
// Fused differential flash attention.
// Block = (b, h, q-tile of 64). 256 threads (16x16), 4x4 microtile on 64x64.
// Two independent online-softmax accumulators (att1, att2); epilogue combines
// with lambda. Causal tiles beyond the diagonal are skipped entirely.
// ---------------------------------------------------------------------------
#define FPAD 65
#define FLASH_SMEM ((6 * 64 * FPAD + 6 * 64 + 2 * 256) * 4)

__device__ __forceinline__ void att_pass(
    const float* __restrict__ Qs, const float* __restrict__ Ks,
    const float* __restrict__ Vs,
    float* Ss, float* rowm, float* rowl, float* corr_s, float* mnew_s,
    float* red, float* red2,
    float acc[4][4], int ty, int tx, int r64, int p4, bool diag)
{
    const float scale = 0.125f;  // 1/sqrt(64)
    float S[4][4];
#pragma unroll
    for (int r = 0; r < 4; r++)
#pragma unroll
        for (int c = 0; c < 4; c++) S[r][c] = 0.f;

    // S = Q @ K^T  (64x64 tile)
#pragma unroll 8
    for (int d = 0; d < 64; d++) {
        float a[4], bq[4];
#pragma unroll
        for (int r = 0; r < 4; r++) a[r] = Qs[(ty * 4 + r) * FPAD + d];
#pragma unroll
        for (int c = 0; c < 4; c++) bq[c] = Ks[(tx * 4 + c) * FPAD + d];
#pragma unroll
        for (int r = 0; r < 4; r++)
#pragma unroll
            for (int c = 0; c < 4; c++) S[r][c] = fmaf(a[r], bq[c], S[r][c]);
    }

    // mask + scale, write to smem
#pragma unroll
    for (int r = 0; r < 4; r++)
#pragma unroll
        for (int c = 0; c < 4; c++) {
            float v = S[r][c] * scale;
            if (diag && (tx * 4 + c) > (ty * 4 + r)) v = -1e30f;
            Ss[(ty * 4 + r) * FPAD + tx * 4 + c] = v;
        }
    __syncthreads();

    // online softmax: 4 threads per row (r64 = row, p4 = 16-col quarter)
    float* srow = Ss + r64 * FPAD + p4 * 16;
    float pmax = -1e30f;
#pragma unroll
    for (int j = 0; j < 16; j++) pmax = fmaxf(pmax, srow[j]);
    red[p4 * 64 + r64] = pmax;
    __syncthreads();

    float mt = fmaxf(fmaxf(red[r64], red[64 + r64]),
                     fmaxf(red[128 + r64], red[192 + r64]));
    float mold = rowm[r64];
    float mnew = fmaxf(mold, mt);
    float psum = 0.f;
#pragma unroll
    for (int j = 0; j < 16; j++) {
        float e = __expf(srow[j] - mnew);
        srow[j] = e;
        psum += e;
    }
    red2[p4 * 64 + r64] = psum;
    if (p4 == 0) { corr_s[r64] = __expf(mold - mnew); mnew_s[r64] = mnew; }
    __syncthreads();

    if (p4 == 0) {
        rowl[r64] = rowl[r64] * corr_s[r64] +
                    red2[r64] + red2[64 + r64] + red2[128 + r64] + red2[192 + r64];
        rowm[r64] = mnew_s[r64];
    }

    // rescale acc, then acc += P @ V
    float cf[4];
#pragma unroll
    for (int r = 0; r < 4; r++) cf[r] = corr_s[ty * 4 + r];
#pragma unroll
    for (int r = 0; r < 4; r++)
#pragma unroll
        for (int c = 0; c < 4; c++) acc[r][c] *= cf[r];

#pragma unroll 8
    for (int kk = 0; kk < 64; kk++) {
        float pr[4], vv[4];
#pragma unroll
        for (int r = 0; r < 4; r++) pr[r] = Ss[(ty * 4 + r) * FPAD + kk];
#pragma unroll
        for (int c = 0; c < 4; c++) vv[c] = Vs[kk * FPAD + tx * 4 + c];
#pragma unroll
        for (int r = 0; r < 4; r++)
#pragma unroll
            for (int c = 0; c < 4; c++) acc[r][c] = fmaf(pr[r], vv[c], acc[r][c]);
    }
}

__global__ __launch_bounds__(256) void flash_diff(
    const float* __restrict__ qb, const float* __restrict__ kb,
    const float* __restrict__ vb, float* __restrict__ yb)
{
    extern __shared__ float sm[];
    float* Q1  = sm;
    float* Q2  = Q1 + 64 * FPAD;
    float* K1s = Q2 + 64 * FPAD;
    float* K2s = K1s + 64 * FPAD;
    float* Vs  = K2s + 64 * FPAD;
    float* Ss  = Vs + 64 * FPAD;
    float* rowm1  = Ss + 64 * FPAD;
    float* rowl1  = rowm1 + 64;
    float* rowm2  = rowl1 + 64;
    float* rowl2  = rowm2 + 64;
    float* corr_s = rowl2 + 64;
    float* mnew_s = corr_s + 64;
    float* red    = mnew_s + 64;   // 256
    float* red2   = red + 256;     // 256

    const int tid = threadIdx.x;
    const int qi = blockIdx.x, h = blockIdx.y, b = blockIdx.z;
    const int q0 = qi * 64;
    const int ty = tid >> 4, tx = tid & 15;
    const int r64 = tid & 63, p4 = tid >> 6;

    // load Q tiles (once per block)
    const size_t qbase = ((size_t)(b * TT) + q0) * (2 * CC) + h * DHD;
    for (int e = tid; e < 4096; e += 256) {
        int row = e >> 6, d = e & 63;
        Q1[row * FPAD + d] = qb[qbase + (size_t)row * (2 * CC) + d];
        Q2[row * FPAD + d] = qb[qbase + (size_t)row * (2 * CC) + CC + d];
    }
    if (tid < 64) {
        rowm1[tid] = -1e30f; rowl1[tid] = 0.f;
        rowm2[tid] = -1e30f; rowl2[tid] = 0.f;
    }

    float acc1[4][4] = {}, acc2[4][4] = {};

    for (int kt = 0; kt <= qi; kt++) {
        const int k0 = kt * 64;
        __syncthreads();  // protect prior-iteration reads of K/V/Ss and init writes
        const size_t kbase = ((size_t)(b * TT) + k0) * (2 * CC) + h * DHD;
        const size_t vbase = ((size_t)(b * TT) + k0) * CC + h * DHD;
        for (int e = tid; e < 4096; e += 256) {
            int row = e >> 6, d = e & 63;
            K1s[row * FPAD + d] = kb[kbase + (size_t)row * (2 * CC) + d];
            K2s[row * FPAD + d] = kb[kbase + (size_t)row * (2 * CC) + CC + d];
            Vs[row * FPAD + d]  = vb[vbase + (size_t)row * CC + d];
        }
        __syncthreads();
        const bool diag = (kt == qi);

        att_pass(Q1, K1s, Vs, Ss, rowm1, rowl1, corr_s, mnew_s, red, red2,
                 acc1, ty, tx, r64, p4, diag);
        __syncthreads();  // att1's reads of Ss/corr done before att2 overwrites
        att_pass(Q2, K2s, Vs, Ss, rowm2, rowl2, corr_s, mnew_s, red, red2,
                 acc2, ty, tx, r64, p4, diag);
    }
    __syncthreads();

    const float lam = g_lambda;
#pragma unroll
    for (int r = 0; r < 4; r++) {
        int i = ty * 4 + r;
        float inv1 = 1.f / rowl1[i];
        float inv2 = lam / rowl2[i];
        float* orow = yb + ((size_t)(b * TT) + q0 + i) * CC + h * DHD + tx * 4;
#pragma unroll
        for (int c = 0; c < 4; c++)
            orow[c] = acc1[r][c] * inv1 - acc2[r][c] * inv2;
    }
}

// ---------------------------------------------------------------------------
// Launch
// ---------------------------------------------------------------------------
extern "C" void kernel_launch(void* const* d_in, const int* in_sizes, int n_in,
                              void* d_out, int out_size)
{
    const float* x   = (const float*)d_in[0];
    const float* wq  = (const float*)d_in[1];
    const float* wk  = (const float*)d_in[2];
    const float* wv  = (const float*)d_in[3];
    const float* wo  = (const float*)d_in[4];
    const float* lq1 = (const float*)d_in[5];
    const float* lk1 = (const float*)d_in[6];
    const float* lq2 = (const float*)d_in[7];
    const float* lk2 = (const float*)d_in[8];
    const float* wc  = (const float*)d_in[9];
    const float* bc  = (const float*)d_in[10];
    const float* we  = (const float*)d_in[11];
    const float* be  = (const float*)d_in[12];

    float *q, *k, *v, *y, *y2, *hb;
    cudaGetSymbolAddress((void**)&q,  g_q);
    cudaGetSymbolAddress((void**)&k,  g_k);
    cudaGetSymbolAddress((void**)&v,  g_v);
    cudaGetSymbolAddress((void**)&y,  g_y);
    cudaGetSymbolAddress((void**)&y2, g_y2);
    cudaGetSymbolAddress((void**)&hb, g_h);

    cudaFuncSetAttribute(flash_diff, cudaFuncAttributeMaxDynamicSharedMemorySize,
                         FLASH_SMEM);

    dim3 blk(256);
    // QKV projections
    sgemm_tn<<<dim3(2 * CC / 128, MT / 128), blk>>>(x, wq, nullptr, q, MT, 2 * CC, CC);
    sgemm_tn<<<dim3(2 * CC / 128, MT / 128), blk>>>(x, wk, nullptr, k, MT, 2 * CC, CC);
    sgemm_tn<<<dim3(CC / 128, MT / 128),     blk>>>(x, wv, nullptr, v, MT, CC, CC);
    // lambda scalar
    lambda_kernel<<<1, 32>>>(lq1, lk1, lq2, lk2);
    // fused differential attention
    flash_diff<<<dim3(TT / 64, HH, BB), blk, FLASH_SMEM>>>(q, k, v, y);
    // output projection + compressor
    sgemm_tn<<<dim3(CC / 128, MT / 128),     blk>>>(y,  wo, nullptr, y2, MT, CC, CC);
    sgemm_tn<<<dim3(CC / 2 / 128, MT / 128), blk>>>(y2, wc, bc, hb, MT, CC / 2, CC);
    sgemm_tn<<<dim3(CC / 128, MT / 128),     blk>>>(hb, we, be, (float*)d_out, MT, CC, CC / 2);
}

// round 4
// speedup vs baseline: 1.2715x; 1.2715x over previous
#include <cuda_runtime.h>
#include <math.h>
#include <stdint.h>

// Problem constants
#define BB 2
#define TT 2048
#define CC 1024
#define HH 16
#define DHD 64
#define MT (BB * TT)          // 4096 rows

// ---------------------------------------------------------------------------
// Scratch (device globals: allocation-free per harness rules)
// ---------------------------------------------------------------------------
__device__ float g_q[MT * 2 * CC];
__device__ float g_k[MT * 2 * CC];
__device__ float g_v[MT * CC];
__device__ float g_y[MT * CC];
__device__ float g_y2[MT * CC];
__device__ float g_h[MT * (CC / 2)];
__device__ float g_lambda;

// ---------------------------------------------------------------------------
// Small PTX helpers (all legal in compute_100 PTX: sm_80-era features)
// ---------------------------------------------------------------------------
__device__ __forceinline__ uint32_t smem_u32(const void* p) {
    uint32_t a;
    asm("{ .reg .u64 t; cvta.to.shared.u64 t, %1; cvt.u32.u64 %0, t; }"
        : "=r"(a) : "l"(p));
    return a;
}

__device__ __forceinline__ void cp_async16(uint32_t dst, const void* src) {
    asm volatile("cp.async.ca.shared.global [%0], [%1], 16;"
                 :: "r"(dst), "l"(src) : "memory");
}
#define CP_ASYNC_COMMIT() asm volatile("cp.async.commit_group;" ::: "memory")
#define CP_ASYNC_WAIT(n)  asm volatile("cp.async.wait_group %0;" :: "n"(n) : "memory")

__device__ __forceinline__ uint32_t f2tf32(float f) {
    uint32_t r;
    asm("cvt.rna.tf32.f32 %0, %1;" : "=r"(r) : "f"(f));
    return r;
}

// D += A*B  (m16n8k8, tf32 in, fp32 out)
__device__ __forceinline__ void mma_tf32(float* d, const uint32_t* a, const uint32_t* b) {
    asm volatile(
        "mma.sync.aligned.m16n8k8.row.col.f32.tf32.tf32.f32 "
        "{%0,%1,%2,%3}, {%4,%5,%6,%7}, {%8,%9}, {%0,%1,%2,%3};"
        : "+f"(d[0]), "+f"(d[1]), "+f"(d[2]), "+f"(d[3])
        : "r"(a[0]), "r"(a[1]), "r"(a[2]), "r"(a[3]), "r"(b[0]), "r"(b[1]));
}

// ---------------------------------------------------------------------------
// tf32 mma.sync TN GEMM: C[M,N] = A[M,K] @ B[N,K]^T (+ bias[N])
// 128x128 CTA tile, BK=32, 8 warps (2x4), warp tile 64x32, cp.async 2-stage.
// Requires M%128==0, N%128==0, K%32==0.
// ---------------------------------------------------------------------------
#define GBM 128
#define GBN 128
#define GBK 32
#define GPAD 36                           // floats per row; am*4+k bank pattern
#define G_TILE_F (GBM * GPAD)             // 4608 floats = 18432 B
#define G_BUF_F  (2 * G_TILE_F)           // A + B
#define GEMM_SMEM (2 * G_BUF_F * 4)       // 73728 B (double buffered)

__device__ __forceinline__ void g_stage(
    uint32_t sbuf, const float* __restrict__ Ag, const float* __restrict__ Bg,
    int K, int tid)
{
    // Ag/Bg point at the (m0, kchunk) corner. 1024 float4 copies per operand
    // tile / 256 threads = 4 each.
#pragma unroll
    for (int j = 0; j < 4; j++) {
        int linear = tid + j * 256;
        int m = linear & 127;
        int kg = linear >> 7;              // 0..7
        uint32_t off = (uint32_t)(m * GPAD + kg * 4) * 4u;
        cp_async16(sbuf + off, Ag + (size_t)m * K + kg * 4);
        cp_async16(sbuf + (uint32_t)G_TILE_F * 4u + off, Bg + (size_t)m * K + kg * 4);
    }
}

__global__ __launch_bounds__(256) void mma_gemm_tn(
    const float* __restrict__ A, const float* __restrict__ B,
    const float* __restrict__ bias, float* __restrict__ C,
    int M, int N, int K)
{
    extern __shared__ float smg[];
    const uint32_t sb = smem_u32(smg);
    const int tid = threadIdx.x;
    const int wid = tid >> 5, lane = tid & 31;
    const int wm = wid >> 2, wn = wid & 3;   // 2 x 4 warp grid
    const int lr = lane >> 2;                // 0..7
    const int lc = lane & 3;                 // 0..3
    const int m0 = blockIdx.y * GBM;
    const int n0 = blockIdx.x * GBN;

    const float* Ag = A + (size_t)m0 * K;
    const float* Bg = B + (size_t)n0 * K;

    float acc[4][4][4];
#pragma unroll
    for (int mt = 0; mt < 4; mt++)
#pragma unroll
        for (int nt = 0; nt < 4; nt++)
#pragma unroll
            for (int r = 0; r < 4; r++) acc[mt][nt][r] = 0.f;

    const int nch = K / GBK;

    g_stage(sb, Ag, Bg, K, tid);
    CP_ASYNC_COMMIT();

    for (int i = 0; i < nch; i++) {
        if (i + 1 < nch) {
            g_stage(sb + (uint32_t)(((i + 1) & 1) * G_BUF_F) * 4u,
                    Ag + (i + 1) * GBK, Bg + (i + 1) * GBK, K, tid);
            CP_ASYNC_COMMIT();
            CP_ASYNC_WAIT(1);
        } else {
            CP_ASYNC_WAIT(0);
        }
        __syncthreads();

        const float* Asf = smg + (i & 1) * G_BUF_F;
        const float* Bsf = Asf + G_TILE_F;

#pragma unroll
        for (int ks = 0; ks < 4; ks++) {
            const int k0 = ks * 8;
            uint32_t af[4][4], bf[4][2];
#pragma unroll
            for (int mt = 0; mt < 4; mt++) {
                const int am = wm * 64 + mt * 16 + lr;
                af[mt][0] = f2tf32(Asf[am * GPAD + k0 + lc]);
                af[mt][1] = f2tf32(Asf[(am + 8) * GPAD + k0 + lc]);
                af[mt][2] = f2tf32(Asf[am * GPAD + k0 + 4 + lc]);
                af[mt][3] = f2tf32(Asf[(am + 8) * GPAD + k0 + 4 + lc]);
            }
#pragma unroll
            for (int nt = 0; nt < 4; nt++) {
                const int bn = wn * 32 + nt * 8 + lr;
                bf[nt][0] = f2tf32(Bsf[bn * GPAD + k0 + lc]);
                bf[nt][1] = f2tf32(Bsf[bn * GPAD + k0 + 4 + lc]);
            }
#pragma unroll
            for (int mt = 0; mt < 4; mt++)
#pragma unroll
                for (int nt = 0; nt < 4; nt++)
                    mma_tf32(acc[mt][nt], af[mt], bf[nt]);
        }
        __syncthreads();
    }

    // epilogue
#pragma unroll
    for (int mt = 0; mt < 4; mt++) {
        const int row = m0 + wm * 64 + mt * 16 + lr;
#pragma unroll
        for (int nt = 0; nt < 4; nt++) {
            const int col = n0 + wn * 32 + nt * 8 + 2 * lc;
            float b0 = 0.f, b1 = 0.f;
            if (bias) { b0 = __ldg(bias + col); b1 = __ldg(bias + col + 1); }
            float2 v0 = make_float2(acc[mt][nt][0] + b0, acc[mt][nt][1] + b1);
            float2 v1 = make_float2(acc[mt][nt][2] + b0, acc[mt][nt][3] + b1);
            *(float2*)(C + (size_t)row * N + col) = v0;
            *(float2*)(C + (size_t)(row + 8) * N + col) = v1;
        }
    }
}

// ---------------------------------------------------------------------------
// Lambda scalar
// ---------------------------------------------------------------------------
__global__ void lambda_kernel(const float* __restrict__ lq1, const float* __restrict__ lk1,
                              const float* __restrict__ lq2, const float* __restrict__ lk2)
{
    if (threadIdx.x == 0) {
        float s1 = 0.f, s2 = 0.f;
        for (int i = 0; i < HH; i++) {
            s1 = fmaf(lq1[i], lk1[i], s1);
            s2 = fmaf(lq2[i], lk2[i], s2);
        }
        double li = 0.8 - 0.6 * exp(-0.3 * 11.0);  // N_LAYER=12
        g_lambda = (float)(exp((double)s1) - exp((double)s2) + li);
    }
}

// ---------------------------------------------------------------------------
// Fused differential flash attention (unchanged — known good, 3137us run).
// ---------------------------------------------------------------------------
#define FPAD 65
#define FLASH_SMEM ((6 * 64 * FPAD + 6 * 64 + 2 * 256) * 4)

__device__ __forceinline__ void att_pass(
    const float* __restrict__ Qs, const float* __restrict__ Ks,
    const float* __restrict__ Vs,
    float* Ss, float* rowm, float* rowl, float* corr_s, float* mnew_s,
    float* red, float* red2,
    float acc[4][4], int ty, int tx, int r64, int p4, bool diag)
{
    const float scale = 0.125f;
    float S[4][4];
#pragma unroll
    for (int r = 0; r < 4; r++)
#pragma unroll
        for (int c = 0; c < 4; c++) S[r][c] = 0.f;

#pragma unroll 8
    for (int d = 0; d < 64; d++) {
        float a[4], bq[4];
#pragma unroll
        for (int r = 0; r < 4; r++) a[r] = Qs[(ty * 4 + r) * FPAD + d];
#pragma unroll
        for (int c = 0; c < 4; c++) bq[c] = Ks[(tx * 4 + c) * FPAD + d];
#pragma unroll
        for (int r = 0; r < 4; r++)
#pragma unroll
            for (int c = 0; c < 4; c++) S[r][c] = fmaf(a[r], bq[c], S[r][c]);
    }

#pragma unroll
    for (int r = 0; r < 4; r++)
#pragma unroll
        for (int c = 0; c < 4; c++) {
            float v = S[r][c] * scale;
            if (diag && (tx * 4 + c) > (ty * 4 + r)) v = -1e30f;
            Ss[(ty * 4 + r) * FPAD + tx * 4 + c] = v;
        }
    __syncthreads();

    float* srow = Ss + r64 * FPAD + p4 * 16;
    float pmax = -1e30f;
#pragma unroll
    for (int j = 0; j < 16; j++) pmax = fmaxf(pmax, srow[j]);
    red[p4 * 64 + r64] = pmax;
    __syncthreads();

    float mt = fmaxf(fmaxf(red[r64], red[64 + r64]),
                     fmaxf(red[128 + r64], red[192 + r64]));
    float mold = rowm[r64];
    float mnew = fmaxf(mold, mt);
    float psum = 0.f;
#pragma unroll
    for (int j = 0; j < 16; j++) {
        float e = __expf(srow[j] - mnew);
        srow[j] = e;
        psum += e;
    }
    red2[p4 * 64 + r64] = psum;
    if (p4 == 0) { corr_s[r64] = __expf(mold - mnew); mnew_s[r64] = mnew; }
    __syncthreads();

    if (p4 == 0) {
        rowl[r64] = rowl[r64] * corr_s[r64] +
                    red2[r64] + red2[64 + r64] + red2[128 + r64] + red2[192 + r64];
        rowm[r64] = mnew_s[r64];
    }

    float cf[4];
#pragma unroll
    for (int r = 0; r < 4; r++) cf[r] = corr_s[ty * 4 + r];
#pragma unroll
    for (int r = 0; r < 4; r++)
#pragma unroll
        for (int c = 0; c < 4; c++) acc[r][c] *= cf[r];

#pragma unroll 8
    for (int kk = 0; kk < 64; kk++) {
        float pr[4], vv[4];
#pragma unroll
        for (int r = 0; r < 4; r++) pr[r] = Ss[(ty * 4 + r) * FPAD + kk];
#pragma unroll
        for (int c = 0; c < 4; c++) vv[c] = Vs[kk * FPAD + tx * 4 + c];
#pragma unroll
        for (int r = 0; r < 4; r++)
#pragma unroll
            for (int c = 0; c < 4; c++) acc[r][c] = fmaf(pr[r], vv[c], acc[r][c]);
    }
}

__global__ __launch_bounds__(256) void flash_diff(
    const float* __restrict__ qb, const float* __restrict__ kb,
    const float* __restrict__ vb, float* __restrict__ yb)
{
    extern __shared__ float smf[];
    float* Q1  = smf;
    float* Q2  = Q1 + 64 * FPAD;
    float* K1s = Q2 + 64 * FPAD;
    float* K2s = K1s + 64 * FPAD;
    float* Vs  = K2s + 64 * FPAD;
    float* Ss  = Vs + 64 * FPAD;
    float* rowm1  = Ss + 64 * FPAD;
    float* rowl1  = rowm1 + 64;
    float* rowm2  = rowl1 + 64;
    float* rowl2  = rowm2 + 64;
    float* corr_s = rowl2 + 64;
    float* mnew_s = corr_s + 64;
    float* red    = mnew_s + 64;
    float* red2   = red + 256;

    const int tid = threadIdx.x;
    const int qi = blockIdx.x, h = blockIdx.y, b = blockIdx.z;
    const int q0 = qi * 64;
    const int ty = tid >> 4, tx = tid & 15;
    const int r64 = tid & 63, p4 = tid >> 6;

    const size_t qbase = ((size_t)(b * TT) + q0) * (2 * CC) + h * DHD;
    for (int e = tid; e < 4096; e += 256) {
        int row = e >> 6, d = e & 63;
        Q1[row * FPAD + d] = qb[qbase + (size_t)row * (2 * CC) + d];
        Q2[row * FPAD + d] = qb[qbase + (size_t)row * (2 * CC) + CC + d];
    }
    if (tid < 64) {
        rowm1[tid] = -1e30f; rowl1[tid] = 0.f;
        rowm2[tid] = -1e30f; rowl2[tid] = 0.f;
    }

    float acc1[4][4] = {}, acc2[4][4] = {};

    for (int kt = 0; kt <= qi; kt++) {
        const int k0 = kt * 64;
        __syncthreads();
        const size_t kbase = ((size_t)(b * TT) + k0) * (2 * CC) + h * DHD;
        const size_t vbase = ((size_t)(b * TT) + k0) * CC + h * DHD;
        for (int e = tid; e < 4096; e += 256) {
            int row = e >> 6, d = e & 63;
            K1s[row * FPAD + d] = kb[kbase + (size_t)row * (2 * CC) + d];
            K2s[row * FPAD + d] = kb[kbase + (size_t)row * (2 * CC) + CC + d];
            Vs[row * FPAD + d]  = vb[vbase + (size_t)row * CC + d];
        }
        __syncthreads();
        const bool diag = (kt == qi);

        att_pass(Q1, K1s, Vs, Ss, rowm1, rowl1, corr_s, mnew_s, red, red2,
                 acc1, ty, tx, r64, p4, diag);
        __syncthreads();
        att_pass(Q2, K2s, Vs, Ss, rowm2, rowl2, corr_s, mnew_s, red, red2,
                 acc2, ty, tx, r64, p4, diag);
    }
    __syncthreads();

    const float lam = g_lambda;
#pragma unroll
    for (int r = 0; r < 4; r++) {
        int i = ty * 4 + r;
        float inv1 = 1.f / rowl1[i];
        float inv2 = lam / rowl2[i];
        float* orow = yb + ((size_t)(b * TT) + q0 + i) * CC + h * DHD + tx * 4;
#pragma unroll
        for (int c = 0; c < 4; c++)
            orow[c] = acc1[r][c] * inv1 - acc2[r][c] * inv2;
    }
}

// ---------------------------------------------------------------------------
// Launch
// ---------------------------------------------------------------------------
extern "C" void kernel_launch(void* const* d_in, const int* in_sizes, int n_in,
                              void* d_out, int out_size)
{
    const float* x   = (const float*)d_in[0];
    const float* wq  = (const float*)d_in[1];
    const float* wk  = (const float*)d_in[2];
    const float* wv  = (const float*)d_in[3];
    const float* wo  = (const float*)d_in[4];
    const float* lq1 = (const float*)d_in[5];
    const float* lk1 = (const float*)d_in[6];
    const float* lq2 = (const float*)d_in[7];
    const float* lk2 = (const float*)d_in[8];
    const float* wc  = (const float*)d_in[9];
    const float* bc  = (const float*)d_in[10];
    const float* we  = (const float*)d_in[11];
    const float* be  = (const float*)d_in[12];

    float *q, *k, *v, *y, *y2, *hb;
    cudaGetSymbolAddress((void**)&q,  g_q);
    cudaGetSymbolAddress((void**)&k,  g_k);
    cudaGetSymbolAddress((void**)&v,  g_v);
    cudaGetSymbolAddress((void**)&y,  g_y);
    cudaGetSymbolAddress((void**)&y2, g_y2);
    cudaGetSymbolAddress((void**)&hb, g_h);

    cudaFuncSetAttribute(mma_gemm_tn, cudaFuncAttributeMaxDynamicSharedMemorySize,
                         GEMM_SMEM);
    cudaFuncSetAttribute(flash_diff, cudaFuncAttributeMaxDynamicSharedMemorySize,
                         FLASH_SMEM);

    dim3 blk(256);
    // QKV projections (tf32 mma.sync)
    mma_gemm_tn<<<dim3(2 * CC / 128, MT / 128), blk, GEMM_SMEM>>>(x, wq, nullptr, q, MT, 2 * CC, CC);
    mma_gemm_tn<<<dim3(2 * CC / 128, MT / 128), blk, GEMM_SMEM>>>(x, wk, nullptr, k, MT, 2 * CC, CC);
    mma_gemm_tn<<<dim3(CC / 128, MT / 128),     blk, GEMM_SMEM>>>(x, wv, nullptr, v, MT, CC, CC);
    // lambda scalar
    lambda_kernel<<<1, 32>>>(lq1, lk1, lq2, lk2);
    // fused differential attention
    flash_diff<<<dim3(TT / 64, HH, BB), blk, FLASH_SMEM>>>(q, k, v, y);
    // output projection + compressor
    mma_gemm_tn<<<dim3(CC / 128, MT / 128),     blk, GEMM_SMEM>>>(y,  wo, nullptr, y2, MT, CC, CC);
    mma_gemm_tn<<<dim3(CC / 2 / 128, MT / 128), blk, GEMM_SMEM>>>(y2, wc, bc, hb, MT, CC / 2, CC);
    mma_gemm_tn<<<dim3(CC / 128, MT / 128),     blk, GEMM_SMEM>>>(hb, we, be, (float*)d_out, MT, CC, CC / 2);
}

// round 5
// speedup vs baseline: 1.4136x; 1.1118x over previous
#include <cuda_runtime.h>
#include <math.h>
#include <stdint.h>

// Problem constants
#define BB 2
#define TT 2048
#define CC 1024
#define HH 16
#define DHD 64
#define MT (BB * TT)          // 4096 rows

// ---------------------------------------------------------------------------
// Scratch (device globals)
// ---------------------------------------------------------------------------
__device__ float g_q[MT * 2 * CC];
__device__ float g_k[MT * 2 * CC];
__device__ float g_v[MT * CC];
__device__ float g_y[MT * CC];
__device__ float g_y2[MT * CC];
__device__ float g_h[MT * (CC / 2)];
__device__ float g_lambda;

// ---------------------------------------------------------------------------
// PTX helpers (compute_100-legal: sm_80-era features only)
// ---------------------------------------------------------------------------
__device__ __forceinline__ uint32_t smem_u32(const void* p) {
    uint32_t a;
    asm("{ .reg .u64 t; cvta.to.shared.u64 t, %1; cvt.u32.u64 %0, t; }"
        : "=r"(a) : "l"(p));
    return a;
}

__device__ __forceinline__ void cp_async16(uint32_t dst, const void* src) {
    asm volatile("cp.async.ca.shared.global [%0], [%1], 16;"
                 :: "r"(dst), "l"(src) : "memory");
}
#define CP_ASYNC_COMMIT() asm volatile("cp.async.commit_group;" ::: "memory")
#define CP_ASYNC_WAIT(n)  asm volatile("cp.async.wait_group %0;" :: "n"(n) : "memory")

__device__ __forceinline__ uint32_t f2tf32(float f) {
    uint32_t r;
    asm("cvt.rna.tf32.f32 %0, %1;" : "=r"(r) : "f"(f));
    return r;
}

// D += A*B  (m16n8k8, tf32 in, fp32 out)
__device__ __forceinline__ void mma_tf32(float* d, const uint32_t* a, const uint32_t* b) {
    asm volatile(
        "mma.sync.aligned.m16n8k8.row.col.f32.tf32.tf32.f32 "
        "{%0,%1,%2,%3}, {%4,%5,%6,%7}, {%8,%9}, {%0,%1,%2,%3};"
        : "+f"(d[0]), "+f"(d[1]), "+f"(d[2]), "+f"(d[3])
        : "r"(a[0]), "r"(a[1]), "r"(a[2]), "r"(a[3]), "r"(b[0]), "r"(b[1]));
}

// split x into tf32 hi + tf32 lo (3xTF32 compensation)
__device__ __forceinline__ void split_tf32(float x, uint32_t& hi, uint32_t& lo) {
    hi = f2tf32(x);
    lo = f2tf32(x - __uint_as_float(hi));
}

// ---------------------------------------------------------------------------
// 3xTF32 mma.sync TN GEMM: C[M,N] = A[M,K] @ B[N,K]^T (+ bias[N])
// 128x128 CTA tile, BK=32, 8 warps (2x4), cp.async 2-stage.
// Optional dual mode: gridDim.z==2 -> z=1 uses (B2, C2). Same A.
// ---------------------------------------------------------------------------
#define GBM 128
#define GBN 128
#define GBK 32
#define GPAD 36
#define G_TILE_F (GBM * GPAD)
#define G_BUF_F  (2 * G_TILE_F)
#define GEMM_SMEM (2 * G_BUF_F * 4)       // 73728 B

__device__ __forceinline__ void g_stage(
    uint32_t sbuf, const float* __restrict__ Ag, const float* __restrict__ Bg,
    int K, int tid)
{
#pragma unroll
    for (int j = 0; j < 4; j++) {
        int linear = tid + j * 256;
        int m = linear & 127;
        int kg = linear >> 7;
        uint32_t off = (uint32_t)(m * GPAD + kg * 4) * 4u;
        cp_async16(sbuf + off, Ag + (size_t)m * K + kg * 4);
        cp_async16(sbuf + (uint32_t)G_TILE_F * 4u + off, Bg + (size_t)m * K + kg * 4);
    }
}

__global__ __launch_bounds__(256) void mma_gemm_tn(
    const float* __restrict__ A, const float* __restrict__ B,
    const float* __restrict__ bias, float* __restrict__ C,
    const float* __restrict__ B2, float* __restrict__ C2,
    int M, int N, int K)
{
    extern __shared__ float smg[];
    const uint32_t sb = smem_u32(smg);
    const int tid = threadIdx.x;
    const int wid = tid >> 5, lane = tid & 31;
    const int wm = wid >> 2, wn = wid & 3;
    const int lr = lane >> 2;
    const int lc = lane & 3;
    const int m0 = blockIdx.y * GBM;
    const int n0 = blockIdx.x * GBN;

    if (blockIdx.z == 1) { B = B2; C = C2; }

    const float* Ag = A + (size_t)m0 * K;
    const float* Bg = B + (size_t)n0 * K;

    float acc[4][4][4];
#pragma unroll
    for (int mt = 0; mt < 4; mt++)
#pragma unroll
        for (int nt = 0; nt < 4; nt++)
#pragma unroll
            for (int r = 0; r < 4; r++) acc[mt][nt][r] = 0.f;

    const int nch = K / GBK;

    g_stage(sb, Ag, Bg, K, tid);
    CP_ASYNC_COMMIT();

    for (int i = 0; i < nch; i++) {
        if (i + 1 < nch) {
            g_stage(sb + (uint32_t)(((i + 1) & 1) * G_BUF_F) * 4u,
                    Ag + (i + 1) * GBK, Bg + (i + 1) * GBK, K, tid);
            CP_ASYNC_COMMIT();
            CP_ASYNC_WAIT(1);
        } else {
            CP_ASYNC_WAIT(0);
        }
        __syncthreads();

        const float* Asf = smg + (i & 1) * G_BUF_F;
        const float* Bsf = Asf + G_TILE_F;

#pragma unroll
        for (int ks = 0; ks < 4; ks++) {
            const int k0 = ks * 8;
            uint32_t ah[4][4], al[4][4];
#pragma unroll
            for (int mt = 0; mt < 4; mt++) {
                const int am = wm * 64 + mt * 16 + lr;
                split_tf32(Asf[am * GPAD + k0 + lc],           ah[mt][0], al[mt][0]);
                split_tf32(Asf[(am + 8) * GPAD + k0 + lc],     ah[mt][1], al[mt][1]);
                split_tf32(Asf[am * GPAD + k0 + 4 + lc],       ah[mt][2], al[mt][2]);
                split_tf32(Asf[(am + 8) * GPAD + k0 + 4 + lc], ah[mt][3], al[mt][3]);
            }
#pragma unroll
            for (int nt = 0; nt < 4; nt++) {
                const int bn = wn * 32 + nt * 8 + lr;
                uint32_t bh[2], bl[2];
                split_tf32(Bsf[bn * GPAD + k0 + lc],     bh[0], bl[0]);
                split_tf32(Bsf[bn * GPAD + k0 + 4 + lc], bh[1], bl[1]);
#pragma unroll
                for (int mt = 0; mt < 4; mt++) {
                    mma_tf32(acc[mt][nt], al[mt], bh);   // lo*hi
                    mma_tf32(acc[mt][nt], ah[mt], bl);   // hi*lo
                    mma_tf32(acc[mt][nt], ah[mt], bh);   // hi*hi (last: biggest term)
                }
            }
        }
        __syncthreads();
    }

    // epilogue
#pragma unroll
    for (int mt = 0; mt < 4; mt++) {
        const int row = m0 + wm * 64 + mt * 16 + lr;
#pragma unroll
        for (int nt = 0; nt < 4; nt++) {
            const int col = n0 + wn * 32 + nt * 8 + 2 * lc;
            float b0 = 0.f, b1 = 0.f;
            if (bias) { b0 = __ldg(bias + col); b1 = __ldg(bias + col + 1); }
            float2 v0 = make_float2(acc[mt][nt][0] + b0, acc[mt][nt][1] + b1);
            float2 v1 = make_float2(acc[mt][nt][2] + b0, acc[mt][nt][3] + b1);
            *(float2*)(C + (size_t)row * N + col) = v0;
            *(float2*)(C + (size_t)(row + 8) * N + col) = v1;
        }
    }
}

// ---------------------------------------------------------------------------
// Lambda scalar
// ---------------------------------------------------------------------------
__global__ void lambda_kernel(const float* __restrict__ lq1, const float* __restrict__ lk1,
                              const float* __restrict__ lq2, const float* __restrict__ lk2)
{
    if (threadIdx.x == 0) {
        float s1 = 0.f, s2 = 0.f;
        for (int i = 0; i < HH; i++) {
            s1 = fmaf(lq1[i], lk1[i], s1);
            s2 = fmaf(lq2[i], lk2[i], s2);
        }
        double li = 0.8 - 0.6 * exp(-0.3 * 11.0);  // N_LAYER=12
        g_lambda = (float)(exp((double)s1) - exp((double)s2) + li);
    }
}

// ---------------------------------------------------------------------------
// Differential flash attention with mma.sync tf32.
// Block = (qtile 64, h, b). 256 threads = 8 warps, grid 4(wm rows)x2(wn cols).
// S = Q@K^T and O += P@V on tensor cores; online softmax in registers.
// V is staged transposed (Vt[d][key]) to serve as the col-major B operand.
// ---------------------------------------------------------------------------
#define APAD 68
#define FLASH_SMEM ((6 * 64 * APAD + 256) * 4)

__device__ __forceinline__ void lda_frag(const float* S, int row0, int k0,
                                         int lr, int lc, uint32_t a[4]) {
    a[0] = f2tf32(S[(row0 + lr) * APAD + k0 + lc]);
    a[1] = f2tf32(S[(row0 + lr + 8) * APAD + k0 + lc]);
    a[2] = f2tf32(S[(row0 + lr) * APAD + k0 + 4 + lc]);
    a[3] = f2tf32(S[(row0 + lr + 8) * APAD + k0 + 4 + lc]);
}
__device__ __forceinline__ void ldb_frag(const float* S, int n0, int k0,
                                         int lr, int lc, uint32_t b[2]) {
    b[0] = f2tf32(S[(n0 + lr) * APAD + k0 + lc]);
    b[1] = f2tf32(S[(n0 + lr) * APAD + k0 + 4 + lc]);
}

__device__ __forceinline__ void process_branch(
    const float* __restrict__ Qs, const float* __restrict__ Ks,
    const float* __restrict__ Vt, float* __restrict__ Ps,
    float* __restrict__ redm, float* __restrict__ redl,
    float (&acc)[4][4], float& m0, float& m1, float& l0, float& l1,
    bool diag, int wm, int wn, int lr, int lc, int rl0)
{
    const float scale = 0.125f;  // 1/sqrt(64)
    float s[4][4];
#pragma unroll
    for (int nt = 0; nt < 4; nt++)
#pragma unroll
        for (int r = 0; r < 4; r++) s[nt][r] = 0.f;

    // S = Q @ K^T
#pragma unroll
    for (int k0 = 0; k0 < 64; k0 += 8) {
        uint32_t a[4];
        lda_frag(Qs, wm * 16, k0, lr, lc, a);
#pragma unroll
        for (int nt = 0; nt < 4; nt++) {
            uint32_t bq[2];
            ldb_frag(Ks, wn * 32 + nt * 8, k0, lr, lc, bq);
            mma_tf32(s[nt], a, bq);
        }
    }

    // scale + causal mask (register space)
    const int r0 = rl0, r1 = rl0 + 8;   // local rows == global offset within tile
#pragma unroll
    for (int nt = 0; nt < 4; nt++) {
        const int c0 = wn * 32 + nt * 8 + 2 * lc;
        s[nt][0] *= scale; s[nt][1] *= scale;
        s[nt][2] *= scale; s[nt][3] *= scale;
        if (diag) {
            if (c0 > r0)     s[nt][0] = -1e30f;
            if (c0 + 1 > r0) s[nt][1] = -1e30f;
            if (c0 > r1)     s[nt][2] = -1e30f;
            if (c0 + 1 > r1) s[nt][3] = -1e30f;
        }
    }

    // row max (thread-local -> quad shuffle -> cross-warp smem)
    float mx0 = -1e30f, mx1 = -1e30f;
#pragma unroll
    for (int nt = 0; nt < 4; nt++) {
        mx0 = fmaxf(mx0, fmaxf(s[nt][0], s[nt][1]));
        mx1 = fmaxf(mx1, fmaxf(s[nt][2], s[nt][3]));
    }
    mx0 = fmaxf(mx0, __shfl_xor_sync(0xffffffffu, mx0, 1));
    mx0 = fmaxf(mx0, __shfl_xor_sync(0xffffffffu, mx0, 2));
    mx1 = fmaxf(mx1, __shfl_xor_sync(0xffffffffu, mx1, 1));
    mx1 = fmaxf(mx1, __shfl_xor_sync(0xffffffffu, mx1, 2));
    if (lc == 0) {
        redm[wn * 64 + r0] = mx0;
        redm[wn * 64 + r1] = mx1;
    }
    __syncthreads();

    const float tm0 = fmaxf(redm[r0], redm[64 + r0]);
    const float tm1 = fmaxf(redm[r1], redm[64 + r1]);
    const float mn0 = fmaxf(m0, tm0);
    const float mn1 = fmaxf(m1, tm1);
    const float cr0 = __expf(m0 - mn0);
    const float cr1 = __expf(m1 - mn1);

    // exp, partial sums, write P to smem
    float ps0 = 0.f, ps1 = 0.f;
#pragma unroll
    for (int nt = 0; nt < 4; nt++) {
        const int cl = wn * 32 + nt * 8 + 2 * lc;
        float p0 = __expf(s[nt][0] - mn0);
        float p1 = __expf(s[nt][1] - mn0);
        float p2 = __expf(s[nt][2] - mn1);
        float p3 = __expf(s[nt][3] - mn1);
        ps0 += p0 + p1;
        ps1 += p2 + p3;
        *(float2*)&Ps[r0 * APAD + cl] = make_float2(p0, p1);
        *(float2*)&Ps[r1 * APAD + cl] = make_float2(p2, p3);
    }
    ps0 += __shfl_xor_sync(0xffffffffu, ps0, 1);
    ps0 += __shfl_xor_sync(0xffffffffu, ps0, 2);
    ps1 += __shfl_xor_sync(0xffffffffu, ps1, 1);
    ps1 += __shfl_xor_sync(0xffffffffu, ps1, 2);
    if (lc == 0) {
        redl[wn * 64 + r0] = ps0;
        redl[wn * 64 + r1] = ps1;
    }

    // rescale O accumulator
#pragma unroll
    for (int nt = 0; nt < 4; nt++) {
        acc[nt][0] *= cr0; acc[nt][1] *= cr0;
        acc[nt][2] *= cr1; acc[nt][3] *= cr1;
    }
    m0 = mn0; m1 = mn1;
    __syncthreads();

    l0 = l0 * cr0 + redl[r0] + redl[64 + r0];
    l1 = l1 * cr1 + redl[r1] + redl[64 + r1];

    // O += P @ V  (K dim = 64 keys)
#pragma unroll
    for (int k0 = 0; k0 < 64; k0 += 8) {
        uint32_t a[4];
        lda_frag(Ps, wm * 16, k0, lr, lc, a);
#pragma unroll
        for (int nt = 0; nt < 4; nt++) {
            uint32_t bv[2];
            ldb_frag(Vt, wn * 32 + nt * 8, k0, lr, lc, bv);
            mma_tf32(acc[nt], a, bv);
        }
    }
}

__global__ __launch_bounds__(256) void flash_diff_mma(
    const float* __restrict__ qb, const float* __restrict__ kb,
    const float* __restrict__ vb, float* __restrict__ yb)
{
    extern __shared__ float smf[];
    float* Q1 = smf;
    float* Q2 = Q1 + 64 * APAD;
    float* K1 = Q2 + 64 * APAD;
    float* K2 = K1 + 64 * APAD;
    float* Vt = K2 + 64 * APAD;
    float* Ps = Vt + 64 * APAD;
    float* redm = Ps + 64 * APAD;   // 128 floats
    float* redl = redm + 128;       // 128 floats

    const int tid = threadIdx.x;
    const int wid = tid >> 5, lane = tid & 31;
    const int wm = wid >> 1, wn = wid & 1;
    const int lr = lane >> 2, lc = lane & 3;
    const int qi = blockIdx.x, h = blockIdx.y, b = blockIdx.z;
    const int q0 = qi * 64;
    const int rl0 = wm * 16 + lr;

    // stage Q (once per block)
    const size_t qbase = ((size_t)(b * TT) + q0) * (2 * CC) + h * DHD;
#pragma unroll
    for (int j = 0; j < 4; j++) {
        int idx = tid + j * 256;
        int row = idx >> 4, c4 = (idx & 15) * 4;
        float4 v1 = *(const float4*)(qb + qbase + (size_t)row * (2 * CC) + c4);
        float4 v2 = *(const float4*)(qb + qbase + (size_t)row * (2 * CC) + CC + c4);
        *(float4*)&Q1[row * APAD + c4] = v1;
        *(float4*)&Q2[row * APAD + c4] = v2;
    }

    float acc1[4][4] = {}, acc2[4][4] = {};
    float m10 = -1e30f, m11 = -1e30f, l10 = 0.f, l11 = 0.f;
    float m20 = -1e30f, m21 = -1e30f, l20 = 0.f, l21 = 0.f;

    for (int kt = 0; kt <= qi; kt++) {
        const int k0t = kt * 64;
        __syncthreads();   // prior-iteration smem reads done
        const size_t kbase = ((size_t)(b * TT) + k0t) * (2 * CC) + h * DHD;
        const size_t vbase = ((size_t)(b * TT) + k0t) * CC + h * DHD;
#pragma unroll
        for (int j = 0; j < 4; j++) {
            int idx = tid + j * 256;
            int row = idx >> 4, c4 = (idx & 15) * 4;
            float4 kv1 = *(const float4*)(kb + kbase + (size_t)row * (2 * CC) + c4);
            float4 kv2 = *(const float4*)(kb + kbase + (size_t)row * (2 * CC) + CC + c4);
            float4 vv  = *(const float4*)(vb + vbase + (size_t)row * CC + c4);
            *(float4*)&K1[row * APAD + c4] = kv1;
            *(float4*)&K2[row * APAD + c4] = kv2;
            Vt[(c4 + 0) * APAD + row] = vv.x;
            Vt[(c4 + 1) * APAD + row] = vv.y;
            Vt[(c4 + 2) * APAD + row] = vv.z;
            Vt[(c4 + 3) * APAD + row] = vv.w;
        }
        __syncthreads();
        const bool diag = (kt == qi);

        process_branch(Q1, K1, Vt, Ps, redm, redl, acc1, m10, m11, l10, l11,
                       diag, wm, wn, lr, lc, rl0);
        process_branch(Q2, K2, Vt, Ps, redm, redl, acc2, m20, m21, l20, l21,
                       diag, wm, wn, lr, lc, rl0);
    }

    // epilogue: y = P1V/l1 - lam * P2V/l2
    const float lam = g_lambda;
    const float i10 = 1.f / l10, i11 = 1.f / l11;
    const float i20 = lam / l20, i21 = lam / l21;
    const int r0g = q0 + rl0, r1g = r0g + 8;
#pragma unroll
    for (int nt = 0; nt < 4; nt++) {
        const int col = h * DHD + wn * 32 + nt * 8 + 2 * lc;
        float2 o0 = make_float2(acc1[nt][0] * i10 - acc2[nt][0] * i20,
                                acc1[nt][1] * i10 - acc2[nt][1] * i20);
        float2 o1 = make_float2(acc1[nt][2] * i11 - acc2[nt][2] * i21,
                                acc1[nt][3] * i11 - acc2[nt][3] * i21);
        *(float2*)(yb + ((size_t)(b * TT) + r0g) * CC + col) = o0;
        *(float2*)(yb + ((size_t)(b * TT) + r1g) * CC + col) = o1;
    }
}

// ---------------------------------------------------------------------------
// Launch. Order chosen so ncu's fixed sample slot (launch index 3) lands on
// flash_diff_mma: lambda(0), qk-fused(1), v(2), flash(3), wo(4), wc(5), we(6).
// ---------------------------------------------------------------------------
extern "C" void kernel_launch(void* const* d_in, const int* in_sizes, int n_in,
                              void* d_out, int out_size)
{
    const float* x   = (const float*)d_in[0];
    const float* wq  = (const float*)d_in[1];
    const float* wk  = (const float*)d_in[2];
    const float* wv  = (const float*)d_in[3];
    const float* wo  = (const float*)d_in[4];
    const float* lq1 = (const float*)d_in[5];
    const float* lk1 = (const float*)d_in[6];
    const float* lq2 = (const float*)d_in[7];
    const float* lk2 = (const float*)d_in[8];
    const float* wc  = (const float*)d_in[9];
    const float* bc  = (const float*)d_in[10];
    const float* we  = (const float*)d_in[11];
    const float* be  = (const float*)d_in[12];

    float *q, *k, *v, *y, *y2, *hb;
    cudaGetSymbolAddress((void**)&q,  g_q);
    cudaGetSymbolAddress((void**)&k,  g_k);
    cudaGetSymbolAddress((void**)&v,  g_v);
    cudaGetSymbolAddress((void**)&y,  g_y);
    cudaGetSymbolAddress((void**)&y2, g_y2);
    cudaGetSymbolAddress((void**)&hb, g_h);

    cudaFuncSetAttribute(mma_gemm_tn, cudaFuncAttributeMaxDynamicSharedMemorySize,
                         GEMM_SMEM);
    cudaFuncSetAttribute(flash_diff_mma, cudaFuncAttributeMaxDynamicSharedMemorySize,
                         FLASH_SMEM);

    dim3 blk(256);
    lambda_kernel<<<1, 32>>>(lq1, lk1, lq2, lk2);
    // fused Q+K projection (z=0 -> wq/q, z=1 -> wk/k)
    mma_gemm_tn<<<dim3(2 * CC / 128, MT / 128, 2), blk, GEMM_SMEM>>>(
        x, wq, nullptr, q, wk, k, MT, 2 * CC, CC);
    mma_gemm_tn<<<dim3(CC / 128, MT / 128, 1),     blk, GEMM_SMEM>>>(
        x, wv, nullptr, v, nullptr, nullptr, MT, CC, CC);
    // fused differential attention (tensor cores)
    flash_diff_mma<<<dim3(TT / 64, HH, BB), blk, FLASH_SMEM>>>(q, k, v, y);
    // output projection + compressor
    mma_gemm_tn<<<dim3(CC / 128, MT / 128, 1),     blk, GEMM_SMEM>>>(
        y,  wo, nullptr, y2, nullptr, nullptr, MT, CC, CC);
    mma_gemm_tn<<<dim3(CC / 2 / 128, MT / 128, 1), blk, GEMM_SMEM>>>(
        y2, wc, bc, hb, nullptr, nullptr, MT, CC / 2, CC);
    mma_gemm_tn<<<dim3(CC / 128, MT / 128, 1),     blk, GEMM_SMEM>>>(
        hb, we, be, (float*)d_out, nullptr, nullptr, MT, CC, CC / 2);
}

// round 6
// speedup vs baseline: 1.8000x; 1.2733x over previous
#include <cuda_runtime.h>
#include <math.h>
#include <stdint.h>

// Problem constants
#define BB 2
#define TT 2048
#define CC 1024
#define HH 16
#define DHD 64
#define MT (BB * TT)          // 4096 rows

// ---------------------------------------------------------------------------
// Scratch (device globals)
// ---------------------------------------------------------------------------
__device__ float g_q[MT * 2 * CC];
__device__ float g_k[MT * 2 * CC];
__device__ float g_v[MT * CC];
__device__ float g_y[MT * CC];
__device__ float g_y2[MT * CC];
__device__ float g_h[MT * (CC / 2)];
__device__ float g_lambda;

// ---------------------------------------------------------------------------
// PTX helpers (compute_100-legal)
// ---------------------------------------------------------------------------
__device__ __forceinline__ uint32_t smem_u32(const void* p) {
    uint32_t a;
    asm("{ .reg .u64 t; cvta.to.shared.u64 t, %1; cvt.u32.u64 %0, t; }"
        : "=r"(a) : "l"(p));
    return a;
}

__device__ __forceinline__ void cp_async16(uint32_t dst, const void* src) {
    asm volatile("cp.async.ca.shared.global [%0], [%1], 16;"
                 :: "r"(dst), "l"(src) : "memory");
}
#define CP_ASYNC_COMMIT() asm volatile("cp.async.commit_group;" ::: "memory")
#define CP_ASYNC_WAIT(n)  asm volatile("cp.async.wait_group %0;" :: "n"(n) : "memory")

__device__ __forceinline__ uint32_t f2tf32(float f) {
    uint32_t r;
    asm("cvt.rna.tf32.f32 %0, %1;" : "=r"(r) : "f"(f));
    return r;
}

// tf32 m16n8k8 (used by attention)
__device__ __forceinline__ void mma_tf32(float* d, const uint32_t* a, const uint32_t* b) {
    asm volatile(
        "mma.sync.aligned.m16n8k8.row.col.f32.tf32.tf32.f32 "
        "{%0,%1,%2,%3}, {%4,%5,%6,%7}, {%8,%9}, {%0,%1,%2,%3};"
        : "+f"(d[0]), "+f"(d[1]), "+f"(d[2]), "+f"(d[3])
        : "r"(a[0]), "r"(a[1]), "r"(a[2]), "r"(a[3]), "r"(b[0]), "r"(b[1]));
}

// bf16 m16n8k16 (used by GEMMs)
__device__ __forceinline__ void mma_bf16(float* d, const uint32_t* a, const uint32_t* b) {
    asm volatile(
        "mma.sync.aligned.m16n8k16.row.col.f32.bf16.bf16.f32 "
        "{%0,%1,%2,%3}, {%4,%5,%6,%7}, {%8,%9}, {%0,%1,%2,%3};"
        : "+f"(d[0]), "+f"(d[1]), "+f"(d[2]), "+f"(d[3])
        : "r"(a[0]), "r"(a[1]), "r"(a[2]), "r"(a[3]), "r"(b[0]), "r"(b[1]));
}

// pack two fp32 -> bf16x2 reg: elem0 in low half, elem1 in high half
__device__ __forceinline__ uint32_t pack_bf16x2(float e0, float e1) {
    uint32_t r;
    asm("cvt.rn.bf16x2.f32 %0, %1, %2;" : "=r"(r) : "f"(e1), "f"(e0));
    return r;
}

// split pair (x0, x1) into packed bf16 hi + bf16 lo (precision-doubling)
__device__ __forceinline__ void split2(float x0, float x1, uint32_t& h, uint32_t& l) {
    h = pack_bf16x2(x0, x1);
    float h0 = __uint_as_float(h << 16);
    float h1 = __uint_as_float(h & 0xffff0000u);
    l = pack_bf16x2(x0 - h0, x1 - h1);
}

// ---------------------------------------------------------------------------
// bf16x3 mma.sync TN GEMM: C[M,N] = A[M,K] @ B[N,K]^T (+ bias[N])
// 128x128 CTA tile, BK=32, 8 warps (2x4), cp.async 2-stage fp32 smem.
// Operands split hi/lo bf16 at fragment load; 3 x m16n8k16 per product.
// Requires M%128==0, N%128==0, K%32==0.
// ---------------------------------------------------------------------------
#define GBM 128
#define GBN 128
#define GBK 32
#define GPAD 40                           // fp32/row; float2 frag loads conflict-free
#define G_TILE_F (GBM * GPAD)             // 5120 floats
#define G_BUF_F  (2 * G_TILE_F)           // A + B per stage
#define GEMM_SMEM (2 * G_BUF_F * 4)       // 81920 B (double buffered)

__device__ __forceinline__ void g_stage(
    uint32_t sbuf, const float* __restrict__ Ag, const float* __restrict__ Bg,
    int K, int tid)
{
#pragma unroll
    for (int j = 0; j < 4; j++) {
        int linear = tid + j * 256;
        int m = linear & 127;
        int kg = linear >> 7;              // 0..7
        uint32_t off = (uint32_t)(m * GPAD + kg * 4) * 4u;
        cp_async16(sbuf + off, Ag + (size_t)m * K + kg * 4);
        cp_async16(sbuf + (uint32_t)G_TILE_F * 4u + off, Bg + (size_t)m * K + kg * 4);
    }
}

__global__ __launch_bounds__(256) void mma_gemm_tn(
    const float* __restrict__ A, const float* __restrict__ B,
    const float* __restrict__ bias, float* __restrict__ C,
    int M, int N, int K)
{
    extern __shared__ float smg[];
    const uint32_t sb = smem_u32(smg);
    const int tid = threadIdx.x;
    const int wid = tid >> 5, lane = tid & 31;
    const int wm = wid >> 2, wn = wid & 3;   // 2 x 4 warp grid
    const int lr = lane >> 2;                // 0..7
    const int lc = lane & 3;                 // 0..3
    const int m0 = blockIdx.y * GBM;
    const int n0 = blockIdx.x * GBN;

    const float* Ag = A + (size_t)m0 * K;
    const float* Bg = B + (size_t)n0 * K;

    float acc[4][4][4];
#pragma unroll
    for (int mt = 0; mt < 4; mt++)
#pragma unroll
        for (int nt = 0; nt < 4; nt++)
#pragma unroll
            for (int r = 0; r < 4; r++) acc[mt][nt][r] = 0.f;

    const int nch = K / GBK;

    g_stage(sb, Ag, Bg, K, tid);
    CP_ASYNC_COMMIT();

    for (int i = 0; i < nch; i++) {
        if (i + 1 < nch) {
            g_stage(sb + (uint32_t)(((i + 1) & 1) * G_BUF_F) * 4u,
                    Ag + (i + 1) * GBK, Bg + (i + 1) * GBK, K, tid);
            CP_ASYNC_COMMIT();
            CP_ASYNC_WAIT(1);
        } else {
            CP_ASYNC_WAIT(0);
        }
        __syncthreads();

        const float* Asf = smg + (i & 1) * G_BUF_F;
        const float* Bsf = Asf + G_TILE_F;

#pragma unroll
        for (int ks = 0; ks < 2; ks++) {
            const int k0 = ks * 16;
            // hoist all B fragments for this k-step (hi+lo)
            uint32_t bh[4][2], bl[4][2];
#pragma unroll
            for (int nt = 0; nt < 4; nt++) {
                const int bn = wn * 32 + nt * 8 + lr;
                float2 p0 = *(const float2*)&Bsf[bn * GPAD + k0 + 2 * lc];
                float2 p1 = *(const float2*)&Bsf[bn * GPAD + k0 + 8 + 2 * lc];
                split2(p0.x, p0.y, bh[nt][0], bl[nt][0]);
                split2(p1.x, p1.y, bh[nt][1], bl[nt][1]);
            }
#pragma unroll
            for (int mt = 0; mt < 4; mt++) {
                const int am = wm * 64 + mt * 16 + lr;
                float2 a0 = *(const float2*)&Asf[am * GPAD + k0 + 2 * lc];
                float2 a1 = *(const float2*)&Asf[(am + 8) * GPAD + k0 + 2 * lc];
                float2 a2 = *(const float2*)&Asf[am * GPAD + k0 + 8 + 2 * lc];
                float2 a3 = *(const float2*)&Asf[(am + 8) * GPAD + k0 + 8 + 2 * lc];
                uint32_t ah[4], al[4];
                split2(a0.x, a0.y, ah[0], al[0]);
                split2(a1.x, a1.y, ah[1], al[1]);
                split2(a2.x, a2.y, ah[2], al[2]);
                split2(a3.x, a3.y, ah[3], al[3]);
#pragma unroll
                for (int nt = 0; nt < 4; nt++) {
                    mma_bf16(acc[mt][nt], al, bh[nt]);   // lo*hi
                    mma_bf16(acc[mt][nt], ah, bl[nt]);   // hi*lo
                    mma_bf16(acc[mt][nt], ah, bh[nt]);   // hi*hi last (largest)
                }
            }
        }
        __syncthreads();
    }

    // epilogue
#pragma unroll
    for (int mt = 0; mt < 4; mt++) {
        const int row = m0 + wm * 64 + mt * 16 + lr;
#pragma unroll
        for (int nt = 0; nt < 4; nt++) {
            const int col = n0 + wn * 32 + nt * 8 + 2 * lc;
            float b0 = 0.f, b1 = 0.f;
            if (bias) { b0 = __ldg(bias + col); b1 = __ldg(bias + col + 1); }
            float2 v0 = make_float2(acc[mt][nt][0] + b0, acc[mt][nt][1] + b1);
            float2 v1 = make_float2(acc[mt][nt][2] + b0, acc[mt][nt][3] + b1);
            *(float2*)(C + (size_t)row * N + col) = v0;
            *(float2*)(C + (size_t)(row + 8) * N + col) = v1;
        }
    }
}

// ---------------------------------------------------------------------------
// Lambda scalar
// ---------------------------------------------------------------------------
__global__ void lambda_kernel(const float* __restrict__ lq1, const float* __restrict__ lk1,
                              const float* __restrict__ lq2, const float* __restrict__ lk2)
{
    if (threadIdx.x == 0) {
        float s1 = 0.f, s2 = 0.f;
        for (int i = 0; i < HH; i++) {
            s1 = fmaf(lq1[i], lk1[i], s1);
            s2 = fmaf(lq2[i], lk2[i], s2);
        }
        double li = 0.8 - 0.6 * exp(-0.3 * 11.0);  // N_LAYER=12
        g_lambda = (float)(exp((double)s1) - exp((double)s2) + li);
    }
}

// ---------------------------------------------------------------------------
// Differential flash attention with mma.sync tf32 (unchanged from R5).
// ---------------------------------------------------------------------------
#define APAD 68
#define FLASH_SMEM ((6 * 64 * APAD + 256) * 4)

__device__ __forceinline__ void lda_frag(const float* S, int row0, int k0,
                                         int lr, int lc, uint32_t a[4]) {
    a[0] = f2tf32(S[(row0 + lr) * APAD + k0 + lc]);
    a[1] = f2tf32(S[(row0 + lr + 8) * APAD + k0 + lc]);
    a[2] = f2tf32(S[(row0 + lr) * APAD + k0 + 4 + lc]);
    a[3] = f2tf32(S[(row0 + lr + 8) * APAD + k0 + 4 + lc]);
}
__device__ __forceinline__ void ldb_frag(const float* S, int n0, int k0,
                                         int lr, int lc, uint32_t b[2]) {
    b[0] = f2tf32(S[(n0 + lr) * APAD + k0 + lc]);
    b[1] = f2tf32(S[(n0 + lr) * APAD + k0 + 4 + lc]);
}

__device__ __forceinline__ void process_branch(
    const float* __restrict__ Qs, const float* __restrict__ Ks,
    const float* __restrict__ Vt, float* __restrict__ Ps,
    float* __restrict__ redm, float* __restrict__ redl,
    float (&acc)[4][4], float& m0, float& m1, float& l0, float& l1,
    bool diag, int wm, int wn, int lr, int lc, int rl0)
{
    const float scale = 0.125f;  // 1/sqrt(64)
    float s[4][4];
#pragma unroll
    for (int nt = 0; nt < 4; nt++)
#pragma unroll
        for (int r = 0; r < 4; r++) s[nt][r] = 0.f;

#pragma unroll
    for (int k0 = 0; k0 < 64; k0 += 8) {
        uint32_t a[4];
        lda_frag(Qs, wm * 16, k0, lr, lc, a);
#pragma unroll
        for (int nt = 0; nt < 4; nt++) {
            uint32_t bq[2];
            ldb_frag(Ks, wn * 32 + nt * 8, k0, lr, lc, bq);
            mma_tf32(s[nt], a, bq);
        }
    }

    const int r0 = rl0, r1 = rl0 + 8;
#pragma unroll
    for (int nt = 0; nt < 4; nt++) {
        const int c0 = wn * 32 + nt * 8 + 2 * lc;
        s[nt][0] *= scale; s[nt][1] *= scale;
        s[nt][2] *= scale; s[nt][3] *= scale;
        if (diag) {
            if (c0 > r0)     s[nt][0] = -1e30f;
            if (c0 + 1 > r0) s[nt][1] = -1e30f;
            if (c0 > r1)     s[nt][2] = -1e30f;
            if (c0 + 1 > r1) s[nt][3] = -1e30f;
        }
    }

    float mx0 = -1e30f, mx1 = -1e30f;
#pragma unroll
    for (int nt = 0; nt < 4; nt++) {
        mx0 = fmaxf(mx0, fmaxf(s[nt][0], s[nt][1]));
        mx1 = fmaxf(mx1, fmaxf(s[nt][2], s[nt][3]));
    }
    mx0 = fmaxf(mx0, __shfl_xor_sync(0xffffffffu, mx0, 1));
    mx0 = fmaxf(mx0, __shfl_xor_sync(0xffffffffu, mx0, 2));
    mx1 = fmaxf(mx1, __shfl_xor_sync(0xffffffffu, mx1, 1));
    mx1 = fmaxf(mx1, __shfl_xor_sync(0xffffffffu, mx1, 2));
    if (lc == 0) {
        redm[wn * 64 + r0] = mx0;
        redm[wn * 64 + r1] = mx1;
    }
    __syncthreads();

    const float tm0 = fmaxf(redm[r0], redm[64 + r0]);
    const float tm1 = fmaxf(redm[r1], redm[64 + r1]);
    const float mn0 = fmaxf(m0, tm0);
    const float mn1 = fmaxf(m1, tm1);
    const float cr0 = __expf(m0 - mn0);
    const float cr1 = __expf(m1 - mn1);

    float ps0 = 0.f, ps1 = 0.f;
#pragma unroll
    for (int nt = 0; nt < 4; nt++) {
        const int cl = wn * 32 + nt * 8 + 2 * lc;
        float p0 = __expf(s[nt][0] - mn0);
        float p1 = __expf(s[nt][1] - mn0);
        float p2 = __expf(s[nt][2] - mn1);
        float p3 = __expf(s[nt][3] - mn1);
        ps0 += p0 + p1;
        ps1 += p2 + p3;
        *(float2*)&Ps[r0 * APAD + cl] = make_float2(p0, p1);
        *(float2*)&Ps[r1 * APAD + cl] = make_float2(p2, p3);
    }
    ps0 += __shfl_xor_sync(0xffffffffu, ps0, 1);
    ps0 += __shfl_xor_sync(0xffffffffu, ps0, 2);
    ps1 += __shfl_xor_sync(0xffffffffu, ps1, 1);
    ps1 += __shfl_xor_sync(0xffffffffu, ps1, 2);
    if (lc == 0) {
        redl[wn * 64 + r0] = ps0;
        redl[wn * 64 + r1] = ps1;
    }

#pragma unroll
    for (int nt = 0; nt < 4; nt++) {
        acc[nt][0] *= cr0; acc[nt][1] *= cr0;
        acc[nt][2] *= cr1; acc[nt][3] *= cr1;
    }
    m0 = mn0; m1 = mn1;
    __syncthreads();

    l0 = l0 * cr0 + redl[r0] + redl[64 + r0];
    l1 = l1 * cr1 + redl[r1] + redl[64 + r1];

#pragma unroll
    for (int k0 = 0; k0 < 64; k0 += 8) {
        uint32_t a[4];
        lda_frag(Ps, wm * 16, k0, lr, lc, a);
#pragma unroll
        for (int nt = 0; nt < 4; nt++) {
            uint32_t bv[2];
            ldb_frag(Vt, wn * 32 + nt * 8, k0, lr, lc, bv);
            mma_tf32(acc[nt], a, bv);
        }
    }
}

__global__ __launch_bounds__(256) void flash_diff_mma(
    const float* __restrict__ qb, const float* __restrict__ kb,
    const float* __restrict__ vb, float* __restrict__ yb)
{
    extern __shared__ float smf[];
    float* Q1 = smf;
    float* Q2 = Q1 + 64 * APAD;
    float* K1 = Q2 + 64 * APAD;
    float* K2 = K1 + 64 * APAD;
    float* Vt = K2 + 64 * APAD;
    float* Ps = Vt + 64 * APAD;
    float* redm = Ps + 64 * APAD;   // 128 floats
    float* redl = redm + 128;       // 128 floats

    const int tid = threadIdx.x;
    const int wid = tid >> 5, lane = tid & 31;
    const int wm = wid >> 1, wn = wid & 1;
    const int lr = lane >> 2, lc = lane & 3;
    const int qi = blockIdx.x, h = blockIdx.y, b = blockIdx.z;
    const int q0 = qi * 64;
    const int rl0 = wm * 16 + lr;

    const size_t qbase = ((size_t)(b * TT) + q0) * (2 * CC) + h * DHD;
#pragma unroll
    for (int j = 0; j < 4; j++) {
        int idx = tid + j * 256;
        int row = idx >> 4, c4 = (idx & 15) * 4;
        float4 v1 = *(const float4*)(qb + qbase + (size_t)row * (2 * CC) + c4);
        float4 v2 = *(const float4*)(qb + qbase + (size_t)row * (2 * CC) + CC + c4);
        *(float4*)&Q1[row * APAD + c4] = v1;
        *(float4*)&Q2[row * APAD + c4] = v2;
    }

    float acc1[4][4] = {}, acc2[4][4] = {};
    float m10 = -1e30f, m11 = -1e30f, l10 = 0.f, l11 = 0.f;
    float m20 = -1e30f, m21 = -1e30f, l20 = 0.f, l21 = 0.f;

    for (int kt = 0; kt <= qi; kt++) {
        const int k0t = kt * 64;
        __syncthreads();
        const size_t kbase = ((size_t)(b * TT) + k0t) * (2 * CC) + h * DHD;
        const size_t vbase = ((size_t)(b * TT) + k0t) * CC + h * DHD;
#pragma unroll
        for (int j = 0; j < 4; j++) {
            int idx = tid + j * 256;
            int row = idx >> 4, c4 = (idx & 15) * 4;
            float4 kv1 = *(const float4*)(kb + kbase + (size_t)row * (2 * CC) + c4);
            float4 kv2 = *(const float4*)(kb + kbase + (size_t)row * (2 * CC) + CC + c4);
            float4 vv  = *(const float4*)(vb + vbase + (size_t)row * CC + c4);
            *(float4*)&K1[row * APAD + c4] = kv1;
            *(float4*)&K2[row * APAD + c4] = kv2;
            Vt[(c4 + 0) * APAD + row] = vv.x;
            Vt[(c4 + 1) * APAD + row] = vv.y;
            Vt[(c4 + 2) * APAD + row] = vv.z;
            Vt[(c4 + 3) * APAD + row] = vv.w;
        }
        __syncthreads();
        const bool diag = (kt == qi);

        process_branch(Q1, K1, Vt, Ps, redm, redl, acc1, m10, m11, l10, l11,
                       diag, wm, wn, lr, lc, rl0);
        process_branch(Q2, K2, Vt, Ps, redm, redl, acc2, m20, m21, l20, l21,
                       diag, wm, wn, lr, lc, rl0);
    }

    const float lam = g_lambda;
    const float i10 = 1.f / l10, i11 = 1.f / l11;
    const float i20 = lam / l20, i21 = lam / l21;
    const int r0g = q0 + rl0, r1g = r0g + 8;
#pragma unroll
    for (int nt = 0; nt < 4; nt++) {
        const int col = h * DHD + wn * 32 + nt * 8 + 2 * lc;
        float2 o0 = make_float2(acc1[nt][0] * i10 - acc2[nt][0] * i20,
                                acc1[nt][1] * i10 - acc2[nt][1] * i20);
        float2 o1 = make_float2(acc1[nt][2] * i11 - acc2[nt][2] * i21,
                                acc1[nt][3] * i11 - acc2[nt][3] * i21);
        *(float2*)(yb + ((size_t)(b * TT) + r0g) * CC + col) = o0;
        *(float2*)(yb + ((size_t)(b * TT) + r1g) * CC + col) = o1;
    }
}

// ---------------------------------------------------------------------------
// Launch. Order: v(0), lambda(1), q(2), k(3), flash(4), wo(5), wc(6), we(7).
// ncu's fixed sample slot (launch index 3) lands on the big K-projection GEMM.
// ---------------------------------------------------------------------------
extern "C" void kernel_launch(void* const* d_in, const int* in_sizes, int n_in,
                              void* d_out, int out_size)
{
    const float* x   = (const float*)d_in[0];
    const float* wq  = (const float*)d_in[1];
    const float* wk  = (const float*)d_in[2];
    const float* wv  = (const float*)d_in[3];
    const float* wo  = (const float*)d_in[4];
    const float* lq1 = (const float*)d_in[5];
    const float* lk1 = (const float*)d_in[6];
    const float* lq2 = (const float*)d_in[7];
    const float* lk2 = (const float*)d_in[8];
    const float* wc  = (const float*)d_in[9];
    const float* bc  = (const float*)d_in[10];
    const float* we  = (const float*)d_in[11];
    const float* be  = (const float*)d_in[12];

    float *q, *k, *v, *y, *y2, *hb;
    cudaGetSymbolAddress((void**)&q,  g_q);
    cudaGetSymbolAddress((void**)&k,  g_k);
    cudaGetSymbolAddress((void**)&v,  g_v);
    cudaGetSymbolAddress((void**)&y,  g_y);
    cudaGetSymbolAddress((void**)&y2, g_y2);
    cudaGetSymbolAddress((void**)&hb, g_h);

    cudaFuncSetAttribute(mma_gemm_tn, cudaFuncAttributeMaxDynamicSharedMemorySize,
                         GEMM_SMEM);
    cudaFuncSetAttribute(flash_diff_mma, cudaFuncAttributeMaxDynamicSharedMemorySize,
                         FLASH_SMEM);

    dim3 blk(256);
    mma_gemm_tn<<<dim3(CC / 128, MT / 128), blk, GEMM_SMEM>>>(
        x, wv, nullptr, v, MT, CC, CC);
    lambda_kernel<<<1, 32>>>(lq1, lk1, lq2, lk2);
    mma_gemm_tn<<<dim3(2 * CC / 128, MT / 128), blk, GEMM_SMEM>>>(
        x, wq, nullptr, q, MT, 2 * CC, CC);
    mma_gemm_tn<<<dim3(2 * CC / 128, MT / 128), blk, GEMM_SMEM>>>(
        x, wk, nullptr, k, MT, 2 * CC, CC);
    flash_diff_mma<<<dim3(TT / 64, HH, BB), blk, FLASH_SMEM>>>(q, k, v, y);
    mma_gemm_tn<<<dim3(CC / 128, MT / 128), blk, GEMM_SMEM>>>(
        y, wo, nullptr, y2, MT, CC, CC);
    mma_gemm_tn<<<dim3(CC / 2 / 128, MT / 128), blk, GEMM_SMEM>>>(
        y2, wc, bc, hb, MT, CC / 2, CC);
    mma_gemm_tn<<<dim3(CC / 128, MT / 128), blk, GEMM_SMEM>>>(
        hb, we, be, (float*)d_out, MT, CC, CC / 2);
}

// round 7
// speedup vs baseline: 1.9436x; 1.0798x over previous
#include <cuda_runtime.h>
#include <math.h>
#include <stdint.h>

// Problem constants
#define BB 2
#define TT 2048
#define CC 1024
#define HH 16
#define DHD 64
#define MT (BB * TT)          // 4096 rows

// ---------------------------------------------------------------------------
// Scratch (device globals)
// ---------------------------------------------------------------------------
__device__ float g_q[MT * 2 * CC];
__device__ float g_k[MT * 2 * CC];
__device__ float g_v[MT * CC];
__device__ float g_y[MT * CC];
__device__ float g_y2[MT * CC];
__device__ float g_h[MT * (CC / 2)];
__device__ float g_lambda;

// ---------------------------------------------------------------------------
// PTX helpers (compute_100-legal)
// ---------------------------------------------------------------------------
__device__ __forceinline__ uint32_t smem_u32(const void* p) {
    uint32_t a;
    asm("{ .reg .u64 t; cvta.to.shared.u64 t, %1; cvt.u32.u64 %0, t; }"
        : "=r"(a) : "l"(p));
    return a;
}

__device__ __forceinline__ void cp_async16(uint32_t dst, const void* src) {
    asm volatile("cp.async.ca.shared.global [%0], [%1], 16;"
                 :: "r"(dst), "l"(src) : "memory");
}
#define CP_ASYNC_COMMIT() asm volatile("cp.async.commit_group;" ::: "memory")
#define CP_ASYNC_WAIT(n)  asm volatile("cp.async.wait_group %0;" :: "n"(n) : "memory")

__device__ __forceinline__ uint32_t f2tf32(float f) {
    uint32_t r;
    asm("cvt.rna.tf32.f32 %0, %1;" : "=r"(r) : "f"(f));
    return r;
}

// tf32 m16n8k8 (used by attention)
__device__ __forceinline__ void mma_tf32(float* d, const uint32_t* a, const uint32_t* b) {
    asm volatile(
        "mma.sync.aligned.m16n8k8.row.col.f32.tf32.tf32.f32 "
        "{%0,%1,%2,%3}, {%4,%5,%6,%7}, {%8,%9}, {%0,%1,%2,%3};"
        : "+f"(d[0]), "+f"(d[1]), "+f"(d[2]), "+f"(d[3])
        : "r"(a[0]), "r"(a[1]), "r"(a[2]), "r"(a[3]), "r"(b[0]), "r"(b[1]));
}

// bf16 m16n8k16 (used by GEMMs)
__device__ __forceinline__ void mma_bf16(float* d, const uint32_t* a, const uint32_t* b) {
    asm volatile(
        "mma.sync.aligned.m16n8k16.row.col.f32.bf16.bf16.f32 "
        "{%0,%1,%2,%3}, {%4,%5,%6,%7}, {%8,%9}, {%0,%1,%2,%3};"
        : "+f"(d[0]), "+f"(d[1]), "+f"(d[2]), "+f"(d[3])
        : "r"(a[0]), "r"(a[1]), "r"(a[2]), "r"(a[3]), "r"(b[0]), "r"(b[1]));
}

// pack two fp32 -> bf16x2 reg: elem0 in low half, elem1 in high half
__device__ __forceinline__ uint32_t pack_bf16x2(float e0, float e1) {
    uint32_t r;
    asm("cvt.rn.bf16x2.f32 %0, %1, %2;" : "=r"(r) : "f"(e1), "f"(e0));
    return r;
}

// split pair (x0, x1) into packed bf16 hi + bf16 lo (precision-doubling)
__device__ __forceinline__ void split2(float x0, float x1, uint32_t& h, uint32_t& l) {
    h = pack_bf16x2(x0, x1);
    float h0 = __uint_as_float(h << 16);
    float h1 = __uint_as_float(h & 0xffff0000u);
    l = pack_bf16x2(x0 - h0, x1 - h1);
}

// ---------------------------------------------------------------------------
// bf16x3 mma.sync TN GEMM: C[M,N] = A[M,K] @ B[N,K]^T (+ bias[N])
// 128x128 CTA tile, BK=32, 8 warps (2x4), cp.async 2-stage fp32 smem.
// __launch_bounds__(256, 2): cap 128 regs -> 2 CTAs/SM.
// ---------------------------------------------------------------------------
#define GBM 128
#define GBN 128
#define GBK 32
#define GPAD 40
#define G_TILE_F (GBM * GPAD)             // 5120 floats
#define G_BUF_F  (2 * G_TILE_F)           // A + B per stage
#define GEMM_SMEM (2 * G_BUF_F * 4)       // 81920 B (double buffered)

__device__ __forceinline__ void g_stage(
    uint32_t sbuf, const float* __restrict__ Ag, const float* __restrict__ Bg,
    int K, int tid)
{
#pragma unroll
    for (int j = 0; j < 4; j++) {
        int linear = tid + j * 256;
        int m = linear & 127;
        int kg = linear >> 7;              // 0..7
        uint32_t off = (uint32_t)(m * GPAD + kg * 4) * 4u;
        cp_async16(sbuf + off, Ag + (size_t)m * K + kg * 4);
        cp_async16(sbuf + (uint32_t)G_TILE_F * 4u + off, Bg + (size_t)m * K + kg * 4);
    }
}

__global__ void __launch_bounds__(256, 2) mma_gemm_tn(
    const float* __restrict__ A, const float* __restrict__ B,
    const float* __restrict__ bias, float* __restrict__ C,
    int M, int N, int K)
{
    extern __shared__ float smg[];
    const uint32_t sb = smem_u32(smg);
    const int tid = threadIdx.x;
    const int wid = tid >> 5, lane = tid & 31;
    const int wm = wid >> 2, wn = wid & 3;   // 2 x 4 warp grid
    const int lr = lane >> 2;                // 0..7
    const int lc = lane & 3;                 // 0..3
    const int m0 = blockIdx.y * GBM;
    const int n0 = blockIdx.x * GBN;

    const float* Ag = A + (size_t)m0 * K;
    const float* Bg = B + (size_t)n0 * K;

    float acc[4][4][4];
#pragma unroll
    for (int mt = 0; mt < 4; mt++)
#pragma unroll
        for (int nt = 0; nt < 4; nt++)
#pragma unroll
            for (int r = 0; r < 4; r++) acc[mt][nt][r] = 0.f;

    const int nch = K / GBK;

    g_stage(sb, Ag, Bg, K, tid);
    CP_ASYNC_COMMIT();

    for (int i = 0; i < nch; i++) {
        if (i + 1 < nch) {
            g_stage(sb + (uint32_t)(((i + 1) & 1) * G_BUF_F) * 4u,
                    Ag + (i + 1) * GBK, Bg + (i + 1) * GBK, K, tid);
            CP_ASYNC_COMMIT();
            CP_ASYNC_WAIT(1);
        } else {
            CP_ASYNC_WAIT(0);
        }
        __syncthreads();

        const float* Asf = smg + (i & 1) * G_BUF_F;
        const float* Bsf = Asf + G_TILE_F;

#pragma unroll
        for (int ks = 0; ks < 2; ks++) {
            const int k0 = ks * 16;
            uint32_t bh[4][2], bl[4][2];
#pragma unroll
            for (int nt = 0; nt < 4; nt++) {
                const int bn = wn * 32 + nt * 8 + lr;
                float2 p0 = *(const float2*)&Bsf[bn * GPAD + k0 + 2 * lc];
                float2 p1 = *(const float2*)&Bsf[bn * GPAD + k0 + 8 + 2 * lc];
                split2(p0.x, p0.y, bh[nt][0], bl[nt][0]);
                split2(p1.x, p1.y, bh[nt][1], bl[nt][1]);
            }
#pragma unroll
            for (int mt = 0; mt < 4; mt++) {
                const int am = wm * 64 + mt * 16 + lr;
                float2 a0 = *(const float2*)&Asf[am * GPAD + k0 + 2 * lc];
                float2 a1 = *(const float2*)&Asf[(am + 8) * GPAD + k0 + 2 * lc];
                float2 a2 = *(const float2*)&Asf[am * GPAD + k0 + 8 + 2 * lc];
                float2 a3 = *(const float2*)&Asf[(am + 8) * GPAD + k0 + 8 + 2 * lc];
                uint32_t ah[4], al[4];
                split2(a0.x, a0.y, ah[0], al[0]);
                split2(a1.x, a1.y, ah[1], al[1]);
                split2(a2.x, a2.y, ah[2], al[2]);
                split2(a3.x, a3.y, ah[3], al[3]);
#pragma unroll
                for (int nt = 0; nt < 4; nt++) {
                    mma_bf16(acc[mt][nt], al, bh[nt]);   // lo*hi
                    mma_bf16(acc[mt][nt], ah, bl[nt]);   // hi*lo
                    mma_bf16(acc[mt][nt], ah, bh[nt]);   // hi*hi last (largest)
                }
            }
        }
        __syncthreads();
    }

    // epilogue
#pragma unroll
    for (int mt = 0; mt < 4; mt++) {
        const int row = m0 + wm * 64 + mt * 16 + lr;
#pragma unroll
        for (int nt = 0; nt < 4; nt++) {
            const int col = n0 + wn * 32 + nt * 8 + 2 * lc;
            float b0 = 0.f, b1 = 0.f;
            if (bias) { b0 = __ldg(bias + col); b1 = __ldg(bias + col + 1); }
            float2 v0 = make_float2(acc[mt][nt][0] + b0, acc[mt][nt][1] + b1);
            float2 v1 = make_float2(acc[mt][nt][2] + b0, acc[mt][nt][3] + b1);
            *(float2*)(C + (size_t)row * N + col) = v0;
            *(float2*)(C + (size_t)(row + 8) * N + col) = v1;
        }
    }
}

// ---------------------------------------------------------------------------
// Lambda scalar
// ---------------------------------------------------------------------------
__global__ void lambda_kernel(const float* __restrict__ lq1, const float* __restrict__ lk1,
                              const float* __restrict__ lq2, const float* __restrict__ lk2)
{
    if (threadIdx.x == 0) {
        float s1 = 0.f, s2 = 0.f;
        for (int i = 0; i < HH; i++) {
            s1 = fmaf(lq1[i], lk1[i], s1);
            s2 = fmaf(lq2[i], lk2[i], s2);
        }
        double li = 0.8 - 0.6 * exp(-0.3 * 11.0);  // N_LAYER=12
        g_lambda = (float)(exp((double)s1) - exp((double)s2) + li);
    }
}

// ---------------------------------------------------------------------------
// Differential flash attention with mma.sync tf32.
// V now kept ROW-MAJOR (VPAD=72 -> conflict-free B-fragment reads); the
// transposed-store staging of R5/R6 is gone.
// ---------------------------------------------------------------------------
#define APAD 68
#define VPAD 72
#define FLASH_SMEM ((5 * 64 * APAD + 64 * VPAD + 256) * 4)

__device__ __forceinline__ void lda_frag(const float* S, int row0, int k0,
                                         int lr, int lc, uint32_t a[4]) {
    a[0] = f2tf32(S[(row0 + lr) * APAD + k0 + lc]);
    a[1] = f2tf32(S[(row0 + lr + 8) * APAD + k0 + lc]);
    a[2] = f2tf32(S[(row0 + lr) * APAD + k0 + 4 + lc]);
    a[3] = f2tf32(S[(row0 + lr + 8) * APAD + k0 + 4 + lc]);
}
__device__ __forceinline__ void ldb_frag(const float* S, int n0, int k0,
                                         int lr, int lc, uint32_t b[2]) {
    b[0] = f2tf32(S[(n0 + lr) * APAD + k0 + lc]);
    b[1] = f2tf32(S[(n0 + lr) * APAD + k0 + 4 + lc]);
}
// B-fragment for P@V from row-major V[key][d]: B(n=d, k=key) = V[k][n]
__device__ __forceinline__ void ldbV_frag(const float* Vs, int n0, int k0,
                                          int lr, int lc, uint32_t b[2]) {
    b[0] = f2tf32(Vs[(k0 + lc) * VPAD + n0 + lr]);
    b[1] = f2tf32(Vs[(k0 + 4 + lc) * VPAD + n0 + lr]);
}

__device__ __forceinline__ void process_branch(
    const float* __restrict__ Qs, const float* __restrict__ Ks,
    const float* __restrict__ Vs, float* __restrict__ Ps,
    float* __restrict__ redm, float* __restrict__ redl,
    float (&acc)[4][4], float& m0, float& m1, float& l0, float& l1,
    bool diag, int wm, int wn, int lr, int lc, int rl0)
{
    const float scale = 0.125f;  // 1/sqrt(64)
    float s[4][4];
#pragma unroll
    for (int nt = 0; nt < 4; nt++)
#pragma unroll
        for (int r = 0; r < 4; r++) s[nt][r] = 0.f;

#pragma unroll
    for (int k0 = 0; k0 < 64; k0 += 8) {
        uint32_t a[4];
        lda_frag(Qs, wm * 16, k0, lr, lc, a);
#pragma unroll
        for (int nt = 0; nt < 4; nt++) {
            uint32_t bq[2];
            ldb_frag(Ks, wn * 32 + nt * 8, k0, lr, lc, bq);
            mma_tf32(s[nt], a, bq);
        }
    }

    const int r0 = rl0, r1 = rl0 + 8;
#pragma unroll
    for (int nt = 0; nt < 4; nt++) {
        const int c0 = wn * 32 + nt * 8 + 2 * lc;
        s[nt][0] *= scale; s[nt][1] *= scale;
        s[nt][2] *= scale; s[nt][3] *= scale;
        if (diag) {
            if (c0 > r0)     s[nt][0] = -1e30f;
            if (c0 + 1 > r0) s[nt][1] = -1e30f;
            if (c0 > r1)     s[nt][2] = -1e30f;
            if (c0 + 1 > r1) s[nt][3] = -1e30f;
        }
    }

    float mx0 = -1e30f, mx1 = -1e30f;
#pragma unroll
    for (int nt = 0; nt < 4; nt++) {
        mx0 = fmaxf(mx0, fmaxf(s[nt][0], s[nt][1]));
        mx1 = fmaxf(mx1, fmaxf(s[nt][2], s[nt][3]));
    }
    mx0 = fmaxf(mx0, __shfl_xor_sync(0xffffffffu, mx0, 1));
    mx0 = fmaxf(mx0, __shfl_xor_sync(0xffffffffu, mx0, 2));
    mx1 = fmaxf(mx1, __shfl_xor_sync(0xffffffffu, mx1, 1));
    mx1 = fmaxf(mx1, __shfl_xor_sync(0xffffffffu, mx1, 2));
    if (lc == 0) {
        redm[wn * 64 + r0] = mx0;
        redm[wn * 64 + r1] = mx1;
    }
    __syncthreads();

    const float tm0 = fmaxf(redm[r0], redm[64 + r0]);
    const float tm1 = fmaxf(redm[r1], redm[64 + r1]);
    const float mn0 = fmaxf(m0, tm0);
    const float mn1 = fmaxf(m1, tm1);
    const float cr0 = __expf(m0 - mn0);
    const float cr1 = __expf(m1 - mn1);

    float ps0 = 0.f, ps1 = 0.f;
#pragma unroll
    for (int nt = 0; nt < 4; nt++) {
        const int cl = wn * 32 + nt * 8 + 2 * lc;
        float p0 = __expf(s[nt][0] - mn0);
        float p1 = __expf(s[nt][1] - mn0);
        float p2 = __expf(s[nt][2] - mn1);
        float p3 = __expf(s[nt][3] - mn1);
        ps0 += p0 + p1;
        ps1 += p2 + p3;
        *(float2*)&Ps[r0 * APAD + cl] = make_float2(p0, p1);
        *(float2*)&Ps[r1 * APAD + cl] = make_float2(p2, p3);
    }
    ps0 += __shfl_xor_sync(0xffffffffu, ps0, 1);
    ps0 += __shfl_xor_sync(0xffffffffu, ps0, 2);
    ps1 += __shfl_xor_sync(0xffffffffu, ps1, 1);
    ps1 += __shfl_xor_sync(0xffffffffu, ps1, 2);
    if (lc == 0) {
        redl[wn * 64 + r0] = ps0;
        redl[wn * 64 + r1] = ps1;
    }

#pragma unroll
    for (int nt = 0; nt < 4; nt++) {
        acc[nt][0] *= cr0; acc[nt][1] *= cr0;
        acc[nt][2] *= cr1; acc[nt][3] *= cr1;
    }
    m0 = mn0; m1 = mn1;
    __syncthreads();

    l0 = l0 * cr0 + redl[r0] + redl[64 + r0];
    l1 = l1 * cr1 + redl[r1] + redl[64 + r1];

#pragma unroll
    for (int k0 = 0; k0 < 64; k0 += 8) {
        uint32_t a[4];
        lda_frag(Ps, wm * 16, k0, lr, lc, a);
#pragma unroll
        for (int nt = 0; nt < 4; nt++) {
            uint32_t bv[2];
            ldbV_frag(Vs, wn * 32 + nt * 8, k0, lr, lc, bv);
            mma_tf32(acc[nt], a, bv);
        }
    }
}

__global__ __launch_bounds__(256) void flash_diff_mma(
    const float* __restrict__ qb, const float* __restrict__ kb,
    const float* __restrict__ vb, float* __restrict__ yb)
{
    extern __shared__ float smf[];
    float* Q1 = smf;
    float* Q2 = Q1 + 64 * APAD;
    float* K1 = Q2 + 64 * APAD;
    float* K2 = K1 + 64 * APAD;
    float* Ps = K2 + 64 * APAD;
    float* Vs = Ps + 64 * APAD;     // row-major, VPAD stride
    float* redm = Vs + 64 * VPAD;   // 128 floats
    float* redl = redm + 128;       // 128 floats

    const int tid = threadIdx.x;
    const int wid = tid >> 5, lane = tid & 31;
    const int wm = wid >> 1, wn = wid & 1;
    const int lr = lane >> 2, lc = lane & 3;
    const int qi = blockIdx.x, h = blockIdx.y, b = blockIdx.z;
    const int q0 = qi * 64;
    const int rl0 = wm * 16 + lr;

    const size_t qbase = ((size_t)(b * TT) + q0) * (2 * CC) + h * DHD;
#pragma unroll
    for (int j = 0; j < 4; j++) {
        int idx = tid + j * 256;
        int row = idx >> 4, c4 = (idx & 15) * 4;
        float4 v1 = *(const float4*)(qb + qbase + (size_t)row * (2 * CC) + c4);
        float4 v2 = *(const float4*)(qb + qbase + (size_t)row * (2 * CC) + CC + c4);
        *(float4*)&Q1[row * APAD + c4] = v1;
        *(float4*)&Q2[row * APAD + c4] = v2;
    }

    float acc1[4][4] = {}, acc2[4][4] = {};
    float m10 = -1e30f, m11 = -1e30f, l10 = 0.f, l11 = 0.f;
    float m20 = -1e30f, m21 = -1e30f, l20 = 0.f, l21 = 0.f;

    for (int kt = 0; kt <= qi; kt++) {
        const int k0t = kt * 64;
        __syncthreads();
        const size_t kbase = ((size_t)(b * TT) + k0t) * (2 * CC) + h * DHD;
        const size_t vbase = ((size_t)(b * TT) + k0t) * CC + h * DHD;
#pragma unroll
        for (int j = 0; j < 4; j++) {
            int idx = tid + j * 256;
            int row = idx >> 4, c4 = (idx & 15) * 4;
            float4 kv1 = *(const float4*)(kb + kbase + (size_t)row * (2 * CC) + c4);
            float4 kv2 = *(const float4*)(kb + kbase + (size_t)row * (2 * CC) + CC + c4);
            float4 vv  = *(const float4*)(vb + vbase + (size_t)row * CC + c4);
            *(float4*)&K1[row * APAD + c4] = kv1;
            *(float4*)&K2[row * APAD + c4] = kv2;
            *(float4*)&Vs[row * VPAD + c4] = vv;
        }
        __syncthreads();
        const bool diag = (kt == qi);

        process_branch(Q1, K1, Vs, Ps, redm, redl, acc1, m10, m11, l10, l11,
                       diag, wm, wn, lr, lc, rl0);
        process_branch(Q2, K2, Vs, Ps, redm, redl, acc2, m20, m21, l20, l21,
                       diag, wm, wn, lr, lc, rl0);
    }

    const float lam = g_lambda;
    const float i10 = 1.f / l10, i11 = 1.f / l11;
    const float i20 = lam / l20, i21 = lam / l21;
    const int r0g = q0 + rl0, r1g = r0g + 8;
#pragma unroll
    for (int nt = 0; nt < 4; nt++) {
        const int col = h * DHD + wn * 32 + nt * 8 + 2 * lc;
        float2 o0 = make_float2(acc1[nt][0] * i10 - acc2[nt][0] * i20,
                                acc1[nt][1] * i10 - acc2[nt][1] * i20);
        float2 o1 = make_float2(acc1[nt][2] * i11 - acc2[nt][2] * i21,
                                acc1[nt][3] * i11 - acc2[nt][3] * i21);
        *(float2*)(yb + ((size_t)(b * TT) + r0g) * CC + col) = o0;
        *(float2*)(yb + ((size_t)(b * TT) + r1g) * CC + col) = o1;
    }
}

// ---------------------------------------------------------------------------
// Launch. Order: v(0), lambda(1), q(2), k(3), flash(4), wo(5), wc(6), we(7).
// ncu's fixed sample slot (launch index 3) lands on the big K-projection GEMM.
// ---------------------------------------------------------------------------
extern "C" void kernel_launch(void* const* d_in, const int* in_sizes, int n_in,
                              void* d_out, int out_size)
{
    const float* x   = (const float*)d_in[0];
    const float* wq  = (const float*)d_in[1];
    const float* wk  = (const float*)d_in[2];
    const float* wv  = (const float*)d_in[3];
    const float* wo  = (const float*)d_in[4];
    const float* lq1 = (const float*)d_in[5];
    const float* lk1 = (const float*)d_in[6];
    const float* lq2 = (const float*)d_in[7];
    const float* lk2 = (const float*)d_in[8];
    const float* wc  = (const float*)d_in[9];
    const float* bc  = (const float*)d_in[10];
    const float* we  = (const float*)d_in[11];
    const float* be  = (const float*)d_in[12];

    float *q, *k, *v, *y, *y2, *hb;
    cudaGetSymbolAddress((void**)&q,  g_q);
    cudaGetSymbolAddress((void**)&k,  g_k);
    cudaGetSymbolAddress((void**)&v,  g_v);
    cudaGetSymbolAddress((void**)&y,  g_y);
    cudaGetSymbolAddress((void**)&y2, g_y2);
    cudaGetSymbolAddress((void**)&hb, g_h);

    cudaFuncSetAttribute(mma_gemm_tn, cudaFuncAttributeMaxDynamicSharedMemorySize,
                         GEMM_SMEM);
    cudaFuncSetAttribute(flash_diff_mma, cudaFuncAttributeMaxDynamicSharedMemorySize,
                         FLASH_SMEM);

    dim3 blk(256);
    mma_gemm_tn<<<dim3(CC / 128, MT / 128), blk, GEMM_SMEM>>>(
        x, wv, nullptr, v, MT, CC, CC);
    lambda_kernel<<<1, 32>>>(lq1, lk1, lq2, lk2);
    mma_gemm_tn<<<dim3(2 * CC / 128, MT / 128), blk, GEMM_SMEM>>>(
        x, wq, nullptr, q, MT, 2 * CC, CC);
    mma_gemm_tn<<<dim3(2 * CC / 128, MT / 128), blk, GEMM_SMEM>>>(
        x, wk, nullptr, k, MT, 2 * CC, CC);
    flash_diff_mma<<<dim3(TT / 64, HH, BB), blk, FLASH_SMEM>>>(q, k, v, y);
    mma_gemm_tn<<<dim3(CC / 128, MT / 128), blk, GEMM_SMEM>>>(
        y, wo, nullptr, y2, MT, CC, CC);
    mma_gemm_tn<<<dim3(CC / 2 / 128, MT / 128), blk, GEMM_SMEM>>>(
        y2, wc, bc, hb, MT, CC / 2, CC);
    mma_gemm_tn<<<dim3(CC / 128, MT / 128), blk, GEMM_SMEM>>>(
        hb, we, be, (float*)d_out, MT, CC, CC / 2);
}

// round 8
// speedup vs baseline: 2.7282x; 1.4037x over previous
#include <cuda_runtime.h>
#include <math.h>
#include <stdint.h>

// Problem constants
#define BB 2
#define TT 2048
#define CC 1024
#define HH 16
#define DHD 64
#define MT (BB * TT)          // 4096 rows

// ---------------------------------------------------------------------------
// Scratch (device globals)
// ---------------------------------------------------------------------------
__device__ float g_q[MT * 2 * CC];
__device__ float g_k[MT * 2 * CC];
__device__ float g_v[MT * CC];
__device__ float g_y[MT * CC];
__device__ float g_y2[MT * CC];
__device__ float g_h[MT * (CC / 2)];
__device__ float g_lambda;

// hi/lo bf16 copies of GEMM operands (hi at [0], lo at [half])
__device__ unsigned short g_xc [2ul * MT * CC];
__device__ unsigned short g_wqc[2ul * 2 * CC * CC];
__device__ unsigned short g_wkc[2ul * 2 * CC * CC];
__device__ unsigned short g_wvc[2ul * CC * CC];
__device__ unsigned short g_woc[2ul * CC * CC];
__device__ unsigned short g_wcc[2ul * (CC / 2) * CC];
__device__ unsigned short g_wec[2ul * CC * (CC / 2)];
__device__ unsigned short g_yc [2ul * MT * CC];
__device__ unsigned short g_y2c[2ul * MT * CC];
__device__ unsigned short g_hc [2ul * MT * (CC / 2)];

// ---------------------------------------------------------------------------
// PTX helpers (compute_100-legal)
// ---------------------------------------------------------------------------
__device__ __forceinline__ uint32_t smem_u32(const void* p) {
    uint32_t a;
    asm("{ .reg .u64 t; cvta.to.shared.u64 t, %1; cvt.u32.u64 %0, t; }"
        : "=r"(a) : "l"(p));
    return a;
}

__device__ __forceinline__ void cp_async16(uint32_t dst, const void* src) {
    asm volatile("cp.async.ca.shared.global [%0], [%1], 16;"
                 :: "r"(dst), "l"(src) : "memory");
}
#define CP_ASYNC_COMMIT() asm volatile("cp.async.commit_group;" ::: "memory")
#define CP_ASYNC_WAIT(n)  asm volatile("cp.async.wait_group %0;" :: "n"(n) : "memory")

__device__ __forceinline__ uint32_t f2tf32(float f) {
    uint32_t r;
    asm("cvt.rna.tf32.f32 %0, %1;" : "=r"(r) : "f"(f));
    return r;
}

// tf32 m16n8k8 (attention)
__device__ __forceinline__ void mma_tf32(float* d, const uint32_t* a, const uint32_t* b) {
    asm volatile(
        "mma.sync.aligned.m16n8k8.row.col.f32.tf32.tf32.f32 "
        "{%0,%1,%2,%3}, {%4,%5,%6,%7}, {%8,%9}, {%0,%1,%2,%3};"
        : "+f"(d[0]), "+f"(d[1]), "+f"(d[2]), "+f"(d[3])
        : "r"(a[0]), "r"(a[1]), "r"(a[2]), "r"(a[3]), "r"(b[0]), "r"(b[1]));
}

// bf16 m16n8k16 (GEMMs)
__device__ __forceinline__ void mma_bf16(float* d, const uint32_t* a, const uint32_t* b) {
    asm volatile(
        "mma.sync.aligned.m16n8k16.row.col.f32.bf16.bf16.f32 "
        "{%0,%1,%2,%3}, {%4,%5,%6,%7}, {%8,%9}, {%0,%1,%2,%3};"
        : "+f"(d[0]), "+f"(d[1]), "+f"(d[2]), "+f"(d[3])
        : "r"(a[0]), "r"(a[1]), "r"(a[2]), "r"(a[3]), "r"(b[0]), "r"(b[1]));
}

__device__ __forceinline__ void ldm_x4(uint32_t* r, uint32_t addr) {
    asm volatile("ldmatrix.sync.aligned.m8n8.x4.shared.b16 {%0,%1,%2,%3}, [%4];"
        : "=r"(r[0]), "=r"(r[1]), "=r"(r[2]), "=r"(r[3]) : "r"(addr));
}
__device__ __forceinline__ void ldm_x2(uint32_t* r, uint32_t addr) {
    asm volatile("ldmatrix.sync.aligned.m8n8.x2.shared.b16 {%0,%1}, [%2];"
        : "=r"(r[0]), "=r"(r[1]) : "r"(addr));
}

// pack two fp32 -> bf16x2 reg: elem0 low half, elem1 high half
__device__ __forceinline__ uint32_t pack_bf16x2(float e0, float e1) {
    uint32_t r;
    asm("cvt.rn.bf16x2.f32 %0, %1, %2;" : "=r"(r) : "f"(e1), "f"(e0));
    return r;
}

// ---------------------------------------------------------------------------
// fp32 -> (hi, lo) bf16 conversion kernel (grid-stride over float4)
// ---------------------------------------------------------------------------
__global__ __launch_bounds__(256) void convert_hilo(
    const float4* __restrict__ src, uint2* __restrict__ hi,
    uint2* __restrict__ lo, int n4)
{
    for (int i = blockIdx.x * blockDim.x + threadIdx.x; i < n4;
         i += gridDim.x * blockDim.x) {
        float4 v = src[i];
        uint32_t h0 = pack_bf16x2(v.x, v.y);
        uint32_t h1 = pack_bf16x2(v.z, v.w);
        uint32_t l0 = pack_bf16x2(v.x - __uint_as_float(h0 << 16),
                                  v.y - __uint_as_float(h0 & 0xffff0000u));
        uint32_t l1 = pack_bf16x2(v.z - __uint_as_float(h1 << 16),
                                  v.w - __uint_as_float(h1 & 0xffff0000u));
        hi[i] = make_uint2(h0, h1);
        lo[i] = make_uint2(l0, l1);
    }
}

// ---------------------------------------------------------------------------
// bf16x3 GEMM with pre-split hi/lo operands + ldmatrix fragments.
// C[M,N] = A[M,K] @ B[N,K]^T (+bias), A/B given as hi/lo bf16 tensors.
// 128x128 CTA tile, BK=32, 8 warps (2x4), cp.async 2-stage.
// smem rows padded to 80B (80 mod 128 -> ldmatrix conflict-free).
// ---------------------------------------------------------------------------
#define GBM 128
#define GBN 128
#define GBK 32
#define SPITCH 80                       // bytes per smem row (40 bf16)
#define TILE_B (128 * SPITCH)           // 10240 B per tile
#define STAGE_B (4 * TILE_B)            // Ah, Al, Bh, Bl
#define GEMM_SMEM (2 * STAGE_B)         // 81920 B

__device__ __forceinline__ void g_stage(
    uint32_t sbuf,
    const unsigned short* __restrict__ Ah, const unsigned short* __restrict__ Al,
    const unsigned short* __restrict__ Bh, const unsigned short* __restrict__ Bl,
    int K, int kc, int tid)
{
    const unsigned short* srcs[4] = {Ah, Al, Bh, Bl};
#pragma unroll
    for (int j = 0; j < 8; j++) {
        const int tile = j >> 1;                    // compile-time per j
        const int idx = (j & 1) * 256 + tid;        // 0..511 within tile
        const int m = idx >> 2, seg = idx & 3;
        uint32_t dst = sbuf + tile * TILE_B + m * SPITCH + seg * 16;
        cp_async16(dst, srcs[tile] + (size_t)m * K + kc * GBK + seg * 8);
    }
}

__global__ void __launch_bounds__(256, 2) mma_gemm_tn(
    const unsigned short* __restrict__ Ah, const unsigned short* __restrict__ Al,
    const unsigned short* __restrict__ Bh, const unsigned short* __restrict__ Bl,
    const float* __restrict__ bias, float* __restrict__ C,
    int M, int N, int K)
{
    extern __shared__ float smg[];
    const uint32_t sb = smem_u32(smg);
    const int tid = threadIdx.x;
    const int wid = tid >> 5, lane = tid & 31;
    const int wm = wid >> 2, wn = wid & 3;   // 2 x 4 warp grid
    const int lr = lane >> 2;                // 0..7
    const int lc = lane & 3;                 // 0..3
    const int m0 = blockIdx.y * GBM;
    const int n0 = blockIdx.x * GBN;

    // tile-local source bases
    const unsigned short* Ah0 = Ah + (size_t)m0 * K;
    const unsigned short* Al0 = Al + (size_t)m0 * K;
    const unsigned short* Bh0 = Bh + (size_t)n0 * K;
    const unsigned short* Bl0 = Bl + (size_t)n0 * K;

    // per-thread ldmatrix address offsets (canonical m16n8k16 mapping)
    // A (.x4): threads 0-7 m0(r0-7,k0-7), 8-15 m1(r8-15,k0-7),
    //          16-23 m2(r0-7,k8-15), 24-31 m3(r8-15,k8-15)
    const uint32_t a_off =
        (uint32_t)(wm * 64 + (lane & 7) + ((lane >> 3) & 1) * 8) * SPITCH +
        ((lane >> 4) & 1) * 16;
    // B (.x2): threads 0-7 m0(n0-7,k0-7), 8-15 m1(n0-7,k8-15)
    const uint32_t b_off =
        (uint32_t)(wn * 32 + (lane & 7)) * SPITCH + ((lane >> 3) & 1) * 16;

    float acc[4][4][4];
#pragma unroll
    for (int mt = 0; mt < 4; mt++)
#pragma unroll
        for (int nt = 0; nt < 4; nt++)
#pragma unroll
            for (int r = 0; r < 4; r++) acc[mt][nt][r] = 0.f;

    const int nch = K / GBK;

    g_stage(sb, Ah0, Al0, Bh0, Bl0, K, 0, tid);
    CP_ASYNC_COMMIT();

    for (int i = 0; i < nch; i++) {
        if (i + 1 < nch) {
            g_stage(sb + ((i + 1) & 1) * STAGE_B, Ah0, Al0, Bh0, Bl0, K, i + 1, tid);
            CP_ASYNC_COMMIT();
            CP_ASYNC_WAIT(1);
        } else {
            CP_ASYNC_WAIT(0);
        }
        __syncthreads();

        const uint32_t st = sb + (i & 1) * STAGE_B;

#pragma unroll
        for (int ks = 0; ks < 2; ks++) {
            const uint32_t kbyte = ks * 32;  // 16 bf16 per k-step
            uint32_t bh[4][2], bl[4][2];
#pragma unroll
            for (int nt = 0; nt < 4; nt++) {
                uint32_t ad = st + 2 * TILE_B + b_off + nt * 8 * SPITCH + kbyte;
                ldm_x2(bh[nt], ad);
                ldm_x2(bl[nt], ad + TILE_B);
            }
#pragma unroll
            for (int mt = 0; mt < 4; mt++) {
                uint32_t ad = st + a_off + mt * 16 * SPITCH + kbyte;
                uint32_t ah[4], al[4];
                ldm_x4(ah, ad);
                ldm_x4(al, ad + TILE_B);
#pragma unroll
                for (int nt = 0; nt < 4; nt++) {
                    mma_bf16(acc[mt][nt], al, bh[nt]);   // lo*hi
                    mma_bf16(acc[mt][nt], ah, bl[nt]);   // hi*lo
                    mma_bf16(acc[mt][nt], ah, bh[nt]);   // hi*hi last
                }
            }
        }
        __syncthreads();
    }

    // epilogue
#pragma unroll
    for (int mt = 0; mt < 4; mt++) {
        const int row = m0 + wm * 64 + mt * 16 + lr;
#pragma unroll
        for (int nt = 0; nt < 4; nt++) {
            const int col = n0 + wn * 32 + nt * 8 + 2 * lc;
            float b0 = 0.f, b1 = 0.f;
            if (bias) { b0 = __ldg(bias + col); b1 = __ldg(bias + col + 1); }
            float2 v0 = make_float2(acc[mt][nt][0] + b0, acc[mt][nt][1] + b1);
            float2 v1 = make_float2(acc[mt][nt][2] + b0, acc[mt][nt][3] + b1);
            *(float2*)(C + (size_t)row * N + col) = v0;
            *(float2*)(C + (size_t)(row + 8) * N + col) = v1;
        }
    }
}

// ---------------------------------------------------------------------------
// Lambda scalar
// ---------------------------------------------------------------------------
__global__ void lambda_kernel(const float* __restrict__ lq1, const float* __restrict__ lk1,
                              const float* __restrict__ lq2, const float* __restrict__ lk2)
{
    if (threadIdx.x == 0) {
        float s1 = 0.f, s2 = 0.f;
        for (int i = 0; i < HH; i++) {
            s1 = fmaf(lq1[i], lk1[i], s1);
            s2 = fmaf(lq2[i], lk2[i], s2);
        }
        double li = 0.8 - 0.6 * exp(-0.3 * 11.0);  // N_LAYER=12
        g_lambda = (float)(exp((double)s1) - exp((double)s2) + li);
    }
}

// ---------------------------------------------------------------------------
// Differential flash attention with mma.sync tf32 (unchanged from R7).
// ---------------------------------------------------------------------------
#define APAD 68
#define VPAD 72
#define FLASH_SMEM ((5 * 64 * APAD + 64 * VPAD + 256) * 4)

__device__ __forceinline__ void lda_frag(const float* S, int row0, int k0,
                                         int lr, int lc, uint32_t a[4]) {
    a[0] = f2tf32(S[(row0 + lr) * APAD + k0 + lc]);
    a[1] = f2tf32(S[(row0 + lr + 8) * APAD + k0 + lc]);
    a[2] = f2tf32(S[(row0 + lr) * APAD + k0 + 4 + lc]);
    a[3] = f2tf32(S[(row0 + lr + 8) * APAD + k0 + 4 + lc]);
}
__device__ __forceinline__ void ldb_frag(const float* S, int n0, int k0,
                                         int lr, int lc, uint32_t b[2]) {
    b[0] = f2tf32(S[(n0 + lr) * APAD + k0 + lc]);
    b[1] = f2tf32(S[(n0 + lr) * APAD + k0 + 4 + lc]);
}
__device__ __forceinline__ void ldbV_frag(const float* Vs, int n0, int k0,
                                          int lr, int lc, uint32_t b[2]) {
    b[0] = f2tf32(Vs[(k0 + lc) * VPAD + n0 + lr]);
    b[1] = f2tf32(Vs[(k0 + 4 + lc) * VPAD + n0 + lr]);
}

__device__ __forceinline__ void process_branch(
    const float* __restrict__ Qs, const float* __restrict__ Ks,
    const float* __restrict__ Vs, float* __restrict__ Ps,
    float* __restrict__ redm, float* __restrict__ redl,
    float (&acc)[4][4], float& m0, float& m1, float& l0, float& l1,
    bool diag, int wm, int wn, int lr, int lc, int rl0)
{
    const float scale = 0.125f;  // 1/sqrt(64)
    float s[4][4];
#pragma unroll
    for (int nt = 0; nt < 4; nt++)
#pragma unroll
        for (int r = 0; r < 4; r++) s[nt][r] = 0.f;

#pragma unroll
    for (int k0 = 0; k0 < 64; k0 += 8) {
        uint32_t a[4];
        lda_frag(Qs, wm * 16, k0, lr, lc, a);
#pragma unroll
        for (int nt = 0; nt < 4; nt++) {
            uint32_t bq[2];
            ldb_frag(Ks, wn * 32 + nt * 8, k0, lr, lc, bq);
            mma_tf32(s[nt], a, bq);
        }
    }

    const int r0 = rl0, r1 = rl0 + 8;
#pragma unroll
    for (int nt = 0; nt < 4; nt++) {
        const int c0 = wn * 32 + nt * 8 + 2 * lc;
        s[nt][0] *= scale; s[nt][1] *= scale;
        s[nt][2] *= scale; s[nt][3] *= scale;
        if (diag) {
            if (c0 > r0)     s[nt][0] = -1e30f;
            if (c0 + 1 > r0) s[nt][1] = -1e30f;
            if (c0 > r1)     s[nt][2] = -1e30f;
            if (c0 + 1 > r1) s[nt][3] = -1e30f;
        }
    }

    float mx0 = -1e30f, mx1 = -1e30f;
#pragma unroll
    for (int nt = 0; nt < 4; nt++) {
        mx0 = fmaxf(mx0, fmaxf(s[nt][0], s[nt][1]));
        mx1 = fmaxf(mx1, fmaxf(s[nt][2], s[nt][3]));
    }
    mx0 = fmaxf(mx0, __shfl_xor_sync(0xffffffffu, mx0, 1));
    mx0 = fmaxf(mx0, __shfl_xor_sync(0xffffffffu, mx0, 2));
    mx1 = fmaxf(mx1, __shfl_xor_sync(0xffffffffu, mx1, 1));
    mx1 = fmaxf(mx1, __shfl_xor_sync(0xffffffffu, mx1, 2));
    if (lc == 0) {
        redm[wn * 64 + r0] = mx0;
        redm[wn * 64 + r1] = mx1;
    }
    __syncthreads();

    const float tm0 = fmaxf(redm[r0], redm[64 + r0]);
    const float tm1 = fmaxf(redm[r1], redm[64 + r1]);
    const float mn0 = fmaxf(m0, tm0);
    const float mn1 = fmaxf(m1, tm1);
    const float cr0 = __expf(m0 - mn0);
    const float cr1 = __expf(m1 - mn1);

    float ps0 = 0.f, ps1 = 0.f;
#pragma unroll
    for (int nt = 0; nt < 4; nt++) {
        const int cl = wn * 32 + nt * 8 + 2 * lc;
        float p0 = __expf(s[nt][0] - mn0);
        float p1 = __expf(s[nt][1] - mn0);
        float p2 = __expf(s[nt][2] - mn1);
        float p3 = __expf(s[nt][3] - mn1);
        ps0 += p0 + p1;
        ps1 += p2 + p3;
        *(float2*)&Ps[r0 * APAD + cl] = make_float2(p0, p1);
        *(float2*)&Ps[r1 * APAD + cl] = make_float2(p2, p3);
    }
    ps0 += __shfl_xor_sync(0xffffffffu, ps0, 1);
    ps0 += __shfl_xor_sync(0xffffffffu, ps0, 2);
    ps1 += __shfl_xor_sync(0xffffffffu, ps1, 1);
    ps1 += __shfl_xor_sync(0xffffffffu, ps1, 2);
    if (lc == 0) {
        redl[wn * 64 + r0] = ps0;
        redl[wn * 64 + r1] = ps1;
    }

#pragma unroll
    for (int nt = 0; nt < 4; nt++) {
        acc[nt][0] *= cr0; acc[nt][1] *= cr0;
        acc[nt][2] *= cr1; acc[nt][3] *= cr1;
    }
    m0 = mn0; m1 = mn1;
    __syncthreads();

    l0 = l0 * cr0 + redl[r0] + redl[64 + r0];
    l1 = l1 * cr1 + redl[r1] + redl[64 + r1];

#pragma unroll
    for (int k0 = 0; k0 < 64; k0 += 8) {
        uint32_t a[4];
        lda_frag(Ps, wm * 16, k0, lr, lc, a);
#pragma unroll
        for (int nt = 0; nt < 4; nt++) {
            uint32_t bv[2];
            ldbV_frag(Vs, wn * 32 + nt * 8, k0, lr, lc, bv);
            mma_tf32(acc[nt], a, bv);
        }
    }
}

__global__ __launch_bounds__(256) void flash_diff_mma(
    const float* __restrict__ qb, const float* __restrict__ kb,
    const float* __restrict__ vb, float* __restrict__ yb)
{
    extern __shared__ float smf[];
    float* Q1 = smf;
    float* Q2 = Q1 + 64 * APAD;
    float* K1 = Q2 + 64 * APAD;
    float* K2 = K1 + 64 * APAD;
    float* Ps = K2 + 64 * APAD;
    float* Vs = Ps + 64 * APAD;     // row-major, VPAD stride
    float* redm = Vs + 64 * VPAD;   // 128 floats
    float* redl = redm + 128;       // 128 floats

    const int tid = threadIdx.x;
    const int wid = tid >> 5, lane = tid & 31;
    const int wm = wid >> 1, wn = wid & 1;
    const int lr = lane >> 2, lc = lane & 3;
    const int qi = blockIdx.x, h = blockIdx.y, b = blockIdx.z;
    const int q0 = qi * 64;
    const int rl0 = wm * 16 + lr;

    const size_t qbase = ((size_t)(b * TT) + q0) * (2 * CC) + h * DHD;
#pragma unroll
    for (int j = 0; j < 4; j++) {
        int idx = tid + j * 256;
        int row = idx >> 4, c4 = (idx & 15) * 4;
        float4 v1 = *(const float4*)(qb + qbase + (size_t)row * (2 * CC) + c4);
        float4 v2 = *(const float4*)(qb + qbase + (size_t)row * (2 * CC) + CC + c4);
        *(float4*)&Q1[row * APAD + c4] = v1;
        *(float4*)&Q2[row * APAD + c4] = v2;
    }

    float acc1[4][4] = {}, acc2[4][4] = {};
    float m10 = -1e30f, m11 = -1e30f, l10 = 0.f, l11 = 0.f;
    float m20 = -1e30f, m21 = -1e30f, l20 = 0.f, l21 = 0.f;

    for (int kt = 0; kt <= qi; kt++) {
        const int k0t = kt * 64;
        __syncthreads();
        const size_t kbase = ((size_t)(b * TT) + k0t) * (2 * CC) + h * DHD;
        const size_t vbase = ((size_t)(b * TT) + k0t) * CC + h * DHD;
#pragma unroll
        for (int j = 0; j < 4; j++) {
            int idx = tid + j * 256;
            int row = idx >> 4, c4 = (idx & 15) * 4;
            float4 kv1 = *(const float4*)(kb + kbase + (size_t)row * (2 * CC) + c4);
            float4 kv2 = *(const float4*)(kb + kbase + (size_t)row * (2 * CC) + CC + c4);
            float4 vv  = *(const float4*)(vb + vbase + (size_t)row * CC + c4);
            *(float4*)&K1[row * APAD + c4] = kv1;
            *(float4*)&K2[row * APAD + c4] = kv2;
            *(float4*)&Vs[row * VPAD + c4] = vv;
        }
        __syncthreads();
        const bool diag = (kt == qi);

        process_branch(Q1, K1, Vs, Ps, redm, redl, acc1, m10, m11, l10, l11,
                       diag, wm, wn, lr, lc, rl0);
        process_branch(Q2, K2, Vs, Ps, redm, redl, acc2, m20, m21, l20, l21,
                       diag, wm, wn, lr, lc, rl0);
    }

    const float lam = g_lambda;
    const float i10 = 1.f / l10, i11 = 1.f / l11;
    const float i20 = lam / l20, i21 = lam / l21;
    const int r0g = q0 + rl0, r1g = r0g + 8;
#pragma unroll
    for (int nt = 0; nt < 4; nt++) {
        const int col = h * DHD + wn * 32 + nt * 8 + 2 * lc;
        float2 o0 = make_float2(acc1[nt][0] * i10 - acc2[nt][0] * i20,
                                acc1[nt][1] * i10 - acc2[nt][1] * i20);
        float2 o1 = make_float2(acc1[nt][2] * i11 - acc2[nt][2] * i21,
                                acc1[nt][3] * i11 - acc2[nt][3] * i21);
        *(float2*)(yb + ((size_t)(b * TT) + r0g) * CC + col) = o0;
        *(float2*)(yb + ((size_t)(b * TT) + r1g) * CC + col) = o1;
    }
}

// ---------------------------------------------------------------------------
// Launch. ncu fixed slot (launch index 3) = Q-projection GEMM.
// ---------------------------------------------------------------------------
static inline void conv(const float* src, unsigned short* dst, size_t n) {
    int n4 = (int)(n / 4);
    int blocks = (n4 + 255) / 256;
    if (blocks > 4096) blocks = 4096;
    convert_hilo<<<blocks, 256>>>((const float4*)src, (uint2*)dst,
                                  (uint2*)(dst + n), n4);
}

extern "C" void kernel_launch(void* const* d_in, const int* in_sizes, int n_in,
                              void* d_out, int out_size)
{
    const float* x   = (const float*)d_in[0];
    const float* wq  = (const float*)d_in[1];
    const float* wk  = (const float*)d_in[2];
    const float* wv  = (const float*)d_in[3];
    const float* wo  = (const float*)d_in[4];
    const float* lq1 = (const float*)d_in[5];
    const float* lk1 = (const float*)d_in[6];
    const float* lq2 = (const float*)d_in[7];
    const float* lk2 = (const float*)d_in[8];
    const float* wc  = (const float*)d_in[9];
    const float* bc  = (const float*)d_in[10];
    const float* we  = (const float*)d_in[11];
    const float* be  = (const float*)d_in[12];

    float *q, *k, *v, *y, *y2, *hb;
    cudaGetSymbolAddress((void**)&q,  g_q);
    cudaGetSymbolAddress((void**)&k,  g_k);
    cudaGetSymbolAddress((void**)&v,  g_v);
    cudaGetSymbolAddress((void**)&y,  g_y);
    cudaGetSymbolAddress((void**)&y2, g_y2);
    cudaGetSymbolAddress((void**)&hb, g_h);

    unsigned short *xc, *wqc, *wkc, *wvc, *woc, *wcc, *wec, *yc, *y2c, *hc;
    cudaGetSymbolAddress((void**)&xc,  g_xc);
    cudaGetSymbolAddress((void**)&wqc, g_wqc);
    cudaGetSymbolAddress((void**)&wkc, g_wkc);
    cudaGetSymbolAddress((void**)&wvc, g_wvc);
    cudaGetSymbolAddress((void**)&woc, g_woc);
    cudaGetSymbolAddress((void**)&wcc, g_wcc);
    cudaGetSymbolAddress((void**)&wec, g_wec);
    cudaGetSymbolAddress((void**)&yc,  g_yc);
    cudaGetSymbolAddress((void**)&y2c, g_y2c);
    cudaGetSymbolAddress((void**)&hc,  g_hc);

    cudaFuncSetAttribute(mma_gemm_tn, cudaFuncAttributeMaxDynamicSharedMemorySize,
                         GEMM_SMEM);
    cudaFuncSetAttribute(flash_diff_mma, cudaFuncAttributeMaxDynamicSharedMemorySize,
                         FLASH_SMEM);

    const size_t NX = (size_t)MT * CC;          // 4M
    const size_t NQK = (size_t)2 * CC * CC;     // 2M
    const size_t NSQ = (size_t)CC * CC;         // 1M
    const size_t NHC = (size_t)(CC / 2) * CC;   // 0.5M

    dim3 blk(256);
    conv(x, xc, NX);                                                        // 0
    conv(wq, wqc, NQK);                                                     // 1
    conv(wk, wkc, NQK);                                                     // 2
    mma_gemm_tn<<<dim3(2 * CC / 128, MT / 128), blk, GEMM_SMEM>>>(          // 3 (ncu)
        xc, xc + NX, wqc, wqc + NQK, nullptr, q, MT, 2 * CC, CC);
    mma_gemm_tn<<<dim3(2 * CC / 128, MT / 128), blk, GEMM_SMEM>>>(          // 4
        xc, xc + NX, wkc, wkc + NQK, nullptr, k, MT, 2 * CC, CC);
    conv(wv, wvc, NSQ);                                                     // 5
    mma_gemm_tn<<<dim3(CC / 128, MT / 128), blk, GEMM_SMEM>>>(              // 6
        xc, xc + NX, wvc, wvc + NSQ, nullptr, v, MT, CC, CC);
    lambda_kernel<<<1, 32>>>(lq1, lk1, lq2, lk2);                           // 7
    flash_diff_mma<<<dim3(TT / 64, HH, BB), blk, FLASH_SMEM>>>(q, k, v, y); // 8
    conv(y, yc, NX);                                                        // 9
    conv(wo, woc, NSQ);                                                     // 10
    mma_gemm_tn<<<dim3(CC / 128, MT / 128), blk, GEMM_SMEM>>>(              // 11
        yc, yc + NX, woc, woc + NSQ, nullptr, y2, MT, CC, CC);
    conv(y2, y2c, NX);                                                      // 12
    conv(wc, wcc, NHC);                                                     // 13
    mma_gemm_tn<<<dim3(CC / 2 / 128, MT / 128), blk, GEMM_SMEM>>>(          // 14
        y2c, y2c + NX, wcc, wcc + NHC, bc, hb, MT, CC / 2, CC);
    conv(hb, hc, (size_t)MT * (CC / 2));                                    // 15
    conv(we, wec, NHC);                                                     // 16
    mma_gemm_tn<<<dim3(CC / 128, MT / 128), blk, GEMM_SMEM>>>(              // 17
        hc, hc + (size_t)MT * (CC / 2), wec, wec + NHC, be, (float*)d_out,
        MT, CC, CC / 2);
}

// round 11
// speedup vs baseline: 2.7350x; 1.0025x over previous
#include <cuda_runtime.h>
#include <math.h>
#include <stdint.h>

// Problem constants
#define BB 2
#define TT 2048
#define CC 1024
#define HH 16
#define DHD 64
#define MT (BB * TT)          // 4096 rows

// ---------------------------------------------------------------------------
// Scratch (device globals)
// ---------------------------------------------------------------------------
__device__ float g_lambda;
__device__ float g_v[MT * CC];          // fp32 V (flash consumes fp32)
__device__ float g_y[MT * CC];          // fp32 attention output

// hi/lo bf16 pairs (hi at [0], lo at [elem_count])
__device__ unsigned short g_xc [2ul * MT * CC];
__device__ unsigned short g_wqc[2ul * 2 * CC * CC];
__device__ unsigned short g_wkc[2ul * 2 * CC * CC];
__device__ unsigned short g_wvc[2ul * CC * CC];
__device__ unsigned short g_woc[2ul * CC * CC];
__device__ unsigned short g_wcc[2ul * (CC / 2) * CC];
__device__ unsigned short g_wec[2ul * CC * (CC / 2)];
__device__ unsigned short g_qc [2ul * MT * 2 * CC];
__device__ unsigned short g_kc [2ul * MT * 2 * CC];
__device__ unsigned short g_yc [2ul * MT * CC];
__device__ unsigned short g_y2c[2ul * MT * CC];
__device__ unsigned short g_hc [2ul * MT * (CC / 2)];

// ---------------------------------------------------------------------------
// PTX helpers (compute_100-legal)
// ---------------------------------------------------------------------------
__device__ __forceinline__ uint32_t smem_u32(const void* p) {
    uint32_t a;
    asm("{ .reg .u64 t; cvta.to.shared.u64 t, %1; cvt.u32.u64 %0, t; }"
        : "=r"(a) : "l"(p));
    return a;
}

__device__ __forceinline__ void cp_async16(uint32_t dst, const void* src) {
    asm volatile("cp.async.ca.shared.global [%0], [%1], 16;"
                 :: "r"(dst), "l"(src) : "memory");
}
#define CP_ASYNC_COMMIT() asm volatile("cp.async.commit_group;" ::: "memory")
#define CP_ASYNC_WAIT(n)  asm volatile("cp.async.wait_group %0;" :: "n"(n) : "memory")

__device__ __forceinline__ uint32_t f2tf32(float f) {
    uint32_t r;
    asm("cvt.rna.tf32.f32 %0, %1;" : "=r"(r) : "f"(f));
    return r;
}

// tf32 m16n8k8 (P@V in attention — R7-proven path)
__device__ __forceinline__ void mma_tf32(float* d, const uint32_t* a, const uint32_t* b) {
    asm volatile(
        "mma.sync.aligned.m16n8k8.row.col.f32.tf32.tf32.f32 "
        "{%0,%1,%2,%3}, {%4,%5,%6,%7}, {%8,%9}, {%0,%1,%2,%3};"
        : "+f"(d[0]), "+f"(d[1]), "+f"(d[2]), "+f"(d[3])
        : "r"(a[0]), "r"(a[1]), "r"(a[2]), "r"(a[3]), "r"(b[0]), "r"(b[1]));
}

// bf16 m16n8k16 (GEMMs + S=QK^T)
__device__ __forceinline__ void mma_bf16(float* d, const uint32_t* a, const uint32_t* b) {
    asm volatile(
        "mma.sync.aligned.m16n8k16.row.col.f32.bf16.bf16.f32 "
        "{%0,%1,%2,%3}, {%4,%5,%6,%7}, {%8,%9}, {%0,%1,%2,%3};"
        : "+f"(d[0]), "+f"(d[1]), "+f"(d[2]), "+f"(d[3])
        : "r"(a[0]), "r"(a[1]), "r"(a[2]), "r"(a[3]), "r"(b[0]), "r"(b[1]));
}

__device__ __forceinline__ void ldm_x4(uint32_t* r, uint32_t addr) {
    asm volatile("ldmatrix.sync.aligned.m8n8.x4.shared.b16 {%0,%1,%2,%3}, [%4];"
        : "=r"(r[0]), "=r"(r[1]), "=r"(r[2]), "=r"(r[3]) : "r"(addr));
}
__device__ __forceinline__ void ldm_x2(uint32_t* r, uint32_t addr) {
    asm volatile("ldmatrix.sync.aligned.m8n8.x2.shared.b16 {%0,%1}, [%2];"
        : "=r"(r[0]), "=r"(r[1]) : "r"(addr));
}

__device__ __forceinline__ uint32_t pack_bf16x2(float e0, float e1) {
    uint32_t r;
    asm("cvt.rn.bf16x2.f32 %0, %1, %2;" : "=r"(r) : "f"(e1), "f"(e0));
    return r;
}
__device__ __forceinline__ uint32_t lo_of(uint32_t h, float x0, float x1) {
    return pack_bf16x2(x0 - __uint_as_float(h << 16),
                       x1 - __uint_as_float(h & 0xffff0000u));
}

// ---------------------------------------------------------------------------
// fp32 -> (hi, lo) bf16 conversion kernel
// ---------------------------------------------------------------------------
__global__ __launch_bounds__(256) void convert_hilo(
    const float4* __restrict__ src, uint2* __restrict__ hi,
    uint2* __restrict__ lo, int n4)
{
    for (int i = blockIdx.x * blockDim.x + threadIdx.x; i < n4;
         i += gridDim.x * blockDim.x) {
        float4 v = src[i];
        uint32_t h0 = pack_bf16x2(v.x, v.y);
        uint32_t h1 = pack_bf16x2(v.z, v.w);
        hi[i] = make_uint2(h0, h1);
        lo[i] = make_uint2(lo_of(h0, v.x, v.y), lo_of(h1, v.z, v.w));
    }
}

// ---------------------------------------------------------------------------
// bf16x3 GEMM (R8-proven core; dual-mode epilogue).
// ---------------------------------------------------------------------------
#define GBM 128
#define GBN 128
#define GBK 32
#define SPITCH 80
#define TILE_B (128 * SPITCH)
#define STAGE_B (4 * TILE_B)
#define GEMM_SMEM (2 * STAGE_B)         // 81920 B

__device__ __forceinline__ void g_stage(
    uint32_t sbuf,
    const unsigned short* __restrict__ Ah, const unsigned short* __restrict__ Al,
    const unsigned short* __restrict__ Bh, const unsigned short* __restrict__ Bl,
    int K, int kc, int tid)
{
    const unsigned short* srcs[4] = {Ah, Al, Bh, Bl};
#pragma unroll
    for (int j = 0; j < 8; j++) {
        const int tile = j >> 1;
        const int idx = (j & 1) * 256 + tid;
        const int m = idx >> 2, seg = idx & 3;
        uint32_t dst = sbuf + tile * TILE_B + m * SPITCH + seg * 16;
        cp_async16(dst, srcs[tile] + (size_t)m * K + kc * GBK + seg * 8);
    }
}

__global__ void __launch_bounds__(256, 2) mma_gemm_tn(
    const unsigned short* __restrict__ Ah, const unsigned short* __restrict__ Al,
    const unsigned short* __restrict__ Bh, const unsigned short* __restrict__ Bl,
    const float* __restrict__ bias, float* __restrict__ Cf,
    unsigned short* __restrict__ Chi, unsigned short* __restrict__ Clo,
    int M, int N, int K)
{
    extern __shared__ float smg[];
    const uint32_t sb = smem_u32(smg);
    const int tid = threadIdx.x;
    const int wid = tid >> 5, lane = tid & 31;
    const int wm = wid >> 2, wn = wid & 3;
    const int lr = lane >> 2;
    const int lc = lane & 3;
    const int m0 = blockIdx.y * GBM;
    const int n0 = blockIdx.x * GBN;

    const unsigned short* Ah0 = Ah + (size_t)m0 * K;
    const unsigned short* Al0 = Al + (size_t)m0 * K;
    const unsigned short* Bh0 = Bh + (size_t)n0 * K;
    const unsigned short* Bl0 = Bl + (size_t)n0 * K;

    const uint32_t a_off =
        (uint32_t)(wm * 64 + (lane & 7) + ((lane >> 3) & 1) * 8) * SPITCH +
        ((lane >> 4) & 1) * 16;
    const uint32_t b_off =
        (uint32_t)(wn * 32 + (lane & 7)) * SPITCH + ((lane >> 3) & 1) * 16;

    float acc[4][4][4];
#pragma unroll
    for (int mt = 0; mt < 4; mt++)
#pragma unroll
        for (int nt = 0; nt < 4; nt++)
#pragma unroll
            for (int r = 0; r < 4; r++) acc[mt][nt][r] = 0.f;

    const int nch = K / GBK;

    g_stage(sb, Ah0, Al0, Bh0, Bl0, K, 0, tid);
    CP_ASYNC_COMMIT();

    for (int i = 0; i < nch; i++) {
        if (i + 1 < nch) {
            g_stage(sb + ((i + 1) & 1) * STAGE_B, Ah0, Al0, Bh0, Bl0, K, i + 1, tid);
            CP_ASYNC_COMMIT();
            CP_ASYNC_WAIT(1);
        } else {
            CP_ASYNC_WAIT(0);
        }
        __syncthreads();

        const uint32_t st = sb + (i & 1) * STAGE_B;

#pragma unroll
        for (int ks = 0; ks < 2; ks++) {
            const uint32_t kbyte = ks * 32;
            uint32_t bh[4][2], bl[4][2];
#pragma unroll
            for (int nt = 0; nt < 4; nt++) {
                uint32_t ad = st + 2 * TILE_B + b_off + nt * 8 * SPITCH + kbyte;
                ldm_x2(bh[nt], ad);
                ldm_x2(bl[nt], ad + TILE_B);
            }
#pragma unroll
            for (int mt = 0; mt < 4; mt++) {
                uint32_t ad = st + a_off + mt * 16 * SPITCH + kbyte;
                uint32_t ah[4], al[4];
                ldm_x4(ah, ad);
                ldm_x4(al, ad + TILE_B);
#pragma unroll
                for (int nt = 0; nt < 4; nt++) {
                    mma_bf16(acc[mt][nt], al, bh[nt]);
                    mma_bf16(acc[mt][nt], ah, bl[nt]);
                    mma_bf16(acc[mt][nt], ah, bh[nt]);
                }
            }
        }
        __syncthreads();
    }

#pragma unroll
    for (int mt = 0; mt < 4; mt++) {
        const int row = m0 + wm * 64 + mt * 16 + lr;
#pragma unroll
        for (int nt = 0; nt < 4; nt++) {
            const int col = n0 + wn * 32 + nt * 8 + 2 * lc;
            float b0 = 0.f, b1 = 0.f;
            if (bias) { b0 = __ldg(bias + col); b1 = __ldg(bias + col + 1); }
            float v0x = acc[mt][nt][0] + b0, v0y = acc[mt][nt][1] + b1;
            float v1x = acc[mt][nt][2] + b0, v1y = acc[mt][nt][3] + b1;
            if (Cf) {
                *(float2*)(Cf + (size_t)row * N + col) = make_float2(v0x, v0y);
                *(float2*)(Cf + (size_t)(row + 8) * N + col) = make_float2(v1x, v1y);
            } else {
                uint32_t h0 = pack_bf16x2(v0x, v0y);
                uint32_t h1 = pack_bf16x2(v1x, v1y);
                *(uint32_t*)&Chi[(size_t)row * N + col] = h0;
                *(uint32_t*)&Clo[(size_t)row * N + col] = lo_of(h0, v0x, v0y);
                *(uint32_t*)&Chi[(size_t)(row + 8) * N + col] = h1;
                *(uint32_t*)&Clo[(size_t)(row + 8) * N + col] = lo_of(h1, v1x, v1y);
            }
        }
    }
}

// ---------------------------------------------------------------------------
// Lambda scalar
// ---------------------------------------------------------------------------
__global__ void lambda_kernel(const float* __restrict__ lq1, const float* __restrict__ lk1,
                              const float* __restrict__ lq2, const float* __restrict__ lk2)
{
    if (threadIdx.x == 0) {
        float s1 = 0.f, s2 = 0.f;
        for (int i = 0; i < HH; i++) {
            s1 = fmaf(lq1[i], lk1[i], s1);
            s2 = fmaf(lq2[i], lk2[i], s2);
        }
        double li = 0.8 - 0.6 * exp(-0.3 * 11.0);  // N_LAYER=12
        g_lambda = (float)(exp((double)s1) - exp((double)s2) + li);
    }
}

// ---------------------------------------------------------------------------
// Hybrid differential flash attention:
//   S = QK^T : bf16x3 via ldmatrix (R8-proven fragment pattern), q/k pre-split.
//   softmax + P@V : R7-proven fp32/tf32 path.
// R11 FIX: staging addresses now include the b*TT batch offset (the R9/R10
// bug: batch-1 CTAs read batch-0 q/k/v).
// ---------------------------------------------------------------------------
#define FBP 144                          // bytes per bf16 tile row (72 bf16)
#define FTILE (64 * FBP)                 // 9216 B
#define APAD 68                          // Ps fp32 pitch (floats)
#define VPAD 72                          // Vs fp32 pitch (floats)
#define OFF_V   (8 * FTILE)                      // 73728
#define OFF_PS  (OFF_V + 64 * VPAD * 4)          // 92160
#define OFF_RED (OFF_PS + 64 * APAD * 4)         // 109568
#define FLASH_SMEM (OFF_RED + 1024)              // 110592

__device__ __forceinline__ void lda_frag(const float* S, int row0, int k0,
                                         int lr, int lc, uint32_t a[4]) {
    a[0] = f2tf32(S[(row0 + lr) * APAD + k0 + lc]);
    a[1] = f2tf32(S[(row0 + lr + 8) * APAD + k0 + lc]);
    a[2] = f2tf32(S[(row0 + lr) * APAD + k0 + 4 + lc]);
    a[3] = f2tf32(S[(row0 + lr + 8) * APAD + k0 + 4 + lc]);
}
__device__ __forceinline__ void ldbV_frag(const float* Vs, int n0, int k0,
                                          int lr, int lc, uint32_t b[2]) {
    b[0] = f2tf32(Vs[(k0 + lc) * VPAD + n0 + lr]);
    b[1] = f2tf32(Vs[(k0 + 4 + lc) * VPAD + n0 + lr]);
}

__device__ __forceinline__ void branch_hyb(
    uint32_t sb, float* __restrict__ Vs, float* __restrict__ Ps,
    float* __restrict__ redm, float* __restrict__ redl, int br,
    float (&acc)[4][4], float& m0, float& m1, float& l0, float& l1,
    bool diag, int wm, int wn, int lr, int lc, int lane, int rl0)
{
    const uint32_t qh = sb + (br * 2 + 0) * FTILE;
    const uint32_t ql = sb + (br * 2 + 1) * FTILE;
    const uint32_t kh = sb + (4 + br * 2) * FTILE;
    const uint32_t kl = sb + (5 + br * 2) * FTILE;
    const uint32_t arow =
        (uint32_t)(wm * 16 + (lane & 7) + ((lane >> 3) & 1) * 8) * FBP +
        ((lane >> 4) & 1) * 16;
    const uint32_t boff =
        (uint32_t)(wn * 32 + (lane & 7)) * FBP + ((lane >> 3) & 1) * 16;

    const float scale = 0.125f;  // 1/sqrt(64)
    float s[4][4];
#pragma unroll
    for (int nt = 0; nt < 4; nt++)
#pragma unroll
        for (int r = 0; r < 4; r++) s[nt][r] = 0.f;

    // S = Q @ K^T (bf16x3)
#pragma unroll
    for (int ks = 0; ks < 4; ks++) {
        uint32_t ah[4], al[4];
        ldm_x4(ah, qh + arow + ks * 32);
        ldm_x4(al, ql + arow + ks * 32);
#pragma unroll
        for (int nt = 0; nt < 4; nt++) {
            uint32_t bh[2], bl[2];
            uint32_t ad = boff + nt * 8 * FBP + ks * 32;
            ldm_x2(bh, kh + ad);
            ldm_x2(bl, kl + ad);
            mma_bf16(s[nt], al, bh);
            mma_bf16(s[nt], ah, bl);
            mma_bf16(s[nt], ah, bh);
        }
    }

    const int r0 = rl0, r1 = rl0 + 8;
#pragma unroll
    for (int nt = 0; nt < 4; nt++) {
        const int c0 = wn * 32 + nt * 8 + 2 * lc;
        s[nt][0] *= scale; s[nt][1] *= scale;
        s[nt][2] *= scale; s[nt][3] *= scale;
        if (diag) {
            if (c0 > r0)     s[nt][0] = -1e30f;
            if (c0 + 1 > r0) s[nt][1] = -1e30f;
            if (c0 > r1)     s[nt][2] = -1e30f;
            if (c0 + 1 > r1) s[nt][3] = -1e30f;
        }
    }

    float mx0 = -1e30f, mx1 = -1e30f;
#pragma unroll
    for (int nt = 0; nt < 4; nt++) {
        mx0 = fmaxf(mx0, fmaxf(s[nt][0], s[nt][1]));
        mx1 = fmaxf(mx1, fmaxf(s[nt][2], s[nt][3]));
    }
    mx0 = fmaxf(mx0, __shfl_xor_sync(0xffffffffu, mx0, 1));
    mx0 = fmaxf(mx0, __shfl_xor_sync(0xffffffffu, mx0, 2));
    mx1 = fmaxf(mx1, __shfl_xor_sync(0xffffffffu, mx1, 1));
    mx1 = fmaxf(mx1, __shfl_xor_sync(0xffffffffu, mx1, 2));
    if (lc == 0) {
        redm[wn * 64 + r0] = mx0;
        redm[wn * 64 + r1] = mx1;
    }
    __syncthreads();

    const float tm0 = fmaxf(redm[r0], redm[64 + r0]);
    const float tm1 = fmaxf(redm[r1], redm[64 + r1]);
    const float mn0 = fmaxf(m0, tm0);
    const float mn1 = fmaxf(m1, tm1);
    const float cr0 = __expf(m0 - mn0);
    const float cr1 = __expf(m1 - mn1);

    float ps0 = 0.f, ps1 = 0.f;
#pragma unroll
    for (int nt = 0; nt < 4; nt++) {
        const int cl = wn * 32 + nt * 8 + 2 * lc;
        float p0 = __expf(s[nt][0] - mn0);
        float p1 = __expf(s[nt][1] - mn0);
        float p2 = __expf(s[nt][2] - mn1);
        float p3 = __expf(s[nt][3] - mn1);
        ps0 += p0 + p1;
        ps1 += p2 + p3;
        *(float2*)&Ps[r0 * APAD + cl] = make_float2(p0, p1);
        *(float2*)&Ps[r1 * APAD + cl] = make_float2(p2, p3);
    }
    ps0 += __shfl_xor_sync(0xffffffffu, ps0, 1);
    ps0 += __shfl_xor_sync(0xffffffffu, ps0, 2);
    ps1 += __shfl_xor_sync(0xffffffffu, ps1, 1);
    ps1 += __shfl_xor_sync(0xffffffffu, ps1, 2);
    if (lc == 0) {
        redl[wn * 64 + r0] = ps0;
        redl[wn * 64 + r1] = ps1;
    }

#pragma unroll
    for (int nt = 0; nt < 4; nt++) {
        acc[nt][0] *= cr0; acc[nt][1] *= cr0;
        acc[nt][2] *= cr1; acc[nt][3] *= cr1;
    }
    m0 = mn0; m1 = mn1;
    __syncthreads();

    l0 = l0 * cr0 + redl[r0] + redl[64 + r0];
    l1 = l1 * cr1 + redl[r1] + redl[64 + r1];

#pragma unroll
    for (int k0 = 0; k0 < 64; k0 += 8) {
        uint32_t a[4];
        lda_frag(Ps, wm * 16, k0, lr, lc, a);
#pragma unroll
        for (int nt = 0; nt < 4; nt++) {
            uint32_t bv[2];
            ldbV_frag(Vs, wn * 32 + nt * 8, k0, lr, lc, bv);
            mma_tf32(acc[nt], a, bv);
        }
    }
}

__global__ __launch_bounds__(256) void flash_diff_hyb(
    const unsigned short* __restrict__ qc, const unsigned short* __restrict__ kc,
    const float* __restrict__ vb, float* __restrict__ yb)
{
    extern __shared__ char smc[];
    const uint32_t sb = smem_u32(smc);
    float* Vs   = (float*)(smc + OFF_V);
    float* Ps   = (float*)(smc + OFF_PS);
    float* redm = (float*)(smc + OFF_RED);
    float* redl = redm + 128;

    const int tid = threadIdx.x;
    const int wid = tid >> 5, lane = tid & 31;
    const int wm = wid >> 1, wn = wid & 1;
    const int lr = lane >> 2, lc = lane & 3;
    const int qi = blockIdx.x, h = blockIdx.y, b = blockIdx.z;
    const int q0 = qi * 64;
    const int rl0 = wm * 16 + lr;

    const size_t NQ2 = (size_t)MT * 2 * CC;
    const size_t brow = (size_t)b * TT;       // R11 FIX: batch row offset

    // stage Q (tiles 0-3: Q1h,Q1l,Q2h,Q2l) via cp.async
#pragma unroll
    for (int t = 0; t < 8; t++) {
        int idx = tid + t * 256;
        int tile = idx >> 9;
        int c = idx & 511;
        int row = c >> 3, seg = c & 7;
        int br = tile >> 1, hl = tile & 1;
        cp_async16(sb + tile * FTILE + row * FBP + seg * 16,
                   qc + (size_t)hl * NQ2 + (brow + q0 + row) * (2 * CC) +
                       br * CC + h * DHD + seg * 8);
    }
    CP_ASYNC_COMMIT();

    float acc1[4][4] = {}, acc2[4][4] = {};
    float m10 = -1e30f, m11 = -1e30f, l10 = 0.f, l11 = 0.f;
    float m20 = -1e30f, m21 = -1e30f, l20 = 0.f, l21 = 0.f;

    for (int kt = 0; kt <= qi; kt++) {
        const int k0t = kt * 64;
        __syncthreads();  // prior-tile smem reads done
        // K tiles 4-7 (bf16 hi/lo)
#pragma unroll
        for (int t = 0; t < 8; t++) {
            int idx = tid + t * 256;
            int tile = idx >> 9;
            int c = idx & 511;
            int row = c >> 3, seg = c & 7;
            int br = tile >> 1, hl = tile & 1;
            cp_async16(sb + (4 + tile) * FTILE + row * FBP + seg * 16,
                       kc + (size_t)hl * NQ2 + (brow + k0t + row) * (2 * CC) +
                           br * CC + h * DHD + seg * 8);
        }
        // V tile (fp32, VPAD pitch)
#pragma unroll
        for (int t = 0; t < 4; t++) {
            int idx = tid + t * 256;
            int row = idx >> 4, sg = idx & 15;
            cp_async16(sb + OFF_V + row * (VPAD * 4) + sg * 16,
                       vb + (brow + k0t + row) * CC + h * DHD + sg * 4);
        }
        CP_ASYNC_COMMIT();
        CP_ASYNC_WAIT(0);
        __syncthreads();
        const bool diag = (kt == qi);

        branch_hyb(sb, Vs, Ps, redm, redl, 0, acc1, m10, m11, l10, l11,
                   diag, wm, wn, lr, lc, lane, rl0);
        branch_hyb(sb, Vs, Ps, redm, redl, 1, acc2, m20, m21, l20, l21,
                   diag, wm, wn, lr, lc, lane, rl0);
    }

    // epilogue: y = P1V/l1 - lam*P2V/l2 (fp32)
    const float lam = g_lambda;
    const float i10 = 1.f / l10, i11 = 1.f / l11;
    const float i20 = lam / l20, i21 = lam / l21;
    const int r0g = q0 + rl0, r1g = r0g + 8;
#pragma unroll
    for (int nt = 0; nt < 4; nt++) {
        const int col = h * DHD + wn * 32 + nt * 8 + 2 * lc;
        float2 o0 = make_float2(acc1[nt][0] * i10 - acc2[nt][0] * i20,
                                acc1[nt][1] * i10 - acc2[nt][1] * i20);
        float2 o1 = make_float2(acc1[nt][2] * i11 - acc2[nt][2] * i21,
                                acc1[nt][3] * i11 - acc2[nt][3] * i21);
        *(float2*)(yb + (brow + r0g) * CC + col) = o0;
        *(float2*)(yb + (brow + r1g) * CC + col) = o1;
    }
}

// ---------------------------------------------------------------------------
// Launch. ncu fixed slot (launch index 3) = Q-projection GEMM.
// ---------------------------------------------------------------------------
static inline void conv(const float* src, unsigned short* dst, size_t n) {
    int n4 = (int)(n / 4);
    int blocks = (n4 + 255) / 256;
    if (blocks > 4096) blocks = 4096;
    convert_hilo<<<blocks, 256>>>((const float4*)src, (uint2*)dst,
                                  (uint2*)(dst + n), n4);
}

extern "C" void kernel_launch(void* const* d_in, const int* in_sizes, int n_in,
                              void* d_out, int out_size)
{
    const float* x   = (const float*)d_in[0];
    const float* wq  = (const float*)d_in[1];
    const float* wk  = (const float*)d_in[2];
    const float* wv  = (const float*)d_in[3];
    const float* wo  = (const float*)d_in[4];
    const float* lq1 = (const float*)d_in[5];
    const float* lk1 = (const float*)d_in[6];
    const float* lq2 = (const float*)d_in[7];
    const float* lk2 = (const float*)d_in[8];
    const float* wc  = (const float*)d_in[9];
    const float* bc  = (const float*)d_in[10];
    const float* we  = (const float*)d_in[11];
    const float* be  = (const float*)d_in[12];

    float *v, *y;
    cudaGetSymbolAddress((void**)&v, g_v);
    cudaGetSymbolAddress((void**)&y, g_y);

    unsigned short *xc, *wqc, *wkc, *wvc, *woc, *wcc, *wec;
    unsigned short *qc, *kc, *yc, *y2c, *hc;
    cudaGetSymbolAddress((void**)&xc,  g_xc);
    cudaGetSymbolAddress((void**)&wqc, g_wqc);
    cudaGetSymbolAddress((void**)&wkc, g_wkc);
    cudaGetSymbolAddress((void**)&wvc, g_wvc);
    cudaGetSymbolAddress((void**)&woc, g_woc);
    cudaGetSymbolAddress((void**)&wcc, g_wcc);
    cudaGetSymbolAddress((void**)&wec, g_wec);
    cudaGetSymbolAddress((void**)&qc,  g_qc);
    cudaGetSymbolAddress((void**)&kc,  g_kc);
    cudaGetSymbolAddress((void**)&yc,  g_yc);
    cudaGetSymbolAddress((void**)&y2c, g_y2c);
    cudaGetSymbolAddress((void**)&hc,  g_hc);

    cudaFuncSetAttribute(mma_gemm_tn, cudaFuncAttributeMaxDynamicSharedMemorySize,
                         GEMM_SMEM);
    cudaFuncSetAttribute(flash_diff_hyb, cudaFuncAttributeMaxDynamicSharedMemorySize,
                         FLASH_SMEM);

    const size_t NX  = (size_t)MT * CC;
    const size_t NQ2 = (size_t)MT * 2 * CC;
    const size_t NQK = (size_t)2 * CC * CC;
    const size_t NSQ = (size_t)CC * CC;
    const size_t NHC = (size_t)(CC / 2) * CC;
    const size_t NH  = (size_t)MT * (CC / 2);

    dim3 blk(256);
    conv(x, xc, NX);                                                       // 0
    conv(wq, wqc, NQK);                                                    // 1
    conv(wk, wkc, NQK);                                                    // 2
    mma_gemm_tn<<<dim3(2 * CC / 128, MT / 128), blk, GEMM_SMEM>>>(         // 3 (ncu)
        xc, xc + NX, wqc, wqc + NQK, nullptr, nullptr, qc, qc + NQ2,
        MT, 2 * CC, CC);
    conv(wv, wvc, NSQ);                                                    // 4
    mma_gemm_tn<<<dim3(2 * CC / 128, MT / 128), blk, GEMM_SMEM>>>(         // 5
        xc, xc + NX, wkc, wkc + NQK, nullptr, nullptr, kc, kc + NQ2,
        MT, 2 * CC, CC);
    mma_gemm_tn<<<dim3(CC / 128, MT / 128), blk, GEMM_SMEM>>>(             // 6: v fp32
        xc, xc + NX, wvc, wvc + NSQ, nullptr, v, nullptr, nullptr,
        MT, CC, CC);
    lambda_kernel<<<1, 32>>>(lq1, lk1, lq2, lk2);                          // 7
    flash_diff_hyb<<<dim3(TT / 64, HH, BB), blk, FLASH_SMEM>>>(            // 8
        qc, kc, v, y);
    conv(y, yc, NX);                                                       // 9
    conv(wo, woc, NSQ);                                                    // 10
    mma_gemm_tn<<<dim3(CC / 128, MT / 128), blk, GEMM_SMEM>>>(             // 11: y2 bf16
        yc, yc + NX, woc, woc + NSQ, nullptr, nullptr, y2c, y2c + NX,
        MT, CC, CC);
    conv(wc, wcc, NHC);                                                    // 12
    mma_gemm_tn<<<dim3(CC / 2 / 128, MT / 128), blk, GEMM_SMEM>>>(         // 13: h bf16
        y2c, y2c + NX, wcc, wcc + NHC, bc, nullptr, hc, hc + NH,
        MT, CC / 2, CC);
    conv(we, wec, NHC);                                                    // 14
    mma_gemm_tn<<<dim3(CC / 128, MT / 128), blk, GEMM_SMEM>>>(             // 15: out fp32
        hc, hc + NH, wec, wec + NHC, be, (float*)d_out, nullptr, nullptr,
        MT, CC, CC / 2);
}

// round 12
// speedup vs baseline: 2.8892x; 1.0564x over previous
#include <cuda_runtime.h>
#include <math.h>
#include <stdint.h>

// Problem constants
#define BB 2
#define TT 2048
#define CC 1024
#define HH 16
#define DHD 64
#define MT (BB * TT)          // 4096 rows

// ---------------------------------------------------------------------------
// Scratch (device globals)
// ---------------------------------------------------------------------------
__device__ float g_lambda;
__device__ float g_v[MT * CC];          // fp32 V (flash consumes fp32)
__device__ float g_y[MT * CC];          // fp32 attention output

// hi/lo bf16 pairs (hi at [0], lo at [elem_count])
__device__ unsigned short g_xc [2ul * MT * CC];
__device__ unsigned short g_wqc[2ul * 2 * CC * CC];
__device__ unsigned short g_wkc[2ul * 2 * CC * CC];
__device__ unsigned short g_wvc[2ul * CC * CC];
__device__ unsigned short g_woc[2ul * CC * CC];
__device__ unsigned short g_wcc[2ul * (CC / 2) * CC];
__device__ unsigned short g_wec[2ul * CC * (CC / 2)];
__device__ unsigned short g_qc [2ul * MT * 2 * CC];
__device__ unsigned short g_kc [2ul * MT * 2 * CC];
__device__ unsigned short g_yc [2ul * MT * CC];
__device__ unsigned short g_y2c[2ul * MT * CC];
__device__ unsigned short g_hc [2ul * MT * (CC / 2)];

// ---------------------------------------------------------------------------
// PTX helpers (compute_100-legal)
// ---------------------------------------------------------------------------
__device__ __forceinline__ uint32_t smem_u32(const void* p) {
    uint32_t a;
    asm("{ .reg .u64 t; cvta.to.shared.u64 t, %1; cvt.u32.u64 %0, t; }"
        : "=r"(a) : "l"(p));
    return a;
}

__device__ __forceinline__ void cp_async16(uint32_t dst, const void* src) {
    asm volatile("cp.async.ca.shared.global [%0], [%1], 16;"
                 :: "r"(dst), "l"(src) : "memory");
}
#define CP_ASYNC_COMMIT() asm volatile("cp.async.commit_group;" ::: "memory")
#define CP_ASYNC_WAIT(n)  asm volatile("cp.async.wait_group %0;" :: "n"(n) : "memory")

__device__ __forceinline__ uint32_t f2tf32(float f) {
    uint32_t r;
    asm("cvt.rna.tf32.f32 %0, %1;" : "=r"(r) : "f"(f));
    return r;
}

// tf32 m16n8k8 (P@V in attention)
__device__ __forceinline__ void mma_tf32(float* d, const uint32_t* a, const uint32_t* b) {
    asm volatile(
        "mma.sync.aligned.m16n8k8.row.col.f32.tf32.tf32.f32 "
        "{%0,%1,%2,%3}, {%4,%5,%6,%7}, {%8,%9}, {%0,%1,%2,%3};"
        : "+f"(d[0]), "+f"(d[1]), "+f"(d[2]), "+f"(d[3])
        : "r"(a[0]), "r"(a[1]), "r"(a[2]), "r"(a[3]), "r"(b[0]), "r"(b[1]));
}

// bf16 m16n8k16 (GEMMs + S=QK^T)
__device__ __forceinline__ void mma_bf16(float* d, const uint32_t* a, const uint32_t* b) {
    asm volatile(
        "mma.sync.aligned.m16n8k16.row.col.f32.bf16.bf16.f32 "
        "{%0,%1,%2,%3}, {%4,%5,%6,%7}, {%8,%9}, {%0,%1,%2,%3};"
        : "+f"(d[0]), "+f"(d[1]), "+f"(d[2]), "+f"(d[3])
        : "r"(a[0]), "r"(a[1]), "r"(a[2]), "r"(a[3]), "r"(b[0]), "r"(b[1]));
}

__device__ __forceinline__ void ldm_x4(uint32_t* r, uint32_t addr) {
    asm volatile("ldmatrix.sync.aligned.m8n8.x4.shared.b16 {%0,%1,%2,%3}, [%4];"
        : "=r"(r[0]), "=r"(r[1]), "=r"(r[2]), "=r"(r[3]) : "r"(addr));
}
__device__ __forceinline__ void ldm_x2(uint32_t* r, uint32_t addr) {
    asm volatile("ldmatrix.sync.aligned.m8n8.x2.shared.b16 {%0,%1}, [%2];"
        : "=r"(r[0]), "=r"(r[1]) : "r"(addr));
}

__device__ __forceinline__ uint32_t pack_bf16x2(float e0, float e1) {
    uint32_t r;
    asm("cvt.rn.bf16x2.f32 %0, %1, %2;" : "=r"(r) : "f"(e1), "f"(e0));
    return r;
}
__device__ __forceinline__ uint32_t lo_of(uint32_t h, float x0, float x1) {
    return pack_bf16x2(x0 - __uint_as_float(h << 16),
                       x1 - __uint_as_float(h & 0xffff0000u));
}

// ---------------------------------------------------------------------------
// fp32 -> (hi, lo) bf16 conversion kernel
// ---------------------------------------------------------------------------
__global__ __launch_bounds__(256) void convert_hilo(
    const float4* __restrict__ src, uint2* __restrict__ hi,
    uint2* __restrict__ lo, int n4)
{
    for (int i = blockIdx.x * blockDim.x + threadIdx.x; i < n4;
         i += gridDim.x * blockDim.x) {
        float4 v = src[i];
        uint32_t h0 = pack_bf16x2(v.x, v.y);
        uint32_t h1 = pack_bf16x2(v.z, v.w);
        hi[i] = make_uint2(h0, h1);
        lo[i] = make_uint2(lo_of(h0, v.x, v.y), lo_of(h1, v.z, v.w));
    }
}

// ---------------------------------------------------------------------------
// bf16x3 GEMM (R8/R11-proven core; dual-mode epilogue). Unchanged.
// ---------------------------------------------------------------------------
#define GBM 128
#define GBN 128
#define GBK 32
#define SPITCH 80
#define TILE_B (128 * SPITCH)
#define STAGE_B (4 * TILE_B)
#define GEMM_SMEM (2 * STAGE_B)         // 81920 B

__device__ __forceinline__ void g_stage(
    uint32_t sbuf,
    const unsigned short* __restrict__ Ah, const unsigned short* __restrict__ Al,
    const unsigned short* __restrict__ Bh, const unsigned short* __restrict__ Bl,
    int K, int kc, int tid)
{
    const unsigned short* srcs[4] = {Ah, Al, Bh, Bl};
#pragma unroll
    for (int j = 0; j < 8; j++) {
        const int tile = j >> 1;
        const int idx = (j & 1) * 256 + tid;
        const int m = idx >> 2, seg = idx & 3;
        uint32_t dst = sbuf + tile * TILE_B + m * SPITCH + seg * 16;
        cp_async16(dst, srcs[tile] + (size_t)m * K + kc * GBK + seg * 8);
    }
}

__global__ void __launch_bounds__(256, 2) mma_gemm_tn(
    const unsigned short* __restrict__ Ah, const unsigned short* __restrict__ Al,
    const unsigned short* __restrict__ Bh, const unsigned short* __restrict__ Bl,
    const float* __restrict__ bias, float* __restrict__ Cf,
    unsigned short* __restrict__ Chi, unsigned short* __restrict__ Clo,
    int M, int N, int K)
{
    extern __shared__ float smg[];
    const uint32_t sb = smem_u32(smg);
    const int tid = threadIdx.x;
    const int wid = tid >> 5, lane = tid & 31;
    const int wm = wid >> 2, wn = wid & 3;
    const int lr = lane >> 2;
    const int lc = lane & 3;
    const int m0 = blockIdx.y * GBM;
    const int n0 = blockIdx.x * GBN;

    const unsigned short* Ah0 = Ah + (size_t)m0 * K;
    const unsigned short* Al0 = Al + (size_t)m0 * K;
    const unsigned short* Bh0 = Bh + (size_t)n0 * K;
    const unsigned short* Bl0 = Bl + (size_t)n0 * K;

    const uint32_t a_off =
        (uint32_t)(wm * 64 + (lane & 7) + ((lane >> 3) & 1) * 8) * SPITCH +
        ((lane >> 4) & 1) * 16;
    const uint32_t b_off =
        (uint32_t)(wn * 32 + (lane & 7)) * SPITCH + ((lane >> 3) & 1) * 16;

    float acc[4][4][4];
#pragma unroll
    for (int mt = 0; mt < 4; mt++)
#pragma unroll
        for (int nt = 0; nt < 4; nt++)
#pragma unroll
            for (int r = 0; r < 4; r++) acc[mt][nt][r] = 0.f;

    const int nch = K / GBK;

    g_stage(sb, Ah0, Al0, Bh0, Bl0, K, 0, tid);
    CP_ASYNC_COMMIT();

    for (int i = 0; i < nch; i++) {
        if (i + 1 < nch) {
            g_stage(sb + ((i + 1) & 1) * STAGE_B, Ah0, Al0, Bh0, Bl0, K, i + 1, tid);
            CP_ASYNC_COMMIT();
            CP_ASYNC_WAIT(1);
        } else {
            CP_ASYNC_WAIT(0);
        }
        __syncthreads();

        const uint32_t st = sb + (i & 1) * STAGE_B;

#pragma unroll
        for (int ks = 0; ks < 2; ks++) {
            const uint32_t kbyte = ks * 32;
            uint32_t bh[4][2], bl[4][2];
#pragma unroll
            for (int nt = 0; nt < 4; nt++) {
                uint32_t ad = st + 2 * TILE_B + b_off + nt * 8 * SPITCH + kbyte;
                ldm_x2(bh[nt], ad);
                ldm_x2(bl[nt], ad + TILE_B);
            }
#pragma unroll
            for (int mt = 0; mt < 4; mt++) {
                uint32_t ad = st + a_off + mt * 16 * SPITCH + kbyte;
                uint32_t ah[4], al[4];
                ldm_x4(ah, ad);
                ldm_x4(al, ad + TILE_B);
#pragma unroll
                for (int nt = 0; nt < 4; nt++) {
                    mma_bf16(acc[mt][nt], al, bh[nt]);
                    mma_bf16(acc[mt][nt], ah, bl[nt]);
                    mma_bf16(acc[mt][nt], ah, bh[nt]);
                }
            }
        }
        __syncthreads();
    }

#pragma unroll
    for (int mt = 0; mt < 4; mt++) {
        const int row = m0 + wm * 64 + mt * 16 + lr;
#pragma unroll
        for (int nt = 0; nt < 4; nt++) {
            const int col = n0 + wn * 32 + nt * 8 + 2 * lc;
            float b0 = 0.f, b1 = 0.f;
            if (bias) { b0 = __ldg(bias + col); b1 = __ldg(bias + col + 1); }
            float v0x = acc[mt][nt][0] + b0, v0y = acc[mt][nt][1] + b1;
            float v1x = acc[mt][nt][2] + b0, v1y = acc[mt][nt][3] + b1;
            if (Cf) {
                *(float2*)(Cf + (size_t)row * N + col) = make_float2(v0x, v0y);
                *(float2*)(Cf + (size_t)(row + 8) * N + col) = make_float2(v1x, v1y);
            } else {
                uint32_t h0 = pack_bf16x2(v0x, v0y);
                uint32_t h1 = pack_bf16x2(v1x, v1y);
                *(uint32_t*)&Chi[(size_t)row * N + col] = h0;
                *(uint32_t*)&Clo[(size_t)row * N + col] = lo_of(h0, v0x, v0y);
                *(uint32_t*)&Chi[(size_t)(row + 8) * N + col] = h1;
                *(uint32_t*)&Clo[(size_t)(row + 8) * N + col] = lo_of(h1, v1x, v1y);
            }
        }
    }
}

// ---------------------------------------------------------------------------
// Lambda scalar
// ---------------------------------------------------------------------------
__global__ void lambda_kernel(const float* __restrict__ lq1, const float* __restrict__ lk1,
                              const float* __restrict__ lq2, const float* __restrict__ lk2)
{
    if (threadIdx.x == 0) {
        float s1 = 0.f, s2 = 0.f;
        for (int i = 0; i < HH; i++) {
            s1 = fmaf(lq1[i], lk1[i], s1);
            s2 = fmaf(lq2[i], lk2[i], s2);
        }
        double li = 0.8 - 0.6 * exp(-0.3 * 11.0);  // N_LAYER=12
        g_lambda = (float)(exp((double)s1) - exp((double)s2) + li);
    }
}

// ---------------------------------------------------------------------------
// Differential flash attention, R12 restructure:
//  - warps 0-3 process branch 1, warps 4-7 process branch 2 CONCURRENTLY;
//    each warp owns full 16x64 rows -> softmax reductions are quad-shuffles
//    only (no block barriers inside branch processing).
//  - K/V double-buffered cp.async prefetch (stage kt+1 during compute of kt).
//  - S=QK^T bf16x3 ldmatrix (R11-proven); P@V fp32/tf32 (R7-proven).
// ---------------------------------------------------------------------------
#define FBP 144                          // bytes per bf16 tile row (72 bf16)
#define FTILE (64 * FBP)                 // 9216 B
#define APAD 68                          // Ps fp32 pitch (floats)
#define VPAD 72                          // Vs fp32 pitch (floats)
#define OFF_K   (4 * FTILE)                    // 36864 (K: 2 bufs x 4 tiles)
#define OFF_V   (12 * FTILE)                   // 110592 (V: 2 bufs fp32)
#define VBYTES  (64 * VPAD * 4)                // 18432
#define OFF_PS  (OFF_V + 2 * VBYTES)           // 147456 (Ps: one per group)
#define PSBYTES (64 * APAD * 4)                // 17408
#define FLASH_SMEM (OFF_PS + 2 * PSBYTES)      // 182272

__device__ __forceinline__ void lda_frag(const float* S, int row0, int k0,
                                         int lr, int lc, uint32_t a[4]) {
    a[0] = f2tf32(S[(row0 + lr) * APAD + k0 + lc]);
    a[1] = f2tf32(S[(row0 + lr + 8) * APAD + k0 + lc]);
    a[2] = f2tf32(S[(row0 + lr) * APAD + k0 + 4 + lc]);
    a[3] = f2tf32(S[(row0 + lr + 8) * APAD + k0 + 4 + lc]);
}
__device__ __forceinline__ void ldbV_frag(const float* Vs, int n0, int k0,
                                          int lr, int lc, uint32_t b[2]) {
    b[0] = f2tf32(Vs[(k0 + lc) * VPAD + n0 + lr]);
    b[1] = f2tf32(Vs[(k0 + 4 + lc) * VPAD + n0 + lr]);
}

__global__ __launch_bounds__(256) void flash_diff_par(
    const unsigned short* __restrict__ qc, const unsigned short* __restrict__ kc,
    const float* __restrict__ vb, float* __restrict__ yb)
{
    extern __shared__ char smc[];
    const uint32_t sb = smem_u32(smc);

    const int tid = threadIdx.x;
    const int wid = tid >> 5, lane = tid & 31;
    const int g = wid >> 2;              // branch group: 0 -> att1, 1 -> att2
    const int wg = wid & 3;              // warp-in-group: rows wg*16..wg*16+15
    const int lr = lane >> 2, lc = lane & 3;
    const int qi = blockIdx.x, h = blockIdx.y, b = blockIdx.z;
    const int q0 = qi * 64;
    const int rl0 = wg * 16 + lr;        // local row of this thread (first)

    const size_t NQ2 = (size_t)MT * 2 * CC;
    const size_t brow = (size_t)b * TT;

    // ldmatrix address offsets (R11-proven pattern, wm -> wg)
    const uint32_t arow =
        (uint32_t)(wg * 16 + (lane & 7) + ((lane >> 3) & 1) * 8) * FBP +
        ((lane >> 4) & 1) * 16;
    const uint32_t boff =
        (uint32_t)(lane & 7) * FBP + ((lane >> 3) & 1) * 16;

    // ---- stage Q (tiles 0-3: Q1h,Q1l,Q2h,Q2l) + K/V for kt=0 ----
#pragma unroll
    for (int t = 0; t < 8; t++) {
        int idx = tid + t * 256;
        int tile = idx >> 9;
        int c = idx & 511;
        int row = c >> 3, seg = c & 7;
        int br = tile >> 1, hl = tile & 1;
        cp_async16(sb + tile * FTILE + row * FBP + seg * 16,
                   qc + (size_t)hl * NQ2 + (brow + q0 + row) * (2 * CC) +
                       br * CC + h * DHD + seg * 8);
    }
    // K kt=0 into buf0
#pragma unroll
    for (int t = 0; t < 8; t++) {
        int idx = tid + t * 256;
        int tile = idx >> 9;
        int c = idx & 511;
        int row = c >> 3, seg = c & 7;
        int br = tile >> 1, hl = tile & 1;
        cp_async16(sb + OFF_K + tile * FTILE + row * FBP + seg * 16,
                   kc + (size_t)hl * NQ2 + (brow + row) * (2 * CC) +
                       br * CC + h * DHD + seg * 8);
    }
    // V kt=0 into buf0
#pragma unroll
    for (int t = 0; t < 4; t++) {
        int idx = tid + t * 256;
        int row = idx >> 4, sg = idx & 15;
        cp_async16(sb + OFF_V + row * (VPAD * 4) + sg * 16,
                   vb + (brow + row) * CC + h * DHD + sg * 4);
    }
    CP_ASYNC_COMMIT();

    float s[8][4], acc[8][4];
#pragma unroll
    for (int nt = 0; nt < 8; nt++)
#pragma unroll
        for (int r = 0; r < 4; r++) acc[nt][r] = 0.f;
    float m0 = -1e30f, m1 = -1e30f, l0 = 0.f, l1 = 0.f;

    for (int kt = 0; kt <= qi; kt++) {
        const int buf = kt & 1;
        // prefetch kt+1 into the other buffer
        if (kt < qi) {
            const int k0n = (kt + 1) * 64;
            const int nb = 1 - buf;
#pragma unroll
            for (int t = 0; t < 8; t++) {
                int idx = tid + t * 256;
                int tile = idx >> 9;
                int c = idx & 511;
                int row = c >> 3, seg = c & 7;
                int br = tile >> 1, hl = tile & 1;
                cp_async16(sb + OFF_K + (nb * 4 + tile) * FTILE + row * FBP + seg * 16,
                           kc + (size_t)hl * NQ2 + (brow + k0n + row) * (2 * CC) +
                               br * CC + h * DHD + seg * 8);
            }
#pragma unroll
            for (int t = 0; t < 4; t++) {
                int idx = tid + t * 256;
                int row = idx >> 4, sg = idx & 15;
                cp_async16(sb + OFF_V + nb * VBYTES + row * (VPAD * 4) + sg * 16,
                           vb + (brow + k0n + row) * CC + h * DHD + sg * 4);
            }
            CP_ASYNC_COMMIT();
            CP_ASYNC_WAIT(1);
        } else {
            CP_ASYNC_WAIT(0);
        }
        __syncthreads();   // current-buffer data visible to all warps

        const bool diag = (kt == qi);
        const uint32_t qh = sb + (g * 2) * FTILE;
        const uint32_t ql = qh + FTILE;
        const uint32_t kh = sb + OFF_K + (buf * 4 + g * 2) * FTILE;
        const uint32_t kl = kh + FTILE;
        const float* Vs = (const float*)(smc + OFF_V + buf * VBYTES);
        float* Ps = (float*)(smc + OFF_PS + g * PSBYTES);

        // ---- S = Q @ K^T (bf16x3), warp tile 16x64 ----
#pragma unroll
        for (int nt = 0; nt < 8; nt++)
#pragma unroll
            for (int r = 0; r < 4; r++) s[nt][r] = 0.f;
#pragma unroll
        for (int ks = 0; ks < 4; ks++) {
            uint32_t ah[4], al[4];
            ldm_x4(ah, qh + arow + ks * 32);
            ldm_x4(al, ql + arow + ks * 32);
#pragma unroll
            for (int nt = 0; nt < 8; nt++) {
                uint32_t bh[2], bl[2];
                uint32_t ad = boff + nt * 8 * FBP + ks * 32;
                ldm_x2(bh, kh + ad);
                ldm_x2(bl, kl + ad);
                mma_bf16(s[nt], al, bh);
                mma_bf16(s[nt], ah, bl);
                mma_bf16(s[nt], ah, bh);
            }
        }

        // ---- scale + mask ----
        const float scale = 0.125f;
        const int r0 = rl0, r1 = rl0 + 8;
#pragma unroll
        for (int nt = 0; nt < 8; nt++) {
            const int c0 = nt * 8 + 2 * lc;
            s[nt][0] *= scale; s[nt][1] *= scale;
            s[nt][2] *= scale; s[nt][3] *= scale;
            if (diag) {
                if (c0 > r0)     s[nt][0] = -1e30f;
                if (c0 + 1 > r0) s[nt][1] = -1e30f;
                if (c0 > r1)     s[nt][2] = -1e30f;
                if (c0 + 1 > r1) s[nt][3] = -1e30f;
            }
        }

        // ---- row max: local + quad shuffle (full row within warp) ----
        float mx0 = -1e30f, mx1 = -1e30f;
#pragma unroll
        for (int nt = 0; nt < 8; nt++) {
            mx0 = fmaxf(mx0, fmaxf(s[nt][0], s[nt][1]));
            mx1 = fmaxf(mx1, fmaxf(s[nt][2], s[nt][3]));
        }
        mx0 = fmaxf(mx0, __shfl_xor_sync(0xffffffffu, mx0, 1));
        mx0 = fmaxf(mx0, __shfl_xor_sync(0xffffffffu, mx0, 2));
        mx1 = fmaxf(mx1, __shfl_xor_sync(0xffffffffu, mx1, 1));
        mx1 = fmaxf(mx1, __shfl_xor_sync(0xffffffffu, mx1, 2));

        const float mn0 = fmaxf(m0, mx0);
        const float mn1 = fmaxf(m1, mx1);
        const float cr0 = __expf(m0 - mn0);
        const float cr1 = __expf(m1 - mn1);

        // ---- exp + partial sums + Ps store (warp-private rows) ----
        __syncwarp();
        float ps0 = 0.f, ps1 = 0.f;
#pragma unroll
        for (int nt = 0; nt < 8; nt++) {
            const int cl = nt * 8 + 2 * lc;
            float p0 = __expf(s[nt][0] - mn0);
            float p1 = __expf(s[nt][1] - mn0);
            float p2 = __expf(s[nt][2] - mn1);
            float p3 = __expf(s[nt][3] - mn1);
            ps0 += p0 + p1;
            ps1 += p2 + p3;
            *(float2*)&Ps[r0 * APAD + cl] = make_float2(p0, p1);
            *(float2*)&Ps[r1 * APAD + cl] = make_float2(p2, p3);
        }
        ps0 += __shfl_xor_sync(0xffffffffu, ps0, 1);
        ps0 += __shfl_xor_sync(0xffffffffu, ps0, 2);
        ps1 += __shfl_xor_sync(0xffffffffu, ps1, 1);
        ps1 += __shfl_xor_sync(0xffffffffu, ps1, 2);

        l0 = l0 * cr0 + ps0;
        l1 = l1 * cr1 + ps1;
        m0 = mn0; m1 = mn1;

        // ---- rescale O accumulator ----
#pragma unroll
        for (int nt = 0; nt < 8; nt++) {
            acc[nt][0] *= cr0; acc[nt][1] *= cr0;
            acc[nt][2] *= cr1; acc[nt][3] *= cr1;
        }
        __syncwarp();   // Ps writes visible across warp lanes

        // ---- O += P @ V (tf32, R7-proven) ----
#pragma unroll
        for (int k0 = 0; k0 < 64; k0 += 8) {
            uint32_t a[4];
            lda_frag(Ps, wg * 16, k0, lr, lc, a);
#pragma unroll
            for (int nt = 0; nt < 8; nt++) {
                uint32_t bv[2];
                ldbV_frag(Vs, nt * 8, k0, lr, lc, bv);
                mma_tf32(acc[nt], a, bv);
            }
        }
        __syncthreads();   // all reads of buf done before next prefetch overwrite
    }

    // ---- epilogue: combine branches via smem exchange ----
    float* Eps = (float*)(smc + OFF_PS);   // reuse Ps group-0 buffer
    const float lam = g_lambda;
    if (g == 1) {
        const float i0 = lam / l0, i1 = lam / l1;
        const int r0 = rl0, r1 = rl0 + 8;
#pragma unroll
        for (int nt = 0; nt < 8; nt++) {
            const int cl = nt * 8 + 2 * lc;
            *(float2*)&Eps[r0 * APAD + cl] =
                make_float2(acc[nt][0] * i0, acc[nt][1] * i0);
            *(float2*)&Eps[r1 * APAD + cl] =
                make_float2(acc[nt][2] * i1, acc[nt][3] * i1);
        }
    }
    __syncthreads();
    if (g == 0) {
        const float i0 = 1.f / l0, i1 = 1.f / l1;
        const int r0g = q0 + rl0, r1g = r0g + 8;
#pragma unroll
        for (int nt = 0; nt < 8; nt++) {
            const int cl = nt * 8 + 2 * lc;
            const int col = h * DHD + cl;
            float2 e0 = *(float2*)&Eps[rl0 * APAD + cl];
            float2 e1 = *(float2*)&Eps[(rl0 + 8) * APAD + cl];
            float2 o0 = make_float2(acc[nt][0] * i0 - e0.x,
                                    acc[nt][1] * i0 - e0.y);
            float2 o1 = make_float2(acc[nt][2] * i1 - e1.x,
                                    acc[nt][3] * i1 - e1.y);
            *(float2*)(yb + (brow + r0g) * CC + col) = o0;
            *(float2*)(yb + (brow + r1g) * CC + col) = o1;
        }
    }
}

// ---------------------------------------------------------------------------
// Launch
// ---------------------------------------------------------------------------
static inline void conv(const float* src, unsigned short* dst, size_t n) {
    int n4 = (int)(n / 4);
    int blocks = (n4 + 255) / 256;
    if (blocks > 4096) blocks = 4096;
    convert_hilo<<<blocks, 256>>>((const float4*)src, (uint2*)dst,
                                  (uint2*)(dst + n), n4);
}

extern "C" void kernel_launch(void* const* d_in, const int* in_sizes, int n_in,
                              void* d_out, int out_size)
{
    const float* x   = (const float*)d_in[0];
    const float* wq  = (const float*)d_in[1];
    const float* wk  = (const float*)d_in[2];
    const float* wv  = (const float*)d_in[3];
    const float* wo  = (const float*)d_in[4];
    const float* lq1 = (const float*)d_in[5];
    const float* lk1 = (const float*)d_in[6];
    const float* lq2 = (const float*)d_in[7];
    const float* lk2 = (const float*)d_in[8];
    const float* wc  = (const float*)d_in[9];
    const float* bc  = (const float*)d_in[10];
    const float* we  = (const float*)d_in[11];
    const float* be  = (const float*)d_in[12];

    float *v, *y;
    cudaGetSymbolAddress((void**)&v, g_v);
    cudaGetSymbolAddress((void**)&y, g_y);

    unsigned short *xc, *wqc, *wkc, *wvc, *woc, *wcc, *wec;
    unsigned short *qc, *kc, *yc, *y2c, *hc;
    cudaGetSymbolAddress((void**)&xc,  g_xc);
    cudaGetSymbolAddress((void**)&wqc, g_wqc);
    cudaGetSymbolAddress((void**)&wkc, g_wkc);
    cudaGetSymbolAddress((void**)&wvc, g_wvc);
    cudaGetSymbolAddress((void**)&woc, g_woc);
    cudaGetSymbolAddress((void**)&wcc, g_wcc);
    cudaGetSymbolAddress((void**)&wec, g_wec);
    cudaGetSymbolAddress((void**)&qc,  g_qc);
    cudaGetSymbolAddress((void**)&kc,  g_kc);
    cudaGetSymbolAddress((void**)&yc,  g_yc);
    cudaGetSymbolAddress((void**)&y2c, g_y2c);
    cudaGetSymbolAddress((void**)&hc,  g_hc);

    cudaFuncSetAttribute(mma_gemm_tn, cudaFuncAttributeMaxDynamicSharedMemorySize,
                         GEMM_SMEM);
    cudaFuncSetAttribute(flash_diff_par, cudaFuncAttributeMaxDynamicSharedMemorySize,
                         FLASH_SMEM);

    const size_t NX  = (size_t)MT * CC;
    const size_t NQ2 = (size_t)MT * 2 * CC;
    const size_t NQK = (size_t)2 * CC * CC;
    const size_t NSQ = (size_t)CC * CC;
    const size_t NHC = (size_t)(CC / 2) * CC;
    const size_t NH  = (size_t)MT * (CC / 2);

    dim3 blk(256);
    conv(x, xc, NX);                                                       // 0
    conv(wq, wqc, NQK);                                                    // 1
    conv(wk, wkc, NQK);                                                    // 2
    mma_gemm_tn<<<dim3(2 * CC / 128, MT / 128), blk, GEMM_SMEM>>>(         // 3
        xc, xc + NX, wqc, wqc + NQK, nullptr, nullptr, qc, qc + NQ2,
        MT, 2 * CC, CC);
    conv(wv, wvc, NSQ);                                                    // 4
    mma_gemm_tn<<<dim3(2 * CC / 128, MT / 128), blk, GEMM_SMEM>>>(         // 5 (ncu)
        xc, xc + NX, wkc, wkc + NQK, nullptr, nullptr, kc, kc + NQ2,
        MT, 2 * CC, CC);
    mma_gemm_tn<<<dim3(CC / 128, MT / 128), blk, GEMM_SMEM>>>(             // 6: v fp32
        xc, xc + NX, wvc, wvc + NSQ, nullptr, v, nullptr, nullptr,
        MT, CC, CC);
    lambda_kernel<<<1, 32>>>(lq1, lk1, lq2, lk2);                          // 7
    flash_diff_par<<<dim3(TT / 64, HH, BB), blk, FLASH_SMEM>>>(            // 8
        qc, kc, v, y);
    conv(y, yc, NX);                                                       // 9
    conv(wo, woc, NSQ);                                                    // 10
    mma_gemm_tn<<<dim3(CC / 128, MT / 128), blk, GEMM_SMEM>>>(             // 11: y2 bf16
        yc, yc + NX, woc, woc + NSQ, nullptr, nullptr, y2c, y2c + NX,
        MT, CC, CC);
    conv(wc, wcc, NHC);                                                    // 12
    mma_gemm_tn<<<dim3(CC / 2 / 128, MT / 128), blk, GEMM_SMEM>>>(         // 13: h bf16
        y2c, y2c + NX, wcc, wcc + NHC, bc, nullptr, hc, hc + NH,
        MT, CC / 2, CC);
    conv(we, wec, NHC);                                                    // 14
    mma_gemm_tn<<<dim3(CC / 128, MT / 128), blk, GEMM_SMEM>>>(             // 15: out fp32
        hc, hc + NH, wec, wec + NHC, be, (float*)d_out, nullptr, nullptr,
        MT, CC, CC / 2);
}

// round 13
// speedup vs baseline: 3.0257x; 1.0473x over previous
#include <cuda_runtime.h>
#include <math.h>
#include <stdint.h>

// Problem constants
#define BB 2
#define TT 2048
#define CC 1024
#define HH 16
#define DHD 64
#define MT (BB * TT)          // 4096 rows

#define NXc  ((size_t)MT * CC)            // 4M
#define NQ2c ((size_t)MT * 2 * CC)        // 8M
#define NQKc ((size_t)2 * CC * CC)        // 2M
#define NSQc ((size_t)CC * CC)            // 1M

// ---------------------------------------------------------------------------
// Scratch (device globals)
// ---------------------------------------------------------------------------
__device__ float g_lambda;
__device__ float g_v[MT * CC];          // fp32 V (flash consumes fp32)

// hi/lo bf16 pairs (hi at [0], lo at [elem_count])
__device__ unsigned short g_xc [2ul * MT * CC];
__device__ unsigned short g_wqc[2ul * 2 * CC * CC];
__device__ unsigned short g_wkc[2ul * 2 * CC * CC];
__device__ unsigned short g_wvc[2ul * CC * CC];
__device__ unsigned short g_woc[2ul * CC * CC];
__device__ unsigned short g_wcc[2ul * (CC / 2) * CC];
__device__ unsigned short g_wec[2ul * CC * (CC / 2)];
__device__ unsigned short g_qc [2ul * MT * 2 * CC];
__device__ unsigned short g_kc [2ul * MT * 2 * CC];
__device__ unsigned short g_yc [2ul * MT * CC];
__device__ unsigned short g_y2c[2ul * MT * CC];
__device__ unsigned short g_hc [2ul * MT * (CC / 2)];

// ---------------------------------------------------------------------------
// PTX helpers (compute_100-legal)
// ---------------------------------------------------------------------------
__device__ __forceinline__ uint32_t smem_u32(const void* p) {
    uint32_t a;
    asm("{ .reg .u64 t; cvta.to.shared.u64 t, %1; cvt.u32.u64 %0, t; }"
        : "=r"(a) : "l"(p));
    return a;
}

__device__ __forceinline__ void cp_async16(uint32_t dst, const void* src) {
    asm volatile("cp.async.ca.shared.global [%0], [%1], 16;"
                 :: "r"(dst), "l"(src) : "memory");
}
#define CP_ASYNC_COMMIT() asm volatile("cp.async.commit_group;" ::: "memory")
#define CP_ASYNC_WAIT(n)  asm volatile("cp.async.wait_group %0;" :: "n"(n) : "memory")

__device__ __forceinline__ uint32_t f2tf32(float f) {
    uint32_t r;
    asm("cvt.rna.tf32.f32 %0, %1;" : "=r"(r) : "f"(f));
    return r;
}

// tf32 m16n8k8 (P@V in attention)
__device__ __forceinline__ void mma_tf32(float* d, const uint32_t* a, const uint32_t* b) {
    asm volatile(
        "mma.sync.aligned.m16n8k8.row.col.f32.tf32.tf32.f32 "
        "{%0,%1,%2,%3}, {%4,%5,%6,%7}, {%8,%9}, {%0,%1,%2,%3};"
        : "+f"(d[0]), "+f"(d[1]), "+f"(d[2]), "+f"(d[3])
        : "r"(a[0]), "r"(a[1]), "r"(a[2]), "r"(a[3]), "r"(b[0]), "r"(b[1]));
}

// bf16 m16n8k16 (GEMMs + S=QK^T)
__device__ __forceinline__ void mma_bf16(float* d, const uint32_t* a, const uint32_t* b) {
    asm volatile(
        "mma.sync.aligned.m16n8k16.row.col.f32.bf16.bf16.f32 "
        "{%0,%1,%2,%3}, {%4,%5,%6,%7}, {%8,%9}, {%0,%1,%2,%3};"
        : "+f"(d[0]), "+f"(d[1]), "+f"(d[2]), "+f"(d[3])
        : "r"(a[0]), "r"(a[1]), "r"(a[2]), "r"(a[3]), "r"(b[0]), "r"(b[1]));
}

__device__ __forceinline__ void ldm_x4(uint32_t* r, uint32_t addr) {
    asm volatile("ldmatrix.sync.aligned.m8n8.x4.shared.b16 {%0,%1,%2,%3}, [%4];"
        : "=r"(r[0]), "=r"(r[1]), "=r"(r[2]), "=r"(r[3]) : "r"(addr));
}
__device__ __forceinline__ void ldm_x2(uint32_t* r, uint32_t addr) {
    asm volatile("ldmatrix.sync.aligned.m8n8.x2.shared.b16 {%0,%1}, [%2];"
        : "=r"(r[0]), "=r"(r[1]) : "r"(addr));
}

__device__ __forceinline__ uint32_t pack_bf16x2(float e0, float e1) {
    uint32_t r;
    asm("cvt.rn.bf16x2.f32 %0, %1, %2;" : "=r"(r) : "f"(e1), "f"(e0));
    return r;
}
__device__ __forceinline__ uint32_t lo_of(uint32_t h, float x0, float x1) {
    return pack_bf16x2(x0 - __uint_as_float(h << 16),
                       x1 - __uint_as_float(h & 0xffff0000u));
}

// ---------------------------------------------------------------------------
// fp32 -> (hi, lo) bf16 conversion kernels
// ---------------------------------------------------------------------------
__global__ __launch_bounds__(256) void convert_hilo(
    const float4* __restrict__ src, uint2* __restrict__ hi,
    uint2* __restrict__ lo, int n4)
{
    for (int i = blockIdx.x * blockDim.x + threadIdx.x; i < n4;
         i += gridDim.x * blockDim.x) {
        float4 v = src[i];
        uint32_t h0 = pack_bf16x2(v.x, v.y);
        uint32_t h1 = pack_bf16x2(v.z, v.w);
        hi[i] = make_uint2(h0, h1);
        lo[i] = make_uint2(lo_of(h0, v.x, v.y), lo_of(h1, v.z, v.w));
    }
}

// dual-source variant: grid.z picks (srcA,dstA) or (srcB,dstB)
__global__ __launch_bounds__(256) void convert_hilo2(
    const float4* __restrict__ srcA, uint2* __restrict__ hiA, uint2* __restrict__ loA,
    const float4* __restrict__ srcB, uint2* __restrict__ hiB, uint2* __restrict__ loB,
    int n4)
{
    const float4* src = blockIdx.z ? srcB : srcA;
    uint2* hi = blockIdx.z ? hiB : hiA;
    uint2* lo = blockIdx.z ? loB : loA;
    for (int i = blockIdx.x * blockDim.x + threadIdx.x; i < n4;
         i += gridDim.x * blockDim.x) {
        float4 v = src[i];
        uint32_t h0 = pack_bf16x2(v.x, v.y);
        uint32_t h1 = pack_bf16x2(v.z, v.w);
        hi[i] = make_uint2(h0, h1);
        lo[i] = make_uint2(lo_of(h0, v.x, v.y), lo_of(h1, v.z, v.w));
    }
}

// ---------------------------------------------------------------------------
// bf16x3 GEMM core (R8/R11/R12-proven; dual-mode epilogue), as __device__ fn.
// ---------------------------------------------------------------------------
#define GBM 128
#define GBN 128
#define GBK 32
#define SPITCH 80
#define TILE_B (128 * SPITCH)
#define STAGE_B (4 * TILE_B)
#define GEMM_SMEM (2 * STAGE_B)         // 81920 B

__device__ __forceinline__ void g_stage(
    uint32_t sbuf,
    const unsigned short* __restrict__ Ah, const unsigned short* __restrict__ Al,
    const unsigned short* __restrict__ Bh, const unsigned short* __restrict__ Bl,
    int K, int kc, int tid)
{
    const unsigned short* srcs[4] = {Ah, Al, Bh, Bl};
#pragma unroll
    for (int j = 0; j < 8; j++) {
        const int tile = j >> 1;
        const int idx = (j & 1) * 256 + tid;
        const int m = idx >> 2, seg = idx & 3;
        uint32_t dst = sbuf + tile * TILE_B + m * SPITCH + seg * 16;
        cp_async16(dst, srcs[tile] + (size_t)m * K + kc * GBK + seg * 8);
    }
}

__device__ __forceinline__ void gemm_core(
    const unsigned short* __restrict__ Ah0, const unsigned short* __restrict__ Al0,
    const unsigned short* __restrict__ Bh0, const unsigned short* __restrict__ Bl0,
    const float* __restrict__ bias, float* __restrict__ Cf,
    unsigned short* __restrict__ Chi, unsigned short* __restrict__ Clo,
    int N, int K, int m0, int n0, uint32_t sb)
{
    const int tid = threadIdx.x;
    const int wid = tid >> 5, lane = tid & 31;
    const int wm = wid >> 2, wn = wid & 3;
    const int lr = lane >> 2;
    const int lc = lane & 3;

    const uint32_t a_off =
        (uint32_t)(wm * 64 + (lane & 7) + ((lane >> 3) & 1) * 8) * SPITCH +
        ((lane >> 4) & 1) * 16;
    const uint32_t b_off =
        (uint32_t)(wn * 32 + (lane & 7)) * SPITCH + ((lane >> 3) & 1) * 16;

    float acc[4][4][4];
#pragma unroll
    for (int mt = 0; mt < 4; mt++)
#pragma unroll
        for (int nt = 0; nt < 4; nt++)
#pragma unroll
            for (int r = 0; r < 4; r++) acc[mt][nt][r] = 0.f;

    const int nch = K / GBK;

    g_stage(sb, Ah0, Al0, Bh0, Bl0, K, 0, tid);
    CP_ASYNC_COMMIT();

    for (int i = 0; i < nch; i++) {
        if (i + 1 < nch) {
            g_stage(sb + ((i + 1) & 1) * STAGE_B, Ah0, Al0, Bh0, Bl0, K, i + 1, tid);
            CP_ASYNC_COMMIT();
            CP_ASYNC_WAIT(1);
        } else {
            CP_ASYNC_WAIT(0);
        }
        __syncthreads();

        const uint32_t st = sb + (i & 1) * STAGE_B;

#pragma unroll
        for (int ks = 0; ks < 2; ks++) {
            const uint32_t kbyte = ks * 32;
            uint32_t bh[4][2], bl[4][2];
#pragma unroll
            for (int nt = 0; nt < 4; nt++) {
                uint32_t ad = st + 2 * TILE_B + b_off + nt * 8 * SPITCH + kbyte;
                ldm_x2(bh[nt], ad);
                ldm_x2(bl[nt], ad + TILE_B);
            }
#pragma unroll
            for (int mt = 0; mt < 4; mt++) {
                uint32_t ad = st + a_off + mt * 16 * SPITCH + kbyte;
                uint32_t ah[4], al[4];
                ldm_x4(ah, ad);
                ldm_x4(al, ad + TILE_B);
#pragma unroll
                for (int nt = 0; nt < 4; nt++) {
                    mma_bf16(acc[mt][nt], al, bh[nt]);
                    mma_bf16(acc[mt][nt], ah, bl[nt]);
                    mma_bf16(acc[mt][nt], ah, bh[nt]);
                }
            }
        }
        __syncthreads();
    }

#pragma unroll
    for (int mt = 0; mt < 4; mt++) {
        const int row = m0 + wm * 64 + mt * 16 + lr;
#pragma unroll
        for (int nt = 0; nt < 4; nt++) {
            const int col = n0 + wn * 32 + nt * 8 + 2 * lc;
            float b0 = 0.f, b1 = 0.f;
            if (bias) { b0 = __ldg(bias + col); b1 = __ldg(bias + col + 1); }
            float v0x = acc[mt][nt][0] + b0, v0y = acc[mt][nt][1] + b1;
            float v1x = acc[mt][nt][2] + b0, v1y = acc[mt][nt][3] + b1;
            if (Cf) {
                *(float2*)(Cf + (size_t)row * N + col) = make_float2(v0x, v0y);
                *(float2*)(Cf + (size_t)(row + 8) * N + col) = make_float2(v1x, v1y);
            } else {
                uint32_t h0 = pack_bf16x2(v0x, v0y);
                uint32_t h1 = pack_bf16x2(v1x, v1y);
                *(uint32_t*)&Chi[(size_t)row * N + col] = h0;
                *(uint32_t*)&Clo[(size_t)row * N + col] = lo_of(h0, v0x, v0y);
                *(uint32_t*)&Chi[(size_t)(row + 8) * N + col] = h1;
                *(uint32_t*)&Clo[(size_t)(row + 8) * N + col] = lo_of(h1, v1x, v1y);
            }
        }
    }
}

// generic single-GEMM kernel (wo / wc / we)
__global__ void __launch_bounds__(256, 2) mma_gemm_tn(
    const unsigned short* __restrict__ Ah, const unsigned short* __restrict__ Al,
    const unsigned short* __restrict__ Bh, const unsigned short* __restrict__ Bl,
    const float* __restrict__ bias, float* __restrict__ Cf,
    unsigned short* __restrict__ Chi, unsigned short* __restrict__ Clo,
    int M, int N, int K)
{
    extern __shared__ float smg[];
    const uint32_t sb = smem_u32(smg);
    const int m0 = blockIdx.y * GBM;
    const int n0 = blockIdx.x * GBN;
    gemm_core(Ah + (size_t)m0 * K, Al + (size_t)m0 * K,
              Bh + (size_t)n0 * K, Bl + (size_t)n0 * K,
              bias, Cf, Chi, Clo, N, K, m0, n0, sb);
}

// fused QKV projection: z=0 -> q, z=1 -> k, z=2 -> v (fp32, bx<8 only)
__global__ void __launch_bounds__(256, 2) mma_gemm_qkv(
    const unsigned short* __restrict__ xc,
    const unsigned short* __restrict__ wqc,
    const unsigned short* __restrict__ wkc,
    const unsigned short* __restrict__ wvc,
    unsigned short* __restrict__ qcC, unsigned short* __restrict__ kcC,
    float* __restrict__ vf)
{
    extern __shared__ float smg[];
    const uint32_t sb = smem_u32(smg);
    const int z = blockIdx.z;
    if (z == 2 && blockIdx.x >= 8) return;
    const int m0 = blockIdx.y * GBM;
    const int n0 = blockIdx.x * GBN;
    const int K = CC;

    const unsigned short *Bh, *Bl;
    unsigned short *Chi = nullptr, *Clo = nullptr;
    float* Cf = nullptr;
    int N;
    if (z == 0) {
        Bh = wqc; Bl = wqc + NQKc; Chi = qcC; Clo = qcC + NQ2c; N = 2 * CC;
    } else if (z == 1) {
        Bh = wkc; Bl = wkc + NQKc; Chi = kcC; Clo = kcC + NQ2c; N = 2 * CC;
    } else {
        Bh = wvc; Bl = wvc + NSQc; Cf = vf; N = CC;
    }
    gemm_core(xc + (size_t)m0 * K, xc + NXc + (size_t)m0 * K,
              Bh + (size_t)n0 * K, Bl + (size_t)n0 * K,
              nullptr, Cf, Chi, Clo, N, K, m0, n0, sb);
}

// ---------------------------------------------------------------------------
// Lambda scalar
// ---------------------------------------------------------------------------
__global__ void lambda_kernel(const float* __restrict__ lq1, const float* __restrict__ lk1,
                              const float* __restrict__ lq2, const float* __restrict__ lk2)
{
    if (threadIdx.x == 0) {
        float s1 = 0.f, s2 = 0.f;
        for (int i = 0; i < HH; i++) {
            s1 = fmaf(lq1[i], lk1[i], s1);
            s2 = fmaf(lq2[i], lk2[i], s2);
        }
        double li = 0.8 - 0.6 * exp(-0.3 * 11.0);  // N_LAYER=12
        g_lambda = (float)(exp((double)s1) - exp((double)s2) + li);
    }
}

// ---------------------------------------------------------------------------
// Differential flash attention (R12 structure), R13: epilogue emits hi/lo bf16
// directly (drops the conv(y) round-trip).
// ---------------------------------------------------------------------------
#define FBP 144
#define FTILE (64 * FBP)
#define APAD 68
#define VPAD 72
#define OFF_K   (4 * FTILE)
#define OFF_V   (12 * FTILE)
#define VBYTES  (64 * VPAD * 4)
#define OFF_PS  (OFF_V + 2 * VBYTES)
#define PSBYTES (64 * APAD * 4)
#define FLASH_SMEM (OFF_PS + 2 * PSBYTES)      // 182272

__device__ __forceinline__ void lda_frag(const float* S, int row0, int k0,
                                         int lr, int lc, uint32_t a[4]) {
    a[0] = f2tf32(S[(row0 + lr) * APAD + k0 + lc]);
    a[1] = f2tf32(S[(row0 + lr + 8) * APAD + k0 + lc]);
    a[2] = f2tf32(S[(row0 + lr) * APAD + k0 + 4 + lc]);
    a[3] = f2tf32(S[(row0 + lr + 8) * APAD + k0 + 4 + lc]);
}
__device__ __forceinline__ void ldbV_frag(const float* Vs, int n0, int k0,
                                          int lr, int lc, uint32_t b[2]) {
    b[0] = f2tf32(Vs[(k0 + lc) * VPAD + n0 + lr]);
    b[1] = f2tf32(Vs[(k0 + 4 + lc) * VPAD + n0 + lr]);
}

__global__ __launch_bounds__(256) void flash_diff_par(
    const unsigned short* __restrict__ qc, const unsigned short* __restrict__ kc,
    const float* __restrict__ vb,
    unsigned short* __restrict__ yh, unsigned short* __restrict__ yl)
{
    extern __shared__ char smc[];
    const uint32_t sb = smem_u32(smc);

    const int tid = threadIdx.x;
    const int wid = tid >> 5, lane = tid & 31;
    const int g = wid >> 2;              // branch group: 0 -> att1, 1 -> att2
    const int wg = wid & 3;              // warp-in-group
    const int lr = lane >> 2, lc = lane & 3;
    const int qi = blockIdx.x, h = blockIdx.y, b = blockIdx.z;
    const int q0 = qi * 64;
    const int rl0 = wg * 16 + lr;

    const size_t NQ2 = NQ2c;
    const size_t brow = (size_t)b * TT;

    const uint32_t arow =
        (uint32_t)(wg * 16 + (lane & 7) + ((lane >> 3) & 1) * 8) * FBP +
        ((lane >> 4) & 1) * 16;
    const uint32_t boff =
        (uint32_t)(lane & 7) * FBP + ((lane >> 3) & 1) * 16;

    // ---- stage Q + K/V for kt=0 ----
#pragma unroll
    for (int t = 0; t < 8; t++) {
        int idx = tid + t * 256;
        int tile = idx >> 9;
        int c = idx & 511;
        int row = c >> 3, seg = c & 7;
        int br = tile >> 1, hl = tile & 1;
        cp_async16(sb + tile * FTILE + row * FBP + seg * 16,
                   qc + (size_t)hl * NQ2 + (brow + q0 + row) * (2 * CC) +
                       br * CC + h * DHD + seg * 8);
    }
#pragma unroll
    for (int t = 0; t < 8; t++) {
        int idx = tid + t * 256;
        int tile = idx >> 9;
        int c = idx & 511;
        int row = c >> 3, seg = c & 7;
        int br = tile >> 1, hl = tile & 1;
        cp_async16(sb + OFF_K + tile * FTILE + row * FBP + seg * 16,
                   kc + (size_t)hl * NQ2 + (brow + row) * (2 * CC) +
                       br * CC + h * DHD + seg * 8);
    }
#pragma unroll
    for (int t = 0; t < 4; t++) {
        int idx = tid + t * 256;
        int row = idx >> 4, sg = idx & 15;
        cp_async16(sb + OFF_V + row * (VPAD * 4) + sg * 16,
                   vb + (brow + row) * CC + h * DHD + sg * 4);
    }
    CP_ASYNC_COMMIT();

    float s[8][4], acc[8][4];
#pragma unroll
    for (int nt = 0; nt < 8; nt++)
#pragma unroll
        for (int r = 0; r < 4; r++) acc[nt][r] = 0.f;
    float m0 = -1e30f, m1 = -1e30f, l0 = 0.f, l1 = 0.f;

    for (int kt = 0; kt <= qi; kt++) {
        const int buf = kt & 1;
        if (kt < qi) {
            const int k0n = (kt + 1) * 64;
            const int nb = 1 - buf;
#pragma unroll
            for (int t = 0; t < 8; t++) {
                int idx = tid + t * 256;
                int tile = idx >> 9;
                int c = idx & 511;
                int row = c >> 3, seg = c & 7;
                int br = tile >> 1, hl = tile & 1;
                cp_async16(sb + OFF_K + (nb * 4 + tile) * FTILE + row * FBP + seg * 16,
                           kc + (size_t)hl * NQ2 + (brow + k0n + row) * (2 * CC) +
                               br * CC + h * DHD + seg * 8);
            }
#pragma unroll
            for (int t = 0; t < 4; t++) {
                int idx = tid + t * 256;
                int row = idx >> 4, sg = idx & 15;
                cp_async16(sb + OFF_V + nb * VBYTES + row * (VPAD * 4) + sg * 16,
                           vb + (brow + k0n + row) * CC + h * DHD + sg * 4);
            }
            CP_ASYNC_COMMIT();
            CP_ASYNC_WAIT(1);
        } else {
            CP_ASYNC_WAIT(0);
        }
        __syncthreads();

        const bool diag = (kt == qi);
        const uint32_t qh = sb + (g * 2) * FTILE;
        const uint32_t ql = qh + FTILE;
        const uint32_t kh = sb + OFF_K + (buf * 4 + g * 2) * FTILE;
        const uint32_t kl = kh + FTILE;
        const float* Vs = (const float*)(smc + OFF_V + buf * VBYTES);
        float* Ps = (float*)(smc + OFF_PS + g * PSBYTES);

        // ---- S = Q @ K^T (bf16x3) ----
#pragma unroll
        for (int nt = 0; nt < 8; nt++)
#pragma unroll
            for (int r = 0; r < 4; r++) s[nt][r] = 0.f;
#pragma unroll
        for (int ks = 0; ks < 4; ks++) {
            uint32_t ah[4], al[4];
            ldm_x4(ah, qh + arow + ks * 32);
            ldm_x4(al, ql + arow + ks * 32);
#pragma unroll
            for (int nt = 0; nt < 8; nt++) {
                uint32_t bh[2], bl[2];
                uint32_t ad = boff + nt * 8 * FBP + ks * 32;
                ldm_x2(bh, kh + ad);
                ldm_x2(bl, kl + ad);
                mma_bf16(s[nt], al, bh);
                mma_bf16(s[nt], ah, bl);
                mma_bf16(s[nt], ah, bh);
            }
        }

        const float scale = 0.125f;
        const int r0 = rl0, r1 = rl0 + 8;
#pragma unroll
        for (int nt = 0; nt < 8; nt++) {
            const int c0 = nt * 8 + 2 * lc;
            s[nt][0] *= scale; s[nt][1] *= scale;
            s[nt][2] *= scale; s[nt][3] *= scale;
            if (diag) {
                if (c0 > r0)     s[nt][0] = -1e30f;
                if (c0 + 1 > r0) s[nt][1] = -1e30f;
                if (c0 > r1)     s[nt][2] = -1e30f;
                if (c0 + 1 > r1) s[nt][3] = -1e30f;
            }
        }

        float mx0 = -1e30f, mx1 = -1e30f;
#pragma unroll
        for (int nt = 0; nt < 8; nt++) {
            mx0 = fmaxf(mx0, fmaxf(s[nt][0], s[nt][1]));
            mx1 = fmaxf(mx1, fmaxf(s[nt][2], s[nt][3]));
        }
        mx0 = fmaxf(mx0, __shfl_xor_sync(0xffffffffu, mx0, 1));
        mx0 = fmaxf(mx0, __shfl_xor_sync(0xffffffffu, mx0, 2));
        mx1 = fmaxf(mx1, __shfl_xor_sync(0xffffffffu, mx1, 1));
        mx1 = fmaxf(mx1, __shfl_xor_sync(0xffffffffu, mx1, 2));

        const float mn0 = fmaxf(m0, mx0);
        const float mn1 = fmaxf(m1, mx1);
        const float cr0 = __expf(m0 - mn0);
        const float cr1 = __expf(m1 - mn1);

        __syncwarp();
        float ps0 = 0.f, ps1 = 0.f;
#pragma unroll
        for (int nt = 0; nt < 8; nt++) {
            const int cl = nt * 8 + 2 * lc;
            float p0 = __expf(s[nt][0] - mn0);
            float p1 = __expf(s[nt][1] - mn0);
            float p2 = __expf(s[nt][2] - mn1);
            float p3 = __expf(s[nt][3] - mn1);
            ps0 += p0 + p1;
            ps1 += p2 + p3;
            *(float2*)&Ps[r0 * APAD + cl] = make_float2(p0, p1);
            *(float2*)&Ps[r1 * APAD + cl] = make_float2(p2, p3);
        }
        ps0 += __shfl_xor_sync(0xffffffffu, ps0, 1);
        ps0 += __shfl_xor_sync(0xffffffffu, ps0, 2);
        ps1 += __shfl_xor_sync(0xffffffffu, ps1, 1);
        ps1 += __shfl_xor_sync(0xffffffffu, ps1, 2);

        l0 = l0 * cr0 + ps0;
        l1 = l1 * cr1 + ps1;
        m0 = mn0; m1 = mn1;

#pragma unroll
        for (int nt = 0; nt < 8; nt++) {
            acc[nt][0] *= cr0; acc[nt][1] *= cr0;
            acc[nt][2] *= cr1; acc[nt][3] *= cr1;
        }
        __syncwarp();

#pragma unroll
        for (int k0 = 0; k0 < 64; k0 += 8) {
            uint32_t a[4];
            lda_frag(Ps, wg * 16, k0, lr, lc, a);
#pragma unroll
            for (int nt = 0; nt < 8; nt++) {
                uint32_t bv[2];
                ldbV_frag(Vs, nt * 8, k0, lr, lc, bv);
                mma_tf32(acc[nt], a, bv);
            }
        }
        __syncthreads();
    }

    // ---- epilogue: combine branches; emit hi/lo bf16 y ----
    float* Eps = (float*)(smc + OFF_PS);
    const float lam = g_lambda;
    if (g == 1) {
        const float i0 = lam / l0, i1 = lam / l1;
        const int r0 = rl0, r1 = rl0 + 8;
#pragma unroll
        for (int nt = 0; nt < 8; nt++) {
            const int cl = nt * 8 + 2 * lc;
            *(float2*)&Eps[r0 * APAD + cl] =
                make_float2(acc[nt][0] * i0, acc[nt][1] * i0);
            *(float2*)&Eps[r1 * APAD + cl] =
                make_float2(acc[nt][2] * i1, acc[nt][3] * i1);
        }
    }
    __syncthreads();
    if (g == 0) {
        const float i0 = 1.f / l0, i1 = 1.f / l1;
        const int r0g = q0 + rl0, r1g = r0g + 8;
#pragma unroll
        for (int nt = 0; nt < 8; nt++) {
            const int cl = nt * 8 + 2 * lc;
            const int col = h * DHD + cl;
            float2 e0 = *(float2*)&Eps[rl0 * APAD + cl];
            float2 e1 = *(float2*)&Eps[(rl0 + 8) * APAD + cl];
            float o0x = acc[nt][0] * i0 - e0.x;
            float o0y = acc[nt][1] * i0 - e0.y;
            float o1x = acc[nt][2] * i1 - e1.x;
            float o1y = acc[nt][3] * i1 - e1.y;
            size_t a0 = (brow + r0g) * CC + col;
            size_t a1 = (brow + r1g) * CC + col;
            uint32_t h0 = pack_bf16x2(o0x, o0y);
            uint32_t h1 = pack_bf16x2(o1x, o1y);
            *(uint32_t*)&yh[a0] = h0;
            *(uint32_t*)&yl[a0] = lo_of(h0, o0x, o0y);
            *(uint32_t*)&yh[a1] = h1;
            *(uint32_t*)&yl[a1] = lo_of(h1, o1x, o1y);
        }
    }
}

// ---------------------------------------------------------------------------
// Launch. ncu fixed slot (launch index 3) = fused QKV GEMM.
// ---------------------------------------------------------------------------
static inline void conv(const float* src, unsigned short* dst, size_t n) {
    int n4 = (int)(n / 4);
    int blocks = (n4 + 255) / 256;
    if (blocks > 4096) blocks = 4096;
    convert_hilo<<<blocks, 256>>>((const float4*)src, (uint2*)dst,
                                  (uint2*)(dst + n), n4);
}

extern "C" void kernel_launch(void* const* d_in, const int* in_sizes, int n_in,
                              void* d_out, int out_size)
{
    const float* x   = (const float*)d_in[0];
    const float* wq  = (const float*)d_in[1];
    const float* wk  = (const float*)d_in[2];
    const float* wv  = (const float*)d_in[3];
    const float* wo  = (const float*)d_in[4];
    const float* lq1 = (const float*)d_in[5];
    const float* lk1 = (const float*)d_in[6];
    const float* lq2 = (const float*)d_in[7];
    const float* lk2 = (const float*)d_in[8];
    const float* wc  = (const float*)d_in[9];
    const float* bc  = (const float*)d_in[10];
    const float* we  = (const float*)d_in[11];
    const float* be  = (const float*)d_in[12];

    float* v;
    cudaGetSymbolAddress((void**)&v, g_v);

    unsigned short *xc, *wqc, *wkc, *wvc, *woc, *wcc, *wec;
    unsigned short *qc, *kc, *yc, *y2c, *hc;
    cudaGetSymbolAddress((void**)&xc,  g_xc);
    cudaGetSymbolAddress((void**)&wqc, g_wqc);
    cudaGetSymbolAddress((void**)&wkc, g_wkc);
    cudaGetSymbolAddress((void**)&wvc, g_wvc);
    cudaGetSymbolAddress((void**)&woc, g_woc);
    cudaGetSymbolAddress((void**)&wcc, g_wcc);
    cudaGetSymbolAddress((void**)&wec, g_wec);
    cudaGetSymbolAddress((void**)&qc,  g_qc);
    cudaGetSymbolAddress((void**)&kc,  g_kc);
    cudaGetSymbolAddress((void**)&yc,  g_yc);
    cudaGetSymbolAddress((void**)&y2c, g_y2c);
    cudaGetSymbolAddress((void**)&hc,  g_hc);

    cudaFuncSetAttribute(mma_gemm_tn, cudaFuncAttributeMaxDynamicSharedMemorySize,
                         GEMM_SMEM);
    cudaFuncSetAttribute(mma_gemm_qkv, cudaFuncAttributeMaxDynamicSharedMemorySize,
                         GEMM_SMEM);
    cudaFuncSetAttribute(flash_diff_par, cudaFuncAttributeMaxDynamicSharedMemorySize,
                         FLASH_SMEM);

    const size_t NX  = NXc;
    const size_t NQK = NQKc;
    const size_t NSQ = NSQc;
    const size_t NHC = (size_t)(CC / 2) * CC;
    const size_t NH  = (size_t)MT * (CC / 2);

    dim3 blk(256);
    conv(x, xc, NX);                                                       // 0
    {   // 1: wq + wk in one dual-source launch
        int n4 = (int)(NQK / 4);
        int blocks = (n4 + 255) / 256;
        if (blocks > 2048) blocks = 2048;
        convert_hilo2<<<dim3(blocks, 1, 2), blk>>>(
            (const float4*)wq, (uint2*)wqc, (uint2*)(wqc + NQK),
            (const float4*)wk, (uint2*)wkc, (uint2*)(wkc + NQK), n4);
    }
    conv(wv, wvc, NSQ);                                                    // 2
    mma_gemm_qkv<<<dim3(2 * CC / 128, MT / 128, 3), blk, GEMM_SMEM>>>(     // 3 (ncu)
        xc, wqc, wkc, wvc, qc, kc, v);
    lambda_kernel<<<1, 32>>>(lq1, lk1, lq2, lk2);                          // 4
    flash_diff_par<<<dim3(TT / 64, HH, BB), blk, FLASH_SMEM>>>(            // 5
        qc, kc, v, yc, yc + NX);
    conv(wo, woc, NSQ);                                                    // 6
    mma_gemm_tn<<<dim3(CC / 128, MT / 128), blk, GEMM_SMEM>>>(             // 7: y2 bf16
        yc, yc + NX, woc, woc + NSQ, nullptr, nullptr, y2c, y2c + NX,
        MT, CC, CC);
    conv(wc, wcc, NHC);                                                    // 8
    mma_gemm_tn<<<dim3(CC / 2 / 128, MT / 128), blk, GEMM_SMEM>>>(         // 9: h bf16
        y2c, y2c + NX, wcc, wcc + NHC, bc, nullptr, hc, hc + NH,
        MT, CC / 2, CC);
    conv(we, wec, NHC);                                                    // 10
    mma_gemm_tn<<<dim3(CC / 128, MT / 128), blk, GEMM_SMEM>>>(             // 11: out fp32
        hc, hc + NH, wec, wec + NHC, be, (float*)d_out, nullptr, nullptr,
        MT, CC, CC / 2);
}

// round 14
// speedup vs baseline: 3.1325x; 1.0353x over previous
#include <cuda_runtime.h>
#include <math.h>
#include <stdint.h>

// Problem constants
#define BB 2
#define TT 2048
#define CC 1024
#define HH 16
#define DHD 64
#define MT (BB * TT)          // 4096 rows

#define NXc  ((size_t)MT * CC)            // 4M
#define NQ2c ((size_t)MT * 2 * CC)        // 8M
#define NQKc ((size_t)2 * CC * CC)        // 2M
#define NSQc ((size_t)CC * CC)            // 1M
#define NHCc ((size_t)(CC / 2) * CC)      // 0.5M
#define NHc  ((size_t)MT * (CC / 2))      // 2M

// ---------------------------------------------------------------------------
// Scratch (device globals)
// ---------------------------------------------------------------------------
__device__ float g_lambda;
__device__ float g_v[MT * CC];          // tf32-rounded fp32 V

// hi/lo bf16 pairs (hi at [0], lo at [elem_count])
__device__ unsigned short g_xc [2ul * MT * CC];
__device__ unsigned short g_wqc[2ul * 2 * CC * CC];
__device__ unsigned short g_wkc[2ul * 2 * CC * CC];
__device__ unsigned short g_wvc[2ul * CC * CC];
__device__ unsigned short g_woc[2ul * CC * CC];
__device__ unsigned short g_wcc[2ul * (CC / 2) * CC];
__device__ unsigned short g_wec[2ul * CC * (CC / 2)];
__device__ unsigned short g_qc [2ul * MT * 2 * CC];
__device__ unsigned short g_kc [2ul * MT * 2 * CC];
__device__ unsigned short g_yc [2ul * MT * CC];
__device__ unsigned short g_y2c[2ul * MT * CC];
__device__ unsigned short g_hc [2ul * MT * (CC / 2)];

// ---------------------------------------------------------------------------
// PTX helpers (compute_100-legal)
// ---------------------------------------------------------------------------
__device__ __forceinline__ uint32_t smem_u32(const void* p) {
    uint32_t a;
    asm("{ .reg .u64 t; cvta.to.shared.u64 t, %1; cvt.u32.u64 %0, t; }"
        : "=r"(a) : "l"(p));
    return a;
}

__device__ __forceinline__ void cp_async16(uint32_t dst, const void* src) {
    asm volatile("cp.async.ca.shared.global [%0], [%1], 16;"
                 :: "r"(dst), "l"(src) : "memory");
}
#define CP_ASYNC_COMMIT() asm volatile("cp.async.commit_group;" ::: "memory")
#define CP_ASYNC_WAIT(n)  asm volatile("cp.async.wait_group %0;" :: "n"(n) : "memory")

__device__ __forceinline__ uint32_t f2tf32(float f) {
    uint32_t r;
    asm("cvt.rna.tf32.f32 %0, %1;" : "=r"(r) : "f"(f));
    return r;
}

// tf32 m16n8k8 (P@V in attention)
__device__ __forceinline__ void mma_tf32(float* d, const uint32_t* a, const uint32_t* b) {
    asm volatile(
        "mma.sync.aligned.m16n8k8.row.col.f32.tf32.tf32.f32 "
        "{%0,%1,%2,%3}, {%4,%5,%6,%7}, {%8,%9}, {%0,%1,%2,%3};"
        : "+f"(d[0]), "+f"(d[1]), "+f"(d[2]), "+f"(d[3])
        : "r"(a[0]), "r"(a[1]), "r"(a[2]), "r"(a[3]), "r"(b[0]), "r"(b[1]));
}

// bf16 m16n8k16 (GEMMs + S=QK^T)
__device__ __forceinline__ void mma_bf16(float* d, const uint32_t* a, const uint32_t* b) {
    asm volatile(
        "mma.sync.aligned.m16n8k16.row.col.f32.bf16.bf16.f32 "
        "{%0,%1,%2,%3}, {%4,%5,%6,%7}, {%8,%9}, {%0,%1,%2,%3};"
        : "+f"(d[0]), "+f"(d[1]), "+f"(d[2]), "+f"(d[3])
        : "r"(a[0]), "r"(a[1]), "r"(a[2]), "r"(a[3]), "r"(b[0]), "r"(b[1]));
}

__device__ __forceinline__ void ldm_x4(uint32_t* r, uint32_t addr) {
    asm volatile("ldmatrix.sync.aligned.m8n8.x4.shared.b16 {%0,%1,%2,%3}, [%4];"
        : "=r"(r[0]), "=r"(r[1]), "=r"(r[2]), "=r"(r[3]) : "r"(addr));
}

__device__ __forceinline__ uint32_t pack_bf16x2(float e0, float e1) {
    uint32_t r;
    asm("cvt.rn.bf16x2.f32 %0, %1, %2;" : "=r"(r) : "f"(e1), "f"(e0));
    return r;
}
__device__ __forceinline__ uint32_t lo_of(uint32_t h, float x0, float x1) {
    return pack_bf16x2(x0 - __uint_as_float(h << 16),
                       x1 - __uint_as_float(h & 0xffff0000u));
}

// ---------------------------------------------------------------------------
// All input conversions in ONE launch: grid.z selects the segment.
// ---------------------------------------------------------------------------
struct ConvSeg { const float4* src; uint2* hi; uint2* lo; int n4; };

__global__ __launch_bounds__(256) void convert_all(
    const float4* s0, uint2* h0, uint2* l0, int n0,
    const float4* s1, uint2* h1, uint2* l1, int n1,
    const float4* s2, uint2* h2, uint2* l2, int n2,
    const float4* s3, uint2* h3, uint2* l3, int n3,
    const float4* s4, uint2* h4, uint2* l4, int n4_,
    const float4* s5, uint2* h5, uint2* l5, int n5,
    const float4* s6, uint2* h6, uint2* l6, int n6)
{
    const float4* src; uint2* hi; uint2* lo; int n;
    switch (blockIdx.z) {
        case 0: src = s0; hi = h0; lo = l0; n = n0; break;
        case 1: src = s1; hi = h1; lo = l1; n = n1; break;
        case 2: src = s2; hi = h2; lo = l2; n = n2; break;
        case 3: src = s3; hi = h3; lo = l3; n = n3; break;
        case 4: src = s4; hi = h4; lo = l4; n = n4_; break;
        case 5: src = s5; hi = h5; lo = l5; n = n5; break;
        default: src = s6; hi = h6; lo = l6; n = n6; break;
    }
    for (int i = blockIdx.x * blockDim.x + threadIdx.x; i < n;
         i += gridDim.x * blockDim.x) {
        float4 v = src[i];
        uint32_t hh0 = pack_bf16x2(v.x, v.y);
        uint32_t hh1 = pack_bf16x2(v.z, v.w);
        hi[i] = make_uint2(hh0, hh1);
        lo[i] = make_uint2(lo_of(hh0, v.x, v.y), lo_of(hh1, v.z, v.w));
    }
}

// ---------------------------------------------------------------------------
// bf16x3 GEMM core (R8/R11-proven; B-fragments now via paired ldm_x4).
// ---------------------------------------------------------------------------
#define GBM 128
#define GBN 128
#define GBK 32
#define SPITCH 80
#define TILE_B (128 * SPITCH)
#define STAGE_B (4 * TILE_B)
#define GEMM_SMEM (2 * STAGE_B)         // 81920 B

__device__ __forceinline__ void g_stage(
    uint32_t sbuf,
    const unsigned short* __restrict__ Ah, const unsigned short* __restrict__ Al,
    const unsigned short* __restrict__ Bh, const unsigned short* __restrict__ Bl,
    int K, int kc, int tid)
{
    const unsigned short* srcs[4] = {Ah, Al, Bh, Bl};
#pragma unroll
    for (int j = 0; j < 8; j++) {
        const int tile = j >> 1;
        const int idx = (j & 1) * 256 + tid;
        const int m = idx >> 2, seg = idx & 3;
        uint32_t dst = sbuf + tile * TILE_B + m * SPITCH + seg * 16;
        cp_async16(dst, srcs[tile] + (size_t)m * K + kc * GBK + seg * 8);
    }
}

__device__ __forceinline__ void gemm_core(
    const unsigned short* __restrict__ Ah0, const unsigned short* __restrict__ Al0,
    const unsigned short* __restrict__ Bh0, const unsigned short* __restrict__ Bl0,
    const float* __restrict__ bias, float* __restrict__ Cf, int cf_tf32,
    unsigned short* __restrict__ Chi, unsigned short* __restrict__ Clo,
    int N, int K, int m0, int n0, uint32_t sb)
{
    const int tid = threadIdx.x;
    const int wid = tid >> 5, lane = tid & 31;
    const int wm = wid >> 2, wn = wid & 3;
    const int lr = lane >> 2;
    const int lc = lane & 3;

    const uint32_t a_off =
        (uint32_t)(wm * 64 + (lane & 7) + ((lane >> 3) & 1) * 8) * SPITCH +
        ((lane >> 4) & 1) * 16;
    // paired-x4 B offset: rows {base..+7, +8..+15} x k-halves via thread groups
    const uint32_t b4_off =
        (uint32_t)(wn * 32 + (lane & 7) + ((lane >> 4) & 1) * 8) * SPITCH +
        ((lane >> 3) & 1) * 16;

    float acc[4][4][4];
#pragma unroll
    for (int mt = 0; mt < 4; mt++)
#pragma unroll
        for (int nt = 0; nt < 4; nt++)
#pragma unroll
            for (int r = 0; r < 4; r++) acc[mt][nt][r] = 0.f;

    const int nch = K / GBK;

    g_stage(sb, Ah0, Al0, Bh0, Bl0, K, 0, tid);
    CP_ASYNC_COMMIT();

    for (int i = 0; i < nch; i++) {
        if (i + 1 < nch) {
            g_stage(sb + ((i + 1) & 1) * STAGE_B, Ah0, Al0, Bh0, Bl0, K, i + 1, tid);
            CP_ASYNC_COMMIT();
            CP_ASYNC_WAIT(1);
        } else {
            CP_ASYNC_WAIT(0);
        }
        __syncthreads();

        const uint32_t st = sb + (i & 1) * STAGE_B;

#pragma unroll
        for (int ks = 0; ks < 2; ks++) {
            const uint32_t kbyte = ks * 32;
            uint32_t bh[4][2], bl[4][2];
#pragma unroll
            for (int np = 0; np < 2; np++) {
                uint32_t ad = st + 2 * TILE_B + b4_off + np * 16 * SPITCH + kbyte;
                uint32_t r4[4];
                ldm_x4(r4, ad);
                bh[2 * np][0] = r4[0]; bh[2 * np][1] = r4[1];
                bh[2 * np + 1][0] = r4[2]; bh[2 * np + 1][1] = r4[3];
                ldm_x4(r4, ad + TILE_B);
                bl[2 * np][0] = r4[0]; bl[2 * np][1] = r4[1];
                bl[2 * np + 1][0] = r4[2]; bl[2 * np + 1][1] = r4[3];
            }
#pragma unroll
            for (int mt = 0; mt < 4; mt++) {
                uint32_t ad = st + a_off + mt * 16 * SPITCH + kbyte;
                uint32_t ah[4], al[4];
                ldm_x4(ah, ad);
                ldm_x4(al, ad + TILE_B);
#pragma unroll
                for (int nt = 0; nt < 4; nt++) {
                    mma_bf16(acc[mt][nt], al, bh[nt]);
                    mma_bf16(acc[mt][nt], ah, bl[nt]);
                    mma_bf16(acc[mt][nt], ah, bh[nt]);
                }
            }
        }
        __syncthreads();
    }

#pragma unroll
    for (int mt = 0; mt < 4; mt++) {
        const int row = m0 + wm * 64 + mt * 16 + lr;
#pragma unroll
        for (int nt = 0; nt < 4; nt++) {
            const int col = n0 + wn * 32 + nt * 8 + 2 * lc;
            float b0 = 0.f, b1 = 0.f;
            if (bias) { b0 = __ldg(bias + col); b1 = __ldg(bias + col + 1); }
            float v0x = acc[mt][nt][0] + b0, v0y = acc[mt][nt][1] + b1;
            float v1x = acc[mt][nt][2] + b0, v1y = acc[mt][nt][3] + b1;
            if (Cf) {
                if (cf_tf32) {
                    v0x = __uint_as_float(f2tf32(v0x));
                    v0y = __uint_as_float(f2tf32(v0y));
                    v1x = __uint_as_float(f2tf32(v1x));
                    v1y = __uint_as_float(f2tf32(v1y));
                }
                *(float2*)(Cf + (size_t)row * N + col) = make_float2(v0x, v0y);
                *(float2*)(Cf + (size_t)(row + 8) * N + col) = make_float2(v1x, v1y);
            } else {
                uint32_t h0 = pack_bf16x2(v0x, v0y);
                uint32_t h1 = pack_bf16x2(v1x, v1y);
                *(uint32_t*)&Chi[(size_t)row * N + col] = h0;
                *(uint32_t*)&Clo[(size_t)row * N + col] = lo_of(h0, v0x, v0y);
                *(uint32_t*)&Chi[(size_t)(row + 8) * N + col] = h1;
                *(uint32_t*)&Clo[(size_t)(row + 8) * N + col] = lo_of(h1, v1x, v1y);
            }
        }
    }
}

// generic single-GEMM kernel (wo / wc / we)
__global__ void __launch_bounds__(256, 2) mma_gemm_tn(
    const unsigned short* __restrict__ Ah, const unsigned short* __restrict__ Al,
    const unsigned short* __restrict__ Bh, const unsigned short* __restrict__ Bl,
    const float* __restrict__ bias, float* __restrict__ Cf,
    unsigned short* __restrict__ Chi, unsigned short* __restrict__ Clo,
    int M, int N, int K)
{
    extern __shared__ float smg[];
    const uint32_t sb = smem_u32(smg);
    const int m0 = blockIdx.y * GBM;
    const int n0 = blockIdx.x * GBN;
    gemm_core(Ah + (size_t)m0 * K, Al + (size_t)m0 * K,
              Bh + (size_t)n0 * K, Bl + (size_t)n0 * K,
              bias, Cf, 0, Chi, Clo, N, K, m0, n0, sb);
}

// fused QKV projection: z=0 -> q, z=1 -> k, z=2 -> v (tf32-rounded fp32)
__global__ void __launch_bounds__(256, 2) mma_gemm_qkv(
    const unsigned short* __restrict__ xc,
    const unsigned short* __restrict__ wqc,
    const unsigned short* __restrict__ wkc,
    const unsigned short* __restrict__ wvc,
    unsigned short* __restrict__ qcC, unsigned short* __restrict__ kcC,
    float* __restrict__ vf)
{
    extern __shared__ float smg[];
    const uint32_t sb = smem_u32(smg);
    const int z = blockIdx.z;
    if (z == 2 && blockIdx.x >= 8) return;
    const int m0 = blockIdx.y * GBM;
    const int n0 = blockIdx.x * GBN;
    const int K = CC;

    const unsigned short *Bh, *Bl;
    unsigned short *Chi = nullptr, *Clo = nullptr;
    float* Cf = nullptr;
    int N, cfr = 0;
    if (z == 0) {
        Bh = wqc; Bl = wqc + NQKc; Chi = qcC; Clo = qcC + NQ2c; N = 2 * CC;
    } else if (z == 1) {
        Bh = wkc; Bl = wkc + NQKc; Chi = kcC; Clo = kcC + NQ2c; N = 2 * CC;
    } else {
        Bh = wvc; Bl = wvc + NSQc; Cf = vf; N = CC; cfr = 1;
    }
    gemm_core(xc + (size_t)m0 * K, xc + NXc + (size_t)m0 * K,
              Bh + (size_t)n0 * K, Bl + (size_t)n0 * K,
              nullptr, Cf, cfr, Chi, Clo, N, K, m0, n0, sb);
}

// ---------------------------------------------------------------------------
// Lambda scalar
// ---------------------------------------------------------------------------
__global__ void lambda_kernel(const float* __restrict__ lq1, const float* __restrict__ lk1,
                              const float* __restrict__ lq2, const float* __restrict__ lk2)
{
    if (threadIdx.x == 0) {
        float s1 = 0.f, s2 = 0.f;
        for (int i = 0; i < HH; i++) {
            s1 = fmaf(lq1[i], lk1[i], s1);
            s2 = fmaf(lq2[i], lk2[i], s2);
        }
        double li = 0.8 - 0.6 * exp(-0.3 * 11.0);  // N_LAYER=12
        g_lambda = (float)(exp((double)s1) - exp((double)s2) + li);
    }
}

// ---------------------------------------------------------------------------
// Differential flash attention (R12/R13 structure).
// R14: B-fragments for S via paired ldm_x4; P stored tf32-pre-rounded;
//      V arrives tf32-pre-rounded -> P@V fragment loads are plain LDS.
// ---------------------------------------------------------------------------
#define FBP 144
#define FTILE (64 * FBP)
#define APAD 68
#define VPAD 72
#define OFF_K   (4 * FTILE)
#define OFF_V   (12 * FTILE)
#define VBYTES  (64 * VPAD * 4)
#define OFF_PS  (OFF_V + 2 * VBYTES)
#define PSBYTES (64 * APAD * 4)
#define FLASH_SMEM (OFF_PS + 2 * PSBYTES)      // 182272

__device__ __forceinline__ void lda_frag_raw(const float* S, int row0, int k0,
                                             int lr, int lc, uint32_t a[4]) {
    a[0] = __float_as_uint(S[(row0 + lr) * APAD + k0 + lc]);
    a[1] = __float_as_uint(S[(row0 + lr + 8) * APAD + k0 + lc]);
    a[2] = __float_as_uint(S[(row0 + lr) * APAD + k0 + 4 + lc]);
    a[3] = __float_as_uint(S[(row0 + lr + 8) * APAD + k0 + 4 + lc]);
}
__device__ __forceinline__ void ldbV_raw(const float* Vs, int n0, int k0,
                                         int lr, int lc, uint32_t b[2]) {
    b[0] = __float_as_uint(Vs[(k0 + lc) * VPAD + n0 + lr]);
    b[1] = __float_as_uint(Vs[(k0 + 4 + lc) * VPAD + n0 + lr]);
}

__global__ __launch_bounds__(256) void flash_diff_par(
    const unsigned short* __restrict__ qc, const unsigned short* __restrict__ kc,
    const float* __restrict__ vb,
    unsigned short* __restrict__ yh, unsigned short* __restrict__ yl)
{
    extern __shared__ char smc[];
    const uint32_t sb = smem_u32(smc);

    const int tid = threadIdx.x;
    const int wid = tid >> 5, lane = tid & 31;
    const int g = wid >> 2;              // branch group: 0 -> att1, 1 -> att2
    const int wg = wid & 3;              // warp-in-group
    const int lr = lane >> 2, lc = lane & 3;
    const int qi = blockIdx.x, h = blockIdx.y, b = blockIdx.z;
    const int q0 = qi * 64;
    const int rl0 = wg * 16 + lr;

    const size_t NQ2 = NQ2c;
    const size_t brow = (size_t)b * TT;

    const uint32_t arow =
        (uint32_t)(wg * 16 + (lane & 7) + ((lane >> 3) & 1) * 8) * FBP +
        ((lane >> 4) & 1) * 16;
    // paired-x4 B offset for K tiles
    const uint32_t b4off =
        (uint32_t)((lane & 7) + ((lane >> 4) & 1) * 8) * FBP +
        ((lane >> 3) & 1) * 16;

    // ---- stage Q + K/V for kt=0 ----
#pragma unroll
    for (int t = 0; t < 8; t++) {
        int idx = tid + t * 256;
        int tile = idx >> 9;
        int c = idx & 511;
        int row = c >> 3, seg = c & 7;
        int br = tile >> 1, hl = tile & 1;
        cp_async16(sb + tile * FTILE + row * FBP + seg * 16,
                   qc + (size_t)hl * NQ2 + (brow + q0 + row) * (2 * CC) +
                       br * CC + h * DHD + seg * 8);
    }
#pragma unroll
    for (int t = 0; t < 8; t++) {
        int idx = tid + t * 256;
        int tile = idx >> 9;
        int c = idx & 511;
        int row = c >> 3, seg = c & 7;
        int br = tile >> 1, hl = tile & 1;
        cp_async16(sb + OFF_K + tile * FTILE + row * FBP + seg * 16,
                   kc + (size_t)hl * NQ2 + (brow + row) * (2 * CC) +
                       br * CC + h * DHD + seg * 8);
    }
#pragma unroll
    for (int t = 0; t < 4; t++) {
        int idx = tid + t * 256;
        int row = idx >> 4, sg = idx & 15;
        cp_async16(sb + OFF_V + row * (VPAD * 4) + sg * 16,
                   vb + (brow + row) * CC + h * DHD + sg * 4);
    }
    CP_ASYNC_COMMIT();

    float s[8][4], acc[8][4];
#pragma unroll
    for (int nt = 0; nt < 8; nt++)
#pragma unroll
        for (int r = 0; r < 4; r++) acc[nt][r] = 0.f;
    float m0 = -1e30f, m1 = -1e30f, l0 = 0.f, l1 = 0.f;

    for (int kt = 0; kt <= qi; kt++) {
        const int buf = kt & 1;
        if (kt < qi) {
            const int k0n = (kt + 1) * 64;
            const int nb = 1 - buf;
#pragma unroll
            for (int t = 0; t < 8; t++) {
                int idx = tid + t * 256;
                int tile = idx >> 9;
                int c = idx & 511;
                int row = c >> 3, seg = c & 7;
                int br = tile >> 1, hl = tile & 1;
                cp_async16(sb + OFF_K + (nb * 4 + tile) * FTILE + row * FBP + seg * 16,
                           kc + (size_t)hl * NQ2 + (brow + k0n + row) * (2 * CC) +
                               br * CC + h * DHD + seg * 8);
            }
#pragma unroll
            for (int t = 0; t < 4; t++) {
                int idx = tid + t * 256;
                int row = idx >> 4, sg = idx & 15;
                cp_async16(sb + OFF_V + nb * VBYTES + row * (VPAD * 4) + sg * 16,
                           vb + (brow + k0n + row) * CC + h * DHD + sg * 4);
            }
            CP_ASYNC_COMMIT();
            CP_ASYNC_WAIT(1);
        } else {
            CP_ASYNC_WAIT(0);
        }
        __syncthreads();

        const bool diag = (kt == qi);
        const uint32_t qh = sb + (g * 2) * FTILE;
        const uint32_t ql = qh + FTILE;
        const uint32_t kh = sb + OFF_K + (buf * 4 + g * 2) * FTILE;
        const uint32_t kl = kh + FTILE;
        const float* Vs = (const float*)(smc + OFF_V + buf * VBYTES);
        float* Ps = (float*)(smc + OFF_PS + g * PSBYTES);

        // ---- S = Q @ K^T (bf16x3, paired-x4 B) ----
#pragma unroll
        for (int nt = 0; nt < 8; nt++)
#pragma unroll
            for (int r = 0; r < 4; r++) s[nt][r] = 0.f;
#pragma unroll
        for (int ks = 0; ks < 4; ks++) {
            uint32_t ah[4], al[4];
            ldm_x4(ah, qh + arow + ks * 32);
            ldm_x4(al, ql + arow + ks * 32);
#pragma unroll
            for (int np = 0; np < 4; np++) {
                uint32_t ad = b4off + np * 16 * FBP + ks * 32;
                uint32_t bh4[4], bl4[4];
                ldm_x4(bh4, kh + ad);
                ldm_x4(bl4, kl + ad);
                mma_bf16(s[2 * np],     al, bh4);
                mma_bf16(s[2 * np],     ah, bl4);
                mma_bf16(s[2 * np],     ah, bh4);
                mma_bf16(s[2 * np + 1], al, bh4 + 2);
                mma_bf16(s[2 * np + 1], ah, bl4 + 2);
                mma_bf16(s[2 * np + 1], ah, bh4 + 2);
            }
        }

        const float scale = 0.125f;
        const int r0 = rl0, r1 = rl0 + 8;
#pragma unroll
        for (int nt = 0; nt < 8; nt++) {
            const int c0 = nt * 8 + 2 * lc;
            s[nt][0] *= scale; s[nt][1] *= scale;
            s[nt][2] *= scale; s[nt][3] *= scale;
            if (diag) {
                if (c0 > r0)     s[nt][0] = -1e30f;
                if (c0 + 1 > r0) s[nt][1] = -1e30f;
                if (c0 > r1)     s[nt][2] = -1e30f;
                if (c0 + 1 > r1) s[nt][3] = -1e30f;
            }
        }

        float mx0 = -1e30f, mx1 = -1e30f;
#pragma unroll
        for (int nt = 0; nt < 8; nt++) {
            mx0 = fmaxf(mx0, fmaxf(s[nt][0], s[nt][1]));
            mx1 = fmaxf(mx1, fmaxf(s[nt][2], s[nt][3]));
        }
        mx0 = fmaxf(mx0, __shfl_xor_sync(0xffffffffu, mx0, 1));
        mx0 = fmaxf(mx0, __shfl_xor_sync(0xffffffffu, mx0, 2));
        mx1 = fmaxf(mx1, __shfl_xor_sync(0xffffffffu, mx1, 1));
        mx1 = fmaxf(mx1, __shfl_xor_sync(0xffffffffu, mx1, 2));

        const float mn0 = fmaxf(m0, mx0);
        const float mn1 = fmaxf(m1, mx1);
        const float cr0 = __expf(m0 - mn0);
        const float cr1 = __expf(m1 - mn1);

        __syncwarp();
        float ps0 = 0.f, ps1 = 0.f;
#pragma unroll
        for (int nt = 0; nt < 8; nt++) {
            const int cl = nt * 8 + 2 * lc;
            float p0 = __expf(s[nt][0] - mn0);
            float p1 = __expf(s[nt][1] - mn0);
            float p2 = __expf(s[nt][2] - mn1);
            float p3 = __expf(s[nt][3] - mn1);
            ps0 += p0 + p1;
            ps1 += p2 + p3;
            // tf32-pre-rounded store (identical numerics to cvt-at-load)
            *(float2*)&Ps[r0 * APAD + cl] =
                make_float2(__uint_as_float(f2tf32(p0)), __uint_as_float(f2tf32(p1)));
            *(float2*)&Ps[r1 * APAD + cl] =
                make_float2(__uint_as_float(f2tf32(p2)), __uint_as_float(f2tf32(p3)));
        }
        ps0 += __shfl_xor_sync(0xffffffffu, ps0, 1);
        ps0 += __shfl_xor_sync(0xffffffffu, ps0, 2);
        ps1 += __shfl_xor_sync(0xffffffffu, ps1, 1);
        ps1 += __shfl_xor_sync(0xffffffffu, ps1, 2);

        l0 = l0 * cr0 + ps0;
        l1 = l1 * cr1 + ps1;
        m0 = mn0; m1 = mn1;

#pragma unroll
        for (int nt = 0; nt < 8; nt++) {
            acc[nt][0] *= cr0; acc[nt][1] *= cr0;
            acc[nt][2] *= cr1; acc[nt][3] *= cr1;
        }
        __syncwarp();

#pragma unroll
        for (int k0 = 0; k0 < 64; k0 += 8) {
            uint32_t a[4];
            lda_frag_raw(Ps, wg * 16, k0, lr, lc, a);
#pragma unroll
            for (int nt = 0; nt < 8; nt++) {
                uint32_t bv[2];
                ldbV_raw(Vs, nt * 8, k0, lr, lc, bv);
                mma_tf32(acc[nt], a, bv);
            }
        }
        __syncthreads();
    }

    // ---- epilogue: combine branches; emit hi/lo bf16 y ----
    float* Eps = (float*)(smc + OFF_PS);
    const float lam = g_lambda;
    if (g == 1) {
        const float i0 = lam / l0, i1 = lam / l1;
        const int r0 = rl0, r1 = rl0 + 8;
#pragma unroll
        for (int nt = 0; nt < 8; nt++) {
            const int cl = nt * 8 + 2 * lc;
            *(float2*)&Eps[r0 * APAD + cl] =
                make_float2(acc[nt][0] * i0, acc[nt][1] * i0);
            *(float2*)&Eps[r1 * APAD + cl] =
                make_float2(acc[nt][2] * i1, acc[nt][3] * i1);
        }
    }
    __syncthreads();
    if (g == 0) {
        const float i0 = 1.f / l0, i1 = 1.f / l1;
        const int r0g = q0 + rl0, r1g = r0g + 8;
#pragma unroll
        for (int nt = 0; nt < 8; nt++) {
            const int cl = nt * 8 + 2 * lc;
            const int col = h * DHD + cl;
            float2 e0 = *(float2*)&Eps[rl0 * APAD + cl];
            float2 e1 = *(float2*)&Eps[(rl0 + 8) * APAD + cl];
            float o0x = acc[nt][0] * i0 - e0.x;
            float o0y = acc[nt][1] * i0 - e0.y;
            float o1x = acc[nt][2] * i1 - e1.x;
            float o1y = acc[nt][3] * i1 - e1.y;
            size_t a0 = (brow + r0g) * CC + col;
            size_t a1 = (brow + r1g) * CC + col;
            uint32_t h0 = pack_bf16x2(o0x, o0y);
            uint32_t h1 = pack_bf16x2(o1x, o1y);
            *(uint32_t*)&yh[a0] = h0;
            *(uint32_t*)&yl[a0] = lo_of(h0, o0x, o0y);
            *(uint32_t*)&yh[a1] = h1;
            *(uint32_t*)&yl[a1] = lo_of(h1, o1x, o1y);
        }
    }
}

// ---------------------------------------------------------------------------
// Launch. ncu fixed slot (launch index 3) = flash_diff_par.
// ---------------------------------------------------------------------------
extern "C" void kernel_launch(void* const* d_in, const int* in_sizes, int n_in,
                              void* d_out, int out_size)
{
    const float* x   = (const float*)d_in[0];
    const float* wq  = (const float*)d_in[1];
    const float* wk  = (const float*)d_in[2];
    const float* wv  = (const float*)d_in[3];
    const float* wo  = (const float*)d_in[4];
    const float* lq1 = (const float*)d_in[5];
    const float* lk1 = (const float*)d_in[6];
    const float* lq2 = (const float*)d_in[7];
    const float* lk2 = (const float*)d_in[8];
    const float* wc  = (const float*)d_in[9];
    const float* bc  = (const float*)d_in[10];
    const float* we  = (const float*)d_in[11];
    const float* be  = (const float*)d_in[12];

    float* v;
    cudaGetSymbolAddress((void**)&v, g_v);

    unsigned short *xc, *wqc, *wkc, *wvc, *woc, *wcc, *wec;
    unsigned short *qc, *kc, *yc, *y2c, *hc;
    cudaGetSymbolAddress((void**)&xc,  g_xc);
    cudaGetSymbolAddress((void**)&wqc, g_wqc);
    cudaGetSymbolAddress((void**)&wkc, g_wkc);
    cudaGetSymbolAddress((void**)&wvc, g_wvc);
    cudaGetSymbolAddress((void**)&woc, g_woc);
    cudaGetSymbolAddress((void**)&wcc, g_wcc);
    cudaGetSymbolAddress((void**)&wec, g_wec);
    cudaGetSymbolAddress((void**)&qc,  g_qc);
    cudaGetSymbolAddress((void**)&kc,  g_kc);
    cudaGetSymbolAddress((void**)&yc,  g_yc);
    cudaGetSymbolAddress((void**)&y2c, g_y2c);
    cudaGetSymbolAddress((void**)&hc,  g_hc);

    cudaFuncSetAttribute(mma_gemm_tn, cudaFuncAttributeMaxDynamicSharedMemorySize,
                         GEMM_SMEM);
    cudaFuncSetAttribute(mma_gemm_qkv, cudaFuncAttributeMaxDynamicSharedMemorySize,
                         GEMM_SMEM);
    cudaFuncSetAttribute(flash_diff_par, cudaFuncAttributeMaxDynamicSharedMemorySize,
                         FLASH_SMEM);

    dim3 blk(256);
    // 0: ALL input conversions in one launch (z = segment)
    {
        int nx4  = (int)(NXc / 4);    // x : 1M float4
        int nqk4 = (int)(NQKc / 4);   // wq/wk : 512K
        int nsq4 = (int)(NSQc / 4);   // wv/wo : 256K
        int nhc4 = (int)(NHCc / 4);   // wc/we : 128K
        int blocks = 1024;            // grid-stride covers all sizes
        convert_all<<<dim3(blocks, 1, 7), blk>>>(
            (const float4*)x,  (uint2*)xc,  (uint2*)(xc + NXc),  nx4,
            (const float4*)wq, (uint2*)wqc, (uint2*)(wqc + NQKc), nqk4,
            (const float4*)wk, (uint2*)wkc, (uint2*)(wkc + NQKc), nqk4,
            (const float4*)wv, (uint2*)wvc, (uint2*)(wvc + NSQc), nsq4,
            (const float4*)wo, (uint2*)woc, (uint2*)(woc + NSQc), nsq4,
            (const float4*)wc, (uint2*)wcc, (uint2*)(wcc + NHCc), nhc4,
            (const float4*)we, (uint2*)wec, (uint2*)(wec + NHCc), nhc4);
    }
    // 1: fused QKV projection
    mma_gemm_qkv<<<dim3(2 * CC / 128, MT / 128, 3), blk, GEMM_SMEM>>>(
        xc, wqc, wkc, wvc, qc, kc, v);
    // 2: lambda
    lambda_kernel<<<1, 32>>>(lq1, lk1, lq2, lk2);
    // 3 (ncu): flash attention
    flash_diff_par<<<dim3(TT / 64, HH, BB), blk, FLASH_SMEM>>>(
        qc, kc, v, yc, yc + NXc);
    // 4: wo -> y2 (bf16 hi/lo)
    mma_gemm_tn<<<dim3(CC / 128, MT / 128), blk, GEMM_SMEM>>>(
        yc, yc + NXc, woc, woc + NSQc, nullptr, nullptr, y2c, y2c + NXc,
        MT, CC, CC);
    // 5: wc -> h (bf16 hi/lo, +bias)
    mma_gemm_tn<<<dim3(CC / 2 / 128, MT / 128), blk, GEMM_SMEM>>>(
        y2c, y2c + NXc, wcc, wcc + NHCc, bc, nullptr, hc, hc + NHc,
        MT, CC / 2, CC);
    // 6: we -> out (fp32, +bias)
    mma_gemm_tn<<<dim3(CC / 128, MT / 128), blk, GEMM_SMEM>>>(
        hc, hc + NHc, wec, wec + NHCc, be, (float*)d_out, nullptr, nullptr,
        MT, CC, CC / 2);
}

// round 17
// speedup vs baseline: 3.1715x; 1.0124x over previous
#include <cuda_runtime.h>
#include <math.h>
#include <stdint.h>

// Problem constants
#define BB 2
#define TT 2048
#define CC 1024
#define HH 16
#define DHD 64
#define MT (BB * TT)          // 4096 rows

#define NXc  ((size_t)MT * CC)            // 4M
#define NQ2c ((size_t)MT * 2 * CC)        // 8M
#define NQKc ((size_t)2 * CC * CC)        // 2M
#define NSQc ((size_t)CC * CC)            // 1M
#define NHCc ((size_t)(CC / 2) * CC)      // 0.5M
#define NHc  ((size_t)MT * (CC / 2))      // 2M

// ---------------------------------------------------------------------------
// Scratch (device globals)
// ---------------------------------------------------------------------------
__device__ float g_lambda;

// hi/lo bf16 pairs (hi at [0], lo at [elem_count])
__device__ unsigned short g_xc [2ul * MT * CC];
__device__ unsigned short g_wqc[2ul * 2 * CC * CC];
__device__ unsigned short g_wkc[2ul * 2 * CC * CC];
__device__ unsigned short g_wvc[2ul * CC * CC];
__device__ unsigned short g_woc[2ul * CC * CC];
__device__ unsigned short g_wcc[2ul * (CC / 2) * CC];
__device__ unsigned short g_wec[2ul * CC * (CC / 2)];
__device__ unsigned short g_qc [2ul * MT * 2 * CC];
__device__ unsigned short g_kc [2ul * MT * 2 * CC];
__device__ unsigned short g_vc [2ul * MT * CC];
__device__ unsigned short g_yc [2ul * MT * CC];
__device__ unsigned short g_y2c[2ul * MT * CC];
__device__ unsigned short g_hc [2ul * MT * (CC / 2)];

// ---------------------------------------------------------------------------
// PTX helpers (compute_100-legal)
// ---------------------------------------------------------------------------
__device__ __forceinline__ uint32_t smem_u32(const void* p) {
    uint32_t a;
    asm("{ .reg .u64 t; cvta.to.shared.u64 t, %1; cvt.u32.u64 %0, t; }"
        : "=r"(a) : "l"(p));
    return a;
}

__device__ __forceinline__ void cp_async16(uint32_t dst, const void* src) {
    asm volatile("cp.async.ca.shared.global [%0], [%1], 16;"
                 :: "r"(dst), "l"(src) : "memory");
}
#define CP_ASYNC_COMMIT() asm volatile("cp.async.commit_group;" ::: "memory")
#define CP_ASYNC_WAIT(n)  asm volatile("cp.async.wait_group %0;" :: "n"(n) : "memory")

__device__ __forceinline__ uint32_t f2tf32(float f) {
    uint32_t r;
    asm("cvt.rna.tf32.f32 %0, %1;" : "=r"(r) : "f"(f));
    return r;
}

// bf16 m16n8k16 (all matmuls)
__device__ __forceinline__ void mma_bf16(float* d, const uint32_t* a, const uint32_t* b) {
    asm volatile(
        "mma.sync.aligned.m16n8k16.row.col.f32.bf16.bf16.f32 "
        "{%0,%1,%2,%3}, {%4,%5,%6,%7}, {%8,%9}, {%0,%1,%2,%3};"
        : "+f"(d[0]), "+f"(d[1]), "+f"(d[2]), "+f"(d[3])
        : "r"(a[0]), "r"(a[1]), "r"(a[2]), "r"(a[3]), "r"(b[0]), "r"(b[1]));
}

__device__ __forceinline__ void ldm_x4(uint32_t* r, uint32_t addr) {
    asm volatile("ldmatrix.sync.aligned.m8n8.x4.shared.b16 {%0,%1,%2,%3}, [%4];"
        : "=r"(r[0]), "=r"(r[1]), "=r"(r[2]), "=r"(r[3]) : "r"(addr));
}
__device__ __forceinline__ void ldm_x2_t(uint32_t* r, uint32_t addr) {
    asm volatile("ldmatrix.sync.aligned.m8n8.x2.trans.shared.b16 {%0,%1}, [%2];"
        : "=r"(r[0]), "=r"(r[1]) : "r"(addr));
}

__device__ __forceinline__ uint32_t pack_bf16x2(float e0, float e1) {
    uint32_t r;
    asm("cvt.rn.bf16x2.f32 %0, %1, %2;" : "=r"(r) : "f"(e1), "f"(e0));
    return r;
}
__device__ __forceinline__ uint32_t lo_of(uint32_t h, float x0, float x1) {
    return pack_bf16x2(x0 - __uint_as_float(h << 16),
                       x1 - __uint_as_float(h & 0xffff0000u));
}

// ---------------------------------------------------------------------------
// All input conversions in ONE launch (grid.z = segment)
// ---------------------------------------------------------------------------
__global__ __launch_bounds__(256) void convert_all(
    const float4* s0, uint2* h0, uint2* l0, int n0,
    const float4* s1, uint2* h1, uint2* l1, int n1,
    const float4* s2, uint2* h2, uint2* l2, int n2,
    const float4* s3, uint2* h3, uint2* l3, int n3,
    const float4* s4, uint2* h4, uint2* l4, int n4_,
    const float4* s5, uint2* h5, uint2* l5, int n5,
    const float4* s6, uint2* h6, uint2* l6, int n6)
{
    const float4* src; uint2* hi; uint2* lo; int n;
    switch (blockIdx.z) {
        case 0: src = s0; hi = h0; lo = l0; n = n0; break;
        case 1: src = s1; hi = h1; lo = l1; n = n1; break;
        case 2: src = s2; hi = h2; lo = l2; n = n2; break;
        case 3: src = s3; hi = h3; lo = l3; n = n3; break;
        case 4: src = s4; hi = h4; lo = l4; n = n4_; break;
        case 5: src = s5; hi = h5; lo = l5; n = n5; break;
        default: src = s6; hi = h6; lo = l6; n = n6; break;
    }
    for (int i = blockIdx.x * blockDim.x + threadIdx.x; i < n;
         i += gridDim.x * blockDim.x) {
        float4 v = src[i];
        uint32_t hh0 = pack_bf16x2(v.x, v.y);
        uint32_t hh1 = pack_bf16x2(v.z, v.w);
        hi[i] = make_uint2(hh0, hh1);
        lo[i] = make_uint2(lo_of(hh0, v.x, v.y), lo_of(hh1, v.z, v.w));
    }
}

// ---------------------------------------------------------------------------
// bf16x3 GEMM core (R8/R11/R14-proven; paired-x4 B fragments)
// ---------------------------------------------------------------------------
#define GBM 128
#define GBN 128
#define GBK 32
#define SPITCH 80
#define TILE_B (128 * SPITCH)
#define STAGE_B (4 * TILE_B)
#define GEMM_SMEM (2 * STAGE_B)         // 81920 B

__device__ __forceinline__ void g_stage(
    uint32_t sbuf,
    const unsigned short* __restrict__ Ah, const unsigned short* __restrict__ Al,
    const unsigned short* __restrict__ Bh, const unsigned short* __restrict__ Bl,
    int K, int kc, int tid)
{
    const unsigned short* srcs[4] = {Ah, Al, Bh, Bl};
#pragma unroll
    for (int j = 0; j < 8; j++) {
        const int tile = j >> 1;
        const int idx = (j & 1) * 256 + tid;
        const int m = idx >> 2, seg = idx & 3;
        uint32_t dst = sbuf + tile * TILE_B + m * SPITCH + seg * 16;
        cp_async16(dst, srcs[tile] + (size_t)m * K + kc * GBK + seg * 8);
    }
}

__device__ __forceinline__ void gemm_core(
    const unsigned short* __restrict__ Ah0, const unsigned short* __restrict__ Al0,
    const unsigned short* __restrict__ Bh0, const unsigned short* __restrict__ Bl0,
    const float* __restrict__ bias, float* __restrict__ Cf,
    unsigned short* __restrict__ Chi, unsigned short* __restrict__ Clo,
    int N, int K, int m0, int n0, uint32_t sb)
{
    const int tid = threadIdx.x;
    const int wid = tid >> 5, lane = tid & 31;
    const int wm = wid >> 2, wn = wid & 3;
    const int lr = lane >> 2;
    const int lc = lane & 3;

    const uint32_t a_off =
        (uint32_t)(wm * 64 + (lane & 7) + ((lane >> 3) & 1) * 8) * SPITCH +
        ((lane >> 4) & 1) * 16;
    const uint32_t b4_off =
        (uint32_t)(wn * 32 + (lane & 7) + ((lane >> 4) & 1) * 8) * SPITCH +
        ((lane >> 3) & 1) * 16;

    float acc[4][4][4];
#pragma unroll
    for (int mt = 0; mt < 4; mt++)
#pragma unroll
        for (int nt = 0; nt < 4; nt++)
#pragma unroll
            for (int r = 0; r < 4; r++) acc[mt][nt][r] = 0.f;

    const int nch = K / GBK;

    g_stage(sb, Ah0, Al0, Bh0, Bl0, K, 0, tid);
    CP_ASYNC_COMMIT();

    for (int i = 0; i < nch; i++) {
        if (i + 1 < nch) {
            g_stage(sb + ((i + 1) & 1) * STAGE_B, Ah0, Al0, Bh0, Bl0, K, i + 1, tid);
            CP_ASYNC_COMMIT();
            CP_ASYNC_WAIT(1);
        } else {
            CP_ASYNC_WAIT(0);
        }
        __syncthreads();

        const uint32_t st = sb + (i & 1) * STAGE_B;

#pragma unroll
        for (int ks = 0; ks < 2; ks++) {
            const uint32_t kbyte = ks * 32;
            uint32_t bh[4][2], bl[4][2];
#pragma unroll
            for (int np = 0; np < 2; np++) {
                uint32_t ad = st + 2 * TILE_B + b4_off + np * 16 * SPITCH + kbyte;
                uint32_t r4[4];
                ldm_x4(r4, ad);
                bh[2 * np][0] = r4[0]; bh[2 * np][1] = r4[1];
                bh[2 * np + 1][0] = r4[2]; bh[2 * np + 1][1] = r4[3];
                ldm_x4(r4, ad + TILE_B);
                bl[2 * np][0] = r4[0]; bl[2 * np][1] = r4[1];
                bl[2 * np + 1][0] = r4[2]; bl[2 * np + 1][1] = r4[3];
            }
#pragma unroll
            for (int mt = 0; mt < 4; mt++) {
                uint32_t ad = st + a_off + mt * 16 * SPITCH + kbyte;
                uint32_t ah[4], al[4];
                ldm_x4(ah, ad);
                ldm_x4(al, ad + TILE_B);
#pragma unroll
                for (int nt = 0; nt < 4; nt++) {
                    mma_bf16(acc[mt][nt], al, bh[nt]);
                    mma_bf16(acc[mt][nt], ah, bl[nt]);
                    mma_bf16(acc[mt][nt], ah, bh[nt]);
                }
            }
        }
        __syncthreads();
    }

#pragma unroll
    for (int mt = 0; mt < 4; mt++) {
        const int row = m0 + wm * 64 + mt * 16 + lr;
#pragma unroll
        for (int nt = 0; nt < 4; nt++) {
            const int col = n0 + wn * 32 + nt * 8 + 2 * lc;
            float b0 = 0.f, b1 = 0.f;
            if (bias) { b0 = __ldg(bias + col); b1 = __ldg(bias + col + 1); }
            float v0x = acc[mt][nt][0] + b0, v0y = acc[mt][nt][1] + b1;
            float v1x = acc[mt][nt][2] + b0, v1y = acc[mt][nt][3] + b1;
            if (Cf) {
                *(float2*)(Cf + (size_t)row * N + col) = make_float2(v0x, v0y);
                *(float2*)(Cf + (size_t)(row + 8) * N + col) = make_float2(v1x, v1y);
            } else {
                uint32_t h0 = pack_bf16x2(v0x, v0y);
                uint32_t h1 = pack_bf16x2(v1x, v1y);
                *(uint32_t*)&Chi[(size_t)row * N + col] = h0;
                *(uint32_t*)&Clo[(size_t)row * N + col] = lo_of(h0, v0x, v0y);
                *(uint32_t*)&Chi[(size_t)(row + 8) * N + col] = h1;
                *(uint32_t*)&Clo[(size_t)(row + 8) * N + col] = lo_of(h1, v1x, v1y);
            }
        }
    }
}

// generic single-GEMM kernel (wo / wc / we)
__global__ void __launch_bounds__(256, 2) mma_gemm_tn(
    const unsigned short* __restrict__ Ah, const unsigned short* __restrict__ Al,
    const unsigned short* __restrict__ Bh, const unsigned short* __restrict__ Bl,
    const float* __restrict__ bias, float* __restrict__ Cf,
    unsigned short* __restrict__ Chi, unsigned short* __restrict__ Clo,
    int M, int N, int K)
{
    extern __shared__ float smg[];
    const uint32_t sb = smem_u32(smg);
    const int m0 = blockIdx.y * GBM;
    const int n0 = blockIdx.x * GBN;
    gemm_core(Ah + (size_t)m0 * K, Al + (size_t)m0 * K,
              Bh + (size_t)n0 * K, Bl + (size_t)n0 * K,
              bias, Cf, Chi, Clo, N, K, m0, n0, sb);
}

// fused QKV projection: z=0 -> q, z=1 -> k, z=2 -> v (all hi/lo bf16)
__global__ void __launch_bounds__(256, 2) mma_gemm_qkv(
    const unsigned short* __restrict__ xc,
    const unsigned short* __restrict__ wqc,
    const unsigned short* __restrict__ wkc,
    const unsigned short* __restrict__ wvc,
    unsigned short* __restrict__ qcC, unsigned short* __restrict__ kcC,
    unsigned short* __restrict__ vcC)
{
    extern __shared__ float smg[];
    const uint32_t sb = smem_u32(smg);
    const int z = blockIdx.z;
    if (z == 2 && blockIdx.x >= 8) return;
    const int m0 = blockIdx.y * GBM;
    const int n0 = blockIdx.x * GBN;
    const int K = CC;

    const unsigned short *Bh, *Bl;
    unsigned short *Chi, *Clo;
    int N;
    if (z == 0) {
        Bh = wqc; Bl = wqc + NQKc; Chi = qcC; Clo = qcC + NQ2c; N = 2 * CC;
    } else if (z == 1) {
        Bh = wkc; Bl = wkc + NQKc; Chi = kcC; Clo = kcC + NQ2c; N = 2 * CC;
    } else {
        Bh = wvc; Bl = wvc + NSQc; Chi = vcC; Clo = vcC + NXc; N = CC;
    }
    gemm_core(xc + (size_t)m0 * K, xc + NXc + (size_t)m0 * K,
              Bh + (size_t)n0 * K, Bl + (size_t)n0 * K,
              nullptr, nullptr, Chi, Clo, N, K, m0, n0, sb);
}

// ---------------------------------------------------------------------------
// Lambda scalar
// ---------------------------------------------------------------------------
__global__ void lambda_kernel(const float* __restrict__ lq1, const float* __restrict__ lk1,
                              const float* __restrict__ lq2, const float* __restrict__ lk2)
{
    if (threadIdx.x == 0) {
        float s1 = 0.f, s2 = 0.f;
        for (int i = 0; i < HH; i++) {
            s1 = fmaf(lq1[i], lk1[i], s1);
            s2 = fmaf(lq2[i], lk2[i], s2);
        }
        double li = 0.8 - 0.6 * exp(-0.3 * 11.0);  // N_LAYER=12
        g_lambda = (float)(exp((double)s1) - exp((double)s2) + li);
    }
}

// ---------------------------------------------------------------------------
// Differential flash attention, R15/R16/R17:
//  - full bf16x3 everywhere: S=QK^T (proven), P@V via bf16 P hi/lo +
//    ldmatrix.x2.trans on row-major bf16 V hi/lo.
//  - LPT scheduling: qi reversed so longest CTAs launch first.
//  - warp-parallel branches + double-buffered K/V prefetch (R12-proven).
// smem: 20 bf16 tiles @ 64 x 144B = 184320 B.
// ---------------------------------------------------------------------------
#define FBP 144
#define FTILE (64 * FBP)
#define APAD 68
#define OFF_K   (4 * FTILE)              // K: 2 bufs x 4 tiles
#define OFF_V   (12 * FTILE)             // V: 2 bufs x (hi,lo)
#define OFF_PS  (16 * FTILE)             // Ps: 2 groups x (hi,lo)
#define FLASH_SMEM (20 * FTILE)          // 184320

__global__ __launch_bounds__(256) void flash_diff_par(
    const unsigned short* __restrict__ qc, const unsigned short* __restrict__ kc,
    const unsigned short* __restrict__ vc,
    unsigned short* __restrict__ yh, unsigned short* __restrict__ yl)
{
    extern __shared__ char smc[];
    const uint32_t sb = smem_u32(smc);

    const int tid = threadIdx.x;
    const int wid = tid >> 5, lane = tid & 31;
    const int g = wid >> 2;              // branch group
    const int wg = wid & 3;              // warp-in-group
    const int lr = lane >> 2, lc = lane & 3;
    const int qi = gridDim.x - 1 - blockIdx.x;   // LPT: longest first
    const int h = blockIdx.y, b = blockIdx.z;
    const int q0 = qi * 64;
    const int rl0 = wg * 16 + lr;

    const size_t NQ2 = NQ2c;
    const size_t brow = (size_t)b * TT;

    const uint32_t arow =
        (uint32_t)(wg * 16 + (lane & 7) + ((lane >> 3) & 1) * 8) * FBP +
        ((lane >> 4) & 1) * 16;
    const uint32_t b4off =
        (uint32_t)((lane & 7) + ((lane >> 4) & 1) * 8) * FBP +
        ((lane >> 3) & 1) * 16;
    // V trans rows: lanes 0-15 -> key rows 0-15 of the ks block
    const uint32_t vtrow =
        (uint32_t)((lane & 7) + ((lane >> 3) & 1) * 8) * FBP;

    // ---- stage Q + K/V for kt=0 ----
#pragma unroll
    for (int t = 0; t < 8; t++) {
        int idx = tid + t * 256;
        int tile = idx >> 9;
        int c = idx & 511;
        int row = c >> 3, seg = c & 7;
        int br = tile >> 1, hl = tile & 1;
        cp_async16(sb + tile * FTILE + row * FBP + seg * 16,
                   qc + (size_t)hl * NQ2 + (brow + q0 + row) * (2 * CC) +
                       br * CC + h * DHD + seg * 8);
    }
#pragma unroll
    for (int t = 0; t < 8; t++) {
        int idx = tid + t * 256;
        int tile = idx >> 9;
        int c = idx & 511;
        int row = c >> 3, seg = c & 7;
        int br = tile >> 1, hl = tile & 1;
        cp_async16(sb + OFF_K + tile * FTILE + row * FBP + seg * 16,
                   kc + (size_t)hl * NQ2 + (brow + row) * (2 * CC) +
                       br * CC + h * DHD + seg * 8);
    }
#pragma unroll
    for (int t = 0; t < 4; t++) {
        int idx = tid + t * 256;
        int tile = idx >> 9;            // 0=hi, 1=lo
        int c = idx & 511;
        int row = c >> 3, seg = c & 7;
        cp_async16(sb + OFF_V + tile * FTILE + row * FBP + seg * 16,
                   vc + (size_t)tile * NXc + (brow + row) * CC + h * DHD + seg * 8);
    }
    CP_ASYNC_COMMIT();

    float s[8][4], acc[8][4];
#pragma unroll
    for (int nt = 0; nt < 8; nt++)
#pragma unroll
        for (int r = 0; r < 4; r++) acc[nt][r] = 0.f;
    float m0 = -1e30f, m1 = -1e30f, l0 = 0.f, l1 = 0.f;

    for (int kt = 0; kt <= qi; kt++) {
        const int buf = kt & 1;
        if (kt < qi) {
            const int k0n = (kt + 1) * 64;
            const int nb = 1 - buf;
#pragma unroll
            for (int t = 0; t < 8; t++) {
                int idx = tid + t * 256;
                int tile = idx >> 9;
                int c = idx & 511;
                int row = c >> 3, seg = c & 7;
                int br = tile >> 1, hl = tile & 1;
                cp_async16(sb + OFF_K + (nb * 4 + tile) * FTILE + row * FBP + seg * 16,
                           kc + (size_t)hl * NQ2 + (brow + k0n + row) * (2 * CC) +
                               br * CC + h * DHD + seg * 8);
            }
#pragma unroll
            for (int t = 0; t < 4; t++) {
                int idx = tid + t * 256;
                int tile = idx >> 9;
                int c = idx & 511;
                int row = c >> 3, seg = c & 7;
                cp_async16(sb + OFF_V + (nb * 2 + tile) * FTILE + row * FBP + seg * 16,
                           vc + (size_t)tile * NXc + (brow + k0n + row) * CC +
                               h * DHD + seg * 8);
            }
            CP_ASYNC_COMMIT();
            CP_ASYNC_WAIT(1);
        } else {
            CP_ASYNC_WAIT(0);
        }
        __syncthreads();

        const bool diag = (kt == qi);
        const uint32_t qh = sb + (g * 2) * FTILE;
        const uint32_t ql = qh + FTILE;
        const uint32_t kh = sb + OFF_K + (buf * 4 + g * 2) * FTILE;
        const uint32_t kl = kh + FTILE;
        const uint32_t vH = sb + OFF_V + (buf * 2) * FTILE;
        const uint32_t vL = vH + FTILE;
        const uint32_t psH = sb + OFF_PS + (g * 2) * FTILE;
        const uint32_t psL = psH + FTILE;

        // ---- S = Q @ K^T (bf16x3, paired-x4 B) ----
#pragma unroll
        for (int nt = 0; nt < 8; nt++)
#pragma unroll
            for (int r = 0; r < 4; r++) s[nt][r] = 0.f;
#pragma unroll
        for (int ks = 0; ks < 4; ks++) {
            uint32_t ah[4], al[4];
            ldm_x4(ah, qh + arow + ks * 32);
            ldm_x4(al, ql + arow + ks * 32);
#pragma unroll
            for (int np = 0; np < 4; np++) {
                uint32_t ad = b4off + np * 16 * FBP + ks * 32;
                uint32_t bh4[4], bl4[4];
                ldm_x4(bh4, kh + ad);
                ldm_x4(bl4, kl + ad);
                mma_bf16(s[2 * np],     al, bh4);
                mma_bf16(s[2 * np],     ah, bl4);
                mma_bf16(s[2 * np],     ah, bh4);
                mma_bf16(s[2 * np + 1], al, bh4 + 2);
                mma_bf16(s[2 * np + 1], ah, bl4 + 2);
                mma_bf16(s[2 * np + 1], ah, bh4 + 2);
            }
        }

        const float scale = 0.125f;
        const int r0 = rl0, r1 = rl0 + 8;
#pragma unroll
        for (int nt = 0; nt < 8; nt++) {
            const int c0 = nt * 8 + 2 * lc;
            s[nt][0] *= scale; s[nt][1] *= scale;
            s[nt][2] *= scale; s[nt][3] *= scale;
            if (diag) {
                if (c0 > r0)     s[nt][0] = -1e30f;
                if (c0 + 1 > r0) s[nt][1] = -1e30f;
                if (c0 > r1)     s[nt][2] = -1e30f;
                if (c0 + 1 > r1) s[nt][3] = -1e30f;
            }
        }

        float mx0 = -1e30f, mx1 = -1e30f;
#pragma unroll
        for (int nt = 0; nt < 8; nt++) {
            mx0 = fmaxf(mx0, fmaxf(s[nt][0], s[nt][1]));
            mx1 = fmaxf(mx1, fmaxf(s[nt][2], s[nt][3]));
        }
        mx0 = fmaxf(mx0, __shfl_xor_sync(0xffffffffu, mx0, 1));
        mx0 = fmaxf(mx0, __shfl_xor_sync(0xffffffffu, mx0, 2));
        mx1 = fmaxf(mx1, __shfl_xor_sync(0xffffffffu, mx1, 1));
        mx1 = fmaxf(mx1, __shfl_xor_sync(0xffffffffu, mx1, 2));

        const float mn0 = fmaxf(m0, mx0);
        const float mn1 = fmaxf(m1, mx1);
        const float cr0 = __expf(m0 - mn0);
        const float cr1 = __expf(m1 - mn1);

        __syncwarp();
        float ps0 = 0.f, ps1 = 0.f;
#pragma unroll
        for (int nt = 0; nt < 8; nt++) {
            const int cl = nt * 8 + 2 * lc;
            float p0 = __expf(s[nt][0] - mn0);
            float p1 = __expf(s[nt][1] - mn0);
            float p2 = __expf(s[nt][2] - mn1);
            float p3 = __expf(s[nt][3] - mn1);
            ps0 += p0 + p1;
            ps1 += p2 + p3;
            uint32_t h0 = pack_bf16x2(p0, p1);
            uint32_t h1 = pack_bf16x2(p2, p3);
            *(uint32_t*)(smc + (psH - sb) + r0 * FBP + cl * 2) = h0;
            *(uint32_t*)(smc + (psL - sb) + r0 * FBP + cl * 2) = lo_of(h0, p0, p1);
            *(uint32_t*)(smc + (psH - sb) + r1 * FBP + cl * 2) = h1;
            *(uint32_t*)(smc + (psL - sb) + r1 * FBP + cl * 2) = lo_of(h1, p2, p3);
        }
        ps0 += __shfl_xor_sync(0xffffffffu, ps0, 1);
        ps0 += __shfl_xor_sync(0xffffffffu, ps0, 2);
        ps1 += __shfl_xor_sync(0xffffffffu, ps1, 1);
        ps1 += __shfl_xor_sync(0xffffffffu, ps1, 2);

        l0 = l0 * cr0 + ps0;
        l1 = l1 * cr1 + ps1;
        m0 = mn0; m1 = mn1;

#pragma unroll
        for (int nt = 0; nt < 8; nt++) {
            acc[nt][0] *= cr0; acc[nt][1] *= cr0;
            acc[nt][2] *= cr1; acc[nt][3] *= cr1;
        }
        __syncwarp();

        // ---- O += P @ V (bf16x3; V via ldmatrix.trans on row-major tile) ----
#pragma unroll
        for (int ks = 0; ks < 4; ks++) {
            uint32_t ph[4], pl[4];
            ldm_x4(ph, psH + arow + ks * 32);
            ldm_x4(pl, psL + arow + ks * 32);
#pragma unroll
            for (int nt = 0; nt < 8; nt++) {
                uint32_t ad = vtrow + (uint32_t)(ks * 16) * FBP + (uint32_t)(nt * 8) * 2;
                uint32_t vh[2], vl[2];
                ldm_x2_t(vh, vH + ad);
                ldm_x2_t(vl, vL + ad);
                mma_bf16(acc[nt], pl, vh);
                mma_bf16(acc[nt], ph, vl);
                mma_bf16(acc[nt], ph, vh);
            }
        }
        __syncthreads();
    }

    // ---- epilogue: combine branches via smem exchange (fp32 in Ps region) ----
    float* Eps = (float*)(smc + OFF_PS);
    const float lam = g_lambda;
    if (g == 1) {
        const float i0 = lam / l0, i1 = lam / l1;
        const int r0 = rl0, r1 = rl0 + 8;
#pragma unroll
        for (int nt = 0; nt < 8; nt++) {
            const int cl = nt * 8 + 2 * lc;
            *(float2*)&Eps[r0 * APAD + cl] =
                make_float2(acc[nt][0] * i0, acc[nt][1] * i0);
            *(float2*)&Eps[r1 * APAD + cl] =
                make_float2(acc[nt][2] * i1, acc[nt][3] * i1);
        }
    }
    __syncthreads();
    if (g == 0) {
        const float i0 = 1.f / l0, i1 = 1.f / l1;
        const int r0g = q0 + rl0, r1g = r0g + 8;
#pragma unroll
        for (int nt = 0; nt < 8; nt++) {
            const int cl = nt * 8 + 2 * lc;
            const int col = h * DHD + cl;
            float2 e0 = *(float2*)&Eps[rl0 * APAD + cl];
            float2 e1 = *(float2*)&Eps[(rl0 + 8) * APAD + cl];
            float o0x = acc[nt][0] * i0 - e0.x;
            float o0y = acc[nt][1] * i0 - e0.y;
            float o1x = acc[nt][2] * i1 - e1.x;
            float o1y = acc[nt][3] * i1 - e1.y;
            size_t a0 = (brow + r0g) * CC + col;
            size_t a1 = (brow + r1g) * CC + col;
            uint32_t h0 = pack_bf16x2(o0x, o0y);
            uint32_t h1 = pack_bf16x2(o1x, o1y);
            *(uint32_t*)&yh[a0] = h0;
            *(uint32_t*)&yl[a0] = lo_of(h0, o0x, o0y);
            *(uint32_t*)&yh[a1] = h1;
            *(uint32_t*)&yl[a1] = lo_of(h1, o1x, o1y);
        }
    }
}

// ---------------------------------------------------------------------------
// Launch. ncu fixed slot (launch index 3) = flash_diff_par.
// ---------------------------------------------------------------------------
extern "C" void kernel_launch(void* const* d_in, const int* in_sizes, int n_in,
                              void* d_out, int out_size)
{
    const float* x   = (const float*)d_in[0];
    const float* wq  = (const float*)d_in[1];
    const float* wk  = (const float*)d_in[2];
    const float* wv  = (const float*)d_in[3];
    const float* wo  = (const float*)d_in[4];
    const float* lq1 = (const float*)d_in[5];
    const float* lk1 = (const float*)d_in[6];
    const float* lq2 = (const float*)d_in[7];
    const float* lk2 = (const float*)d_in[8];
    const float* wc  = (const float*)d_in[9];
    const float* bc  = (const float*)d_in[10];
    const float* we  = (const float*)d_in[11];
    const float* be  = (const float*)d_in[12];

    unsigned short *xc, *wqc, *wkc, *wvc, *woc, *wcc, *wec;
    unsigned short *qc, *kc, *vc, *yc, *y2c, *hc;
    cudaGetSymbolAddress((void**)&xc,  g_xc);
    cudaGetSymbolAddress((void**)&wqc, g_wqc);
    cudaGetSymbolAddress((void**)&wkc, g_wkc);
    cudaGetSymbolAddress((void**)&wvc, g_wvc);
    cudaGetSymbolAddress((void**)&woc, g_woc);
    cudaGetSymbolAddress((void**)&wcc, g_wcc);
    cudaGetSymbolAddress((void**)&wec, g_wec);
    cudaGetSymbolAddress((void**)&qc,  g_qc);
    cudaGetSymbolAddress((void**)&kc,  g_kc);
    cudaGetSymbolAddress((void**)&vc,  g_vc);
    cudaGetSymbolAddress((void**)&yc,  g_yc);
    cudaGetSymbolAddress((void**)&y2c, g_y2c);
    cudaGetSymbolAddress((void**)&hc,  g_hc);

    cudaFuncSetAttribute(mma_gemm_tn, cudaFuncAttributeMaxDynamicSharedMemorySize,
                         GEMM_SMEM);
    cudaFuncSetAttribute(mma_gemm_qkv, cudaFuncAttributeMaxDynamicSharedMemorySize,
                         GEMM_SMEM);
    cudaFuncSetAttribute(flash_diff_par, cudaFuncAttributeMaxDynamicSharedMemorySize,
                         FLASH_SMEM);

    dim3 blk(256);
    // 0: all input conversions in one launch
    {
        int nx4  = (int)(NXc / 4);
        int nqk4 = (int)(NQKc / 4);
        int nsq4 = (int)(NSQc / 4);
        int nhc4 = (int)(NHCc / 4);
        convert_all<<<dim3(1024, 1, 7), blk>>>(
            (const float4*)x,  (uint2*)xc,  (uint2*)(xc + NXc),  nx4,
            (const float4*)wq, (uint2*)wqc, (uint2*)(wqc + NQKc), nqk4,
            (const float4*)wk, (uint2*)wkc, (uint2*)(wkc + NQKc), nqk4,
            (const float4*)wv, (uint2*)wvc, (uint2*)(wvc + NSQc), nsq4,
            (const float4*)wo, (uint2*)woc, (uint2*)(woc + NSQc), nsq4,
            (const float4*)wc, (uint2*)wcc, (uint2*)(wcc + NHCc), nhc4,
            (const float4*)we, (uint2*)wec, (uint2*)(wec + NHCc), nhc4);
    }
    // 1: fused QKV projection (v now bf16 hi/lo)
    mma_gemm_qkv<<<dim3(2 * CC / 128, MT / 128, 3), blk, GEMM_SMEM>>>(
        xc, wqc, wkc, wvc, qc, kc, vc);
    // 2: lambda
    lambda_kernel<<<1, 32>>>(lq1, lk1, lq2, lk2);
    // 3 (ncu): flash attention
    flash_diff_par<<<dim3(TT / 64, HH, BB), blk, FLASH_SMEM>>>(
        qc, kc, vc, yc, yc + NXc);
    // 4: wo -> y2 (bf16 hi/lo)
    mma_gemm_tn<<<dim3(CC / 128, MT / 128), blk, GEMM_SMEM>>>(
        yc, yc + NXc, woc, woc + NSQc, nullptr, nullptr, y2c, y2c + NXc,
        MT, CC, CC);
    // 5: wc -> h (bf16 hi/lo, +bias)
    mma_gemm_tn<<<dim3(CC / 2 / 128, MT / 128), blk, GEMM_SMEM>>>(
        y2c, y2c + NXc, wcc, wcc + NHCc, bc, nullptr, hc, hc + NHc,
        MT, CC / 2, CC);
    // 6: we -> out (fp32, +bias)
    mma_gemm_tn<<<dim3(CC / 128, MT / 128), blk, GEMM_SMEM>>>(
        hc, hc + NHc, wec, wec + NHCc, be, (float*)d_out, nullptr, nullptr,
        MT, CC, CC / 2);
}